// round 9
// baseline (speedup 1.0000x reference)
#include <cuda_runtime.h>
#include <cuda_bf16.h>
#include <math.h>
#include <cstdint>

#if defined(__CUDA_ARCH_SPECIFIC__) || defined(__CUDA_ARCH_FEAT_SM103_ALL)
#define HAS_TCGEN05 1
#else
#define HAS_TCGEN05 0
#endif

// ---------------------------------------------------------------------------
// Scratch buffers (packed u32 = bf16 hi << 16 | bf16 lo)
// ---------------------------------------------------------------------------
__device__ uint32_t g_pk_a[15728640];
__device__ uint32_t g_pk_b[50331648];
__device__ uint32_t g_pk_f[4194304];
__device__ uint32_t g_pk_x2d[1048576];
__device__ uint8_t  g_wpk[14155776];
__device__ uint8_t  g_wpk2[12582912];
__device__ uint32_t g_ynpk[8192 * 512];
__device__ float    g_qkv[8192 * 1536];
__device__ uint32_t g_atpk[8192 * 512];
__device__ int2     g_dec[8192];
__device__ int      g_npack[256];

// ---------------------------------------------------------------------------
// Common helpers
// ---------------------------------------------------------------------------
__device__ __forceinline__ uint32_t smem_u32(const void* p) {
    uint32_t a;
    asm("{ .reg .u64 t; cvta.to.shared.u64 t, %1; cvt.u32.u64 %0, t; }"
        : "=r"(a) : "l"(p));
    return a;
}
__device__ __forceinline__ float gelu_tanh(float x) {
    float x3 = x * x * x;
    float t = tanhf(0.7978845608028654f * (x + 0.044715f * x3));
    return 0.5f * x * (1.0f + t);
}
__device__ __forceinline__ uint32_t pack_hl(float f) {
    __nv_bfloat16 h = __float2bfloat16(f);
    __nv_bfloat16 l = __float2bfloat16(f - __bfloat162float(h));
    return ((uint32_t)__bfloat16_as_ushort(h) << 16) | __bfloat16_as_ushort(l);
}
__device__ __forceinline__ float unpack_hl(uint32_t v) {
    float h = __bfloat162float(__ushort_as_bfloat16((unsigned short)(v >> 16)));
    float l = __bfloat162float(__ushort_as_bfloat16((unsigned short)(v & 0xFFFF)));
    return h + l;
}

#if HAS_TCGEN05
__device__ __forceinline__ uint32_t elect_one() {
    uint32_t pred;
    asm volatile("{ .reg .pred p; elect.sync _|p, 0xFFFFFFFF; selp.b32 %0, 1, 0, p; }"
                 : "=r"(pred));
    return pred;
}
#define TCGEN05_ALLOC(a, n) \
    asm volatile("tcgen05.alloc.cta_group::1.sync.aligned.shared::cta.b32 [%0], %1;" \
                 :: "r"((uint32_t)(a)), "r"((uint32_t)(n)) : "memory")
#define TCGEN05_DEALLOC(t, n) \
    asm volatile("tcgen05.dealloc.cta_group::1.sync.aligned.b32 %0, %1;" :: "r"(t), "r"(n))
#define TCGEN05_RELINQ() \
    asm volatile("tcgen05.relinquish_alloc_permit.cta_group::1.sync.aligned;")
#define TCGEN05_COMMIT(m) \
    asm volatile("tcgen05.commit.cta_group::1.mbarrier::arrive::one.shared::cluster.b64 [%0];" \
                 :: "r"((uint32_t)(m)) : "memory")
#define TCGEN05_FENCE_AFTER() \
    asm volatile("tcgen05.fence::after_thread_sync;" ::: "memory")
#define TCGEN05_FENCE_BEFORE() \
    asm volatile("tcgen05.fence::before_thread_sync;" ::: "memory")
#define TCGEN05_WAIT_LD() asm volatile("tcgen05.wait::ld.sync.aligned;" ::: "memory")
#define FENCE_PROXY_ASYNC() asm volatile("fence.proxy.async.shared::cta;" ::: "memory")
#define MBARRIER_INIT(m, c) \
    asm volatile("mbarrier.init.shared.b64 [%0], %1;" :: "r"((uint32_t)(m)), "r"((uint32_t)(c)) : "memory")
#define MBARRIER_INVAL(m) \
    asm volatile("mbarrier.inval.shared.b64 [%0];" :: "r"((uint32_t)(m)) : "memory")
#define MBARRIER_WAIT_PARITY(m, ph) do {                                           \
    uint32_t _m = (uint32_t)(m), _p = (uint32_t)(ph), _d;                          \
    asm volatile("{ .reg .pred p; mbarrier.try_wait.parity.acquire.cta.shared::cta.b64 p, [%1], %2;" \
                 " selp.b32 %0, 1, 0, p; }" : "=r"(_d) : "r"(_m), "r"(_p) : "memory"); \
    if (!_d) {                                                                     \
        asm volatile("{ .reg .pred P1; WL_%=: mbarrier.try_wait.parity.acquire.cta.shared::cta.b64 P1, [%0], %1, 0x989680;" \
                     " @P1 bra.uni WD_%=; bra.uni WL_%=; WD_%=: }"                 \
                     :: "r"(_m), "r"(_p) : "memory");                              \
    }                                                                              \
} while (0)
#define TCGEN05_LD_X32(r, a)                                                       \
    asm volatile("tcgen05.ld.sync.aligned.32x32b.x32.b32 "                         \
        "{%0, %1, %2, %3, %4, %5, %6, %7, %8, %9, %10, %11, %12, %13, %14, %15, "  \
        " %16, %17, %18, %19, %20, %21, %22, %23, %24, %25, %26, %27, %28, %29, %30, %31}, [%32];" \
        : "=r"((r)[0]), "=r"((r)[1]), "=r"((r)[2]), "=r"((r)[3]),                  \
          "=r"((r)[4]), "=r"((r)[5]), "=r"((r)[6]), "=r"((r)[7]),                  \
          "=r"((r)[8]), "=r"((r)[9]), "=r"((r)[10]), "=r"((r)[11]),                \
          "=r"((r)[12]), "=r"((r)[13]), "=r"((r)[14]), "=r"((r)[15]),              \
          "=r"((r)[16]), "=r"((r)[17]), "=r"((r)[18]), "=r"((r)[19]),              \
          "=r"((r)[20]), "=r"((r)[21]), "=r"((r)[22]), "=r"((r)[23]),              \
          "=r"((r)[24]), "=r"((r)[25]), "=r"((r)[26]), "=r"((r)[27]),              \
          "=r"((r)[28]), "=r"((r)[29]), "=r"((r)[30]), "=r"((r)[31])               \
        : "r"(a))

static constexpr uint64_t SMEM_DESC_BASE_SW128 =
    (uint64_t(2) << 61) | (uint64_t(1) << 46) | (uint64_t(64) << 32) | (uint64_t(1) << 16);
__device__ __forceinline__ uint64_t make_desc(uint32_t addr) {
    return SMEM_DESC_BASE_SW128 | ((uint64_t)(addr >> 4) & 0x3FFF);
}
__device__ __forceinline__ void mma_f16_ss(uint32_t d, uint64_t ad, uint64_t bd,
                                           uint32_t idesc, uint32_t en) {
    asm volatile(
        "{ .reg .pred p; setp.ne.u32 p, %5, 0;\n\t"
        "tcgen05.mma.cta_group::1.kind::f16 [%0], %1, %2, %3, {%4, %4, %4, %4}, p; }"
        :: "r"(d), "l"(ad), "l"(bd), "r"(idesc), "r"(0u), "r"(en) : "memory");
}
static constexpr uint32_t CONV_IDESC =
    (1u << 4) | (1u << 7) | (1u << 10) | ((128u / 8) << 17) | ((128u / 16) << 24);
#endif // HAS_TCGEN05

#define SME_A0 0
#define SME_A1 32768
#define SME_B0 65536
#define SME_B1 98304
#define SME_MBAR 131072
#define SME_TSLOT 131104
#define CONV_SMEM_BYTES (1024 + 131072 + 128)

// natt smem: ksm 32x491 u32 | vsm 64x491 f32 | psh 8x248 f32 | qsh 8x64 f32
#define NSM_K 0
#define NSM_V 62848
#define NSM_P (62848 + 125696)
#define NSM_Q (62848 + 125696 + 7936)
#define NATT_SMEM_BYTES (62848 + 125696 + 7936 + 2048)

// ---------------------------------------------------------------------------
// Init / pack kernels
// ---------------------------------------------------------------------------
__global__ void conv_decode_kernel(int K, int Kpad, int KV, int KHW, int KW,
                                   int D, int H, int W) {
    int k = blockIdx.x * 256 + threadIdx.x;
    if (k >= Kpad) return;
    if (k < K) {
        int ci = k / KV; int tap = k - ci * KV;
        int kd = tap / KHW; int t2 = tap - kd * KHW;
        int kh = t2 / KW; int kw = t2 - kh * KW;
        g_dec[k] = make_int2(((ci * D + kd) * H + kh) * W + kw,
                             (kd << 20) | (kh << 10) | kw);
    } else {
        g_dec[k] = make_int2(0, 1023 << 20);
    }
}

__global__ void natt_table_kernel() {
    int nb = threadIdx.x;
    if (nb < 245) {
        int od = nb / 49; int r = nb - od * 49;
        int oh = r / 7;   int ow = r - oh * 7;
        g_npack[nb] = (od << 16) | (oh << 8) | ow;
    }
}

__global__ void xpack_kernel(const float* __restrict__ x,
                             uint32_t* __restrict__ dst, int n4) {
    int i = blockIdx.x * 256 + threadIdx.x;
    if (i >= n4) return;
    float4 v = reinterpret_cast<const float4*>(x)[i];
    uint4 o;
    o.x = pack_hl(v.x); o.y = pack_hl(v.y);
    o.z = pack_hl(v.z); o.w = pack_hl(v.w);
    reinterpret_cast<uint4*>(dst)[i] = o;
}

__global__ void wpack_kernel(const float* __restrict__ w, int K, int NC) {
    int kc = blockIdx.x, bm = blockIdx.y;
    int tid = threadIdx.x;
    int r = tid >> 1, half = tid & 1;
    const float* wrow = w + (size_t)(bm * 128 + r) * K;
    uint8_t* hi = g_wpk + (size_t)(bm * NC + kc) * 32768;
    uint8_t* lo = hi + 16384;
#pragma unroll
    for (int i = 0; i < 16; i++) {
        int kk = half * 32 + 2 * i;
        int k = kc * 64 + kk;
        float a0 = (k < K) ? wrow[k] : 0.f;
        float a1 = (k + 1 < K) ? wrow[k + 1] : 0.f;
        uint32_t p0 = pack_hl(a0), p1 = pack_hl(a1);
        uint32_t hp = __byte_perm(p0, p1, 0x7632);
        uint32_t lp = __byte_perm(p0, p1, 0x5410);
        uint32_t off = r * 128 + kk * 2;
        uint32_t sw = off ^ ((off >> 3) & 0x70);
        *reinterpret_cast<uint32_t*>(hi + sw) = hp;
        *reinterpret_cast<uint32_t*>(lo + sw) = lp;
    }
}

__global__ void wpackT_kernel(const float* __restrict__ w, uint8_t* dst,
                              int K, int NC, int J) {
    int kc = blockIdx.x, bm = blockIdx.y;
    int tid = threadIdx.x;
    int r = tid >> 1, half = tid & 1;
    int m = bm * 128 + r;
    uint8_t* hi = dst + (size_t)(bm * NC + kc) * 32768;
    uint8_t* lo = hi + 16384;
#pragma unroll
    for (int i = 0; i < 16; i++) {
        int kk = half * 32 + 2 * i;
        int k = kc * 64 + kk;
        float a0 = (k < K) ? w[(size_t)k * J + m] : 0.f;
        float a1 = (k + 1 < K) ? w[(size_t)(k + 1) * J + m] : 0.f;
        uint32_t p0 = pack_hl(a0), p1 = pack_hl(a1);
        uint32_t hp = __byte_perm(p0, p1, 0x7632);
        uint32_t lp = __byte_perm(p0, p1, 0x5410);
        uint32_t off = r * 128 + kk * 2;
        uint32_t sw = off ^ ((off >> 3) & 0x70);
        *reinterpret_cast<uint32_t*>(hi + sw) = hp;
        *reinterpret_cast<uint32_t*>(lo + sw) = lp;
    }
}

// ---------------------------------------------------------------------------
// Conv kernel (R8 structure, mbarrier ring of 4)
// ---------------------------------------------------------------------------
struct ConvParams {
    const uint32_t* xpk;
    const float* wf;
    const float* bias;
    uint32_t* outpk;
    float* outf;
    int D, H, W;
    int Hout, Wout;
    int sd, sh, sw, pd, ph, pw;
    int K, NC;
    int outStrideC, outOffset;
    int gelu;
};

template <int BM>
__global__ __launch_bounds__(512) void conv_mma_kernel(ConvParams p) {
    extern __shared__ char smem_raw[];
    char* smem_al = (char*)(((uintptr_t)smem_raw + 1023) & ~(uintptr_t)1023);

    const int tid = threadIdx.x;
    const int bn = blockIdx.x;
    const int mblk0 = blockIdx.y * BM;
    const int HWo = p.Hout * p.Wout;

#if HAS_TCGEN05
    const uint32_t sb = smem_u32(smem_al);
    const uint32_t mbar = sb + SME_MBAR;
    const uint32_t tmem_slot = sb + SME_TSLOT;
    const int wid = tid >> 5;
    const int lane = tid & 31;

    if (wid == 0) {
        TCGEN05_ALLOC(tmem_slot, 512);
        TCGEN05_RELINQ();
    }
    if (tid == 0) {
#pragma unroll
        for (int i = 0; i < 4; i++) MBARRIER_INIT(mbar + 8 * i, 1);
    }
    __syncthreads();
    uint32_t tmem;
    asm volatile("ld.shared.b32 %0, [%1];" : "=r"(tmem) : "r"(tmem_slot));

    const int r = tid >> 2;
    const int q = tid & 3;
    const int n = bn * 128 + r;
    const int od = n / HWo; int rr2 = n - od * HWo;
    const int oh = rr2 / p.Wout; const int ow = rr2 - oh * p.Wout;
    const int id0 = od * p.sd - p.pd;
    const int ih0 = oh * p.sh - p.ph;
    const int iw0 = ow * p.sw - p.pw;
    const int gbase = (id0 * p.H + ih0) * p.W + iw0;
    const int NC = p.NC;

    auto fillA = [&](int ab, int kc, int bm) {
        const uint8_t* src = g_wpk + ((size_t)(mblk0 + bm) * NC + kc) * 32768 + tid * 16;
        char* dst = smem_al + (ab ? SME_A1 : SME_A0) + tid * 16;
#pragma unroll
        for (int i = 0; i < 4; i++) {
            uint4 v = *reinterpret_cast<const uint4*>(src + i * 8192);
            *reinterpret_cast<uint4*>(dst + i * 8192) = v;
        }
    };
    auto fillB = [&](int st, int kc) {
        char* Bhi = smem_al + (st ? SME_B1 : SME_B0);
        char* Blo = Bhi + 16384;
        const int kt = kc * 64;
#pragma unroll
        for (int i = 0; i < 8; i++) {
            int kk = q * 16 + 2 * i;
            int k = kt + kk;
            int4 dv = *reinterpret_cast<const int4*>(&g_dec[k]);
            uint32_t v0 = 0, v1 = 0;
            {
                int kd = dv.y >> 20, kh = (dv.y >> 10) & 1023, kw = dv.y & 1023;
                if ((unsigned)(id0 + kd) < (unsigned)p.D &&
                    (unsigned)(ih0 + kh) < (unsigned)p.H &&
                    (unsigned)(iw0 + kw) < (unsigned)p.W)
                    v0 = p.xpk[gbase + dv.x];
            }
            {
                int kd = dv.w >> 20, kh = (dv.w >> 10) & 1023, kw = dv.w & 1023;
                if ((unsigned)(id0 + kd) < (unsigned)p.D &&
                    (unsigned)(ih0 + kh) < (unsigned)p.H &&
                    (unsigned)(iw0 + kw) < (unsigned)p.W)
                    v1 = p.xpk[gbase + dv.z];
            }
            uint32_t off = r * 128 + kk * 2;
            uint32_t sw = off ^ ((off >> 3) & 0x70);
            *reinterpret_cast<uint32_t*>(Bhi + sw) = __byte_perm(v0, v1, 0x7632);
            *reinterpret_cast<uint32_t*>(Blo + sw) = __byte_perm(v0, v1, 0x5410);
        }
    };

    int wpar = 0;
    auto waitCommits = [&](int target) {
        while (wpar < target) {
            MBARRIER_WAIT_PARITY(mbar + 8 * (wpar & 3), (wpar >> 2) & 1);
            wpar++;
        }
    };

    fillB(0, 0);

    for (int kc = 0; kc < NC; kc++) {
        int st = kc & 1;
#pragma unroll
        for (int bm = 0; bm < BM; bm++) {
            int ni = kc * BM + bm;
            if (ni >= 2) waitCommits(ni - 1);
            fillA(ni & 1, kc, bm);
            FENCE_PROXY_ASYNC();
            __syncthreads();
            if (wid == 0 && elect_one()) {
                uint64_t dAh = make_desc(sb + ((ni & 1) ? SME_A1 : SME_A0));
                uint64_t dAl = dAh + (16384 >> 4);
                uint64_t dBh = make_desc(sb + (st ? SME_B1 : SME_B0));
                uint64_t dBl = dBh + (16384 >> 4);
                uint32_t d = tmem + bm * 128;
                uint32_t first = (kc == 0) ? 0u : 1u;
#pragma unroll
                for (int s = 0; s < 4; s++) {
                    uint64_t o = s * 2;
                    mma_f16_ss(d, dAh + o, dBh + o, CONV_IDESC, first); first = 1;
                    mma_f16_ss(d, dAh + o, dBl + o, CONV_IDESC, 1);
                    mma_f16_ss(d, dAl + o, dBh + o, CONV_IDESC, 1);
                }
                TCGEN05_COMMIT(mbar + 8 * (ni & 3));
            }
        }
        if (kc + 1 < NC) {
            waitCommits(kc * BM);
            fillB(st ^ 1, kc + 1);
        }
    }
    waitCommits(NC * BM);
    TCGEN05_FENCE_AFTER();

    {
        const int sp = wid & 3;
        const int cb = wid >> 2;
#pragma unroll
        for (int bm = 0; bm < BM; bm++) {
            const int m = (mblk0 + bm) * 128 + sp * 32 + lane;
            const float bv = p.bias[m];
            uint32_t dr[32];
            TCGEN05_LD_X32(dr, tmem + bm * 128 + cb * 32);
            TCGEN05_WAIT_LD();
            size_t obase = (size_t)m * p.outStrideC + p.outOffset + bn * 128 + cb * 32;
            if (p.outpk) {
                uint32_t* orow = p.outpk + obase;
#pragma unroll
                for (int j = 0; j < 32; j++) {
                    float v = __uint_as_float(dr[j]) + bv;
                    if (p.gelu) v = gelu_tanh(v);
                    orow[j] = pack_hl(v);
                }
            } else {
                float* orow = p.outf + obase;
#pragma unroll
                for (int j = 0; j < 32; j++) {
                    float v = __uint_as_float(dr[j]) + bv;
                    if (p.gelu) v = gelu_tanh(v);
                    orow[j] = v;
                }
            }
        }
        TCGEN05_FENCE_BEFORE();
    }
    __syncthreads();
    if (tid == 0) {
#pragma unroll
        for (int i = 0; i < 4; i++) MBARRIER_INVAL(mbar + 8 * i);
    }
    if (wid == 0) TCGEN05_DEALLOC(tmem, 512);

#else  // FFMA fallback (never executes on GB300)
    for (int bm = 0; bm < BM; bm++) {
        const int m_base = (mblk0 + bm) * 128;
        for (int idx = tid; idx < 128 * 128; idx += 512) {
            int ml = idx >> 7, nl = idx & 127;
            int m = m_base + ml;
            int nn = bn * 128 + nl;
            int od = nn / HWo; int rr2 = nn - od * HWo;
            int oh = rr2 / p.Wout; int ow = rr2 - oh * p.Wout;
            int id0 = od * p.sd - p.pd, ih0 = oh * p.sh - p.ph, iw0 = ow * p.sw - p.pw;
            int gb = (id0 * p.H + ih0) * p.W + iw0;
            float s = 0.f;
            for (int k = 0; k < p.K; k++) {
                int2 dv = g_dec[k];
                int kd = dv.y >> 20, kh = (dv.y >> 10) & 1023, kw = dv.y & 1023;
                if ((unsigned)(id0 + kd) < (unsigned)p.D &&
                    (unsigned)(ih0 + kh) < (unsigned)p.H &&
                    (unsigned)(iw0 + kw) < (unsigned)p.W)
                    s += p.wf[(size_t)m * p.K + k] * unpack_hl(p.xpk[gb + dv.x]);
            }
            s += p.bias[m];
            if (p.gelu) s = gelu_tanh(s);
            size_t ob = (size_t)m * p.outStrideC + p.outOffset + nn;
            if (p.outpk) p.outpk[ob] = pack_hl(s);
            else p.outf[ob] = s;
        }
    }
#endif
}

// ---------------------------------------------------------------------------
// Token GEMM (R8 structure, mbarrier ring of 4)
// ---------------------------------------------------------------------------
struct TokParams {
    const uint32_t* bpk;
    const uint8_t* wpk;
    const float* wf;
    const float* bias;
    float* out;
    int T, J, Kdim, NC, mode;
};

template <int BM>
__global__ __launch_bounds__(512) void tok_mma_kernel(TokParams p) {
    extern __shared__ char smem_raw[];
    char* smem_al = (char*)(((uintptr_t)smem_raw + 1023) & ~(uintptr_t)1023);

    const int tid = threadIdx.x;
    const int bn = blockIdx.x;
    const int mblk0 = blockIdx.y * BM;

#if HAS_TCGEN05
    const uint32_t sb = smem_u32(smem_al);
    const uint32_t mbar = sb + SME_MBAR;
    const uint32_t tmem_slot = sb + SME_TSLOT;
    const int wid = tid >> 5;
    const int lane = tid & 31;

    if (wid == 0) {
        TCGEN05_ALLOC(tmem_slot, 512);
        TCGEN05_RELINQ();
    }
    if (tid == 0) {
#pragma unroll
        for (int i = 0; i < 4; i++) MBARRIER_INIT(mbar + 8 * i, 1);
    }
    __syncthreads();
    uint32_t tmem;
    asm volatile("ld.shared.b32 %0, [%1];" : "=r"(tmem) : "r"(tmem_slot));

    const int r = tid >> 2;
    const int q = tid & 3;
    const uint32_t* bsrc = p.bpk + (size_t)(bn * 128 + r) * p.Kdim;
    const int NC = p.NC;

    auto fillA = [&](int ab, int kc, int bm) {
        const uint8_t* src = p.wpk + ((size_t)(mblk0 + bm) * NC + kc) * 32768 + tid * 16;
        char* dst = smem_al + (ab ? SME_A1 : SME_A0) + tid * 16;
#pragma unroll
        for (int i = 0; i < 4; i++) {
            uint4 v = *reinterpret_cast<const uint4*>(src + i * 8192);
            *reinterpret_cast<uint4*>(dst + i * 8192) = v;
        }
    };
    auto fillB = [&](int st, int kc) {
        char* Bhi = smem_al + (st ? SME_B1 : SME_B0);
        char* Blo = Bhi + 16384;
        const uint32_t* src = bsrc + kc * 64 + q * 16;
        uint32_t buf[16];
#pragma unroll
        for (int i = 0; i < 4; i++)
            *reinterpret_cast<uint4*>(&buf[i * 4]) =
                *reinterpret_cast<const uint4*>(src + i * 4);
#pragma unroll
        for (int i = 0; i < 8; i++) {
            int kk = q * 16 + 2 * i;
            uint32_t v0 = buf[2 * i], v1 = buf[2 * i + 1];
            uint32_t off = r * 128 + kk * 2;
            uint32_t sw = off ^ ((off >> 3) & 0x70);
            *reinterpret_cast<uint32_t*>(Bhi + sw) = __byte_perm(v0, v1, 0x7632);
            *reinterpret_cast<uint32_t*>(Blo + sw) = __byte_perm(v0, v1, 0x5410);
        }
    };

    int wpar = 0;
    auto waitCommits = [&](int target) {
        while (wpar < target) {
            MBARRIER_WAIT_PARITY(mbar + 8 * (wpar & 3), (wpar >> 2) & 1);
            wpar++;
        }
    };

    fillB(0, 0);

    for (int kc = 0; kc < NC; kc++) {
        int st = kc & 1;
#pragma unroll
        for (int bm = 0; bm < BM; bm++) {
            int ni = kc * BM + bm;
            if (ni >= 2) waitCommits(ni - 1);
            fillA(ni & 1, kc, bm);
            FENCE_PROXY_ASYNC();
            __syncthreads();
            if (wid == 0 && elect_one()) {
                uint64_t dAh = make_desc(sb + ((ni & 1) ? SME_A1 : SME_A0));
                uint64_t dAl = dAh + (16384 >> 4);
                uint64_t dBh = make_desc(sb + (st ? SME_B1 : SME_B0));
                uint64_t dBl = dBh + (16384 >> 4);
                uint32_t d = tmem + bm * 128;
                uint32_t first = (kc == 0) ? 0u : 1u;
#pragma unroll
                for (int s = 0; s < 4; s++) {
                    uint64_t o = s * 2;
                    mma_f16_ss(d, dAh + o, dBh + o, CONV_IDESC, first); first = 1;
                    mma_f16_ss(d, dAh + o, dBl + o, CONV_IDESC, 1);
                    mma_f16_ss(d, dAl + o, dBh + o, CONV_IDESC, 1);
                }
                TCGEN05_COMMIT(mbar + 8 * (ni & 3));
            }
        }
        if (kc + 1 < NC) {
            waitCommits(kc * BM);
            fillB(st ^ 1, kc + 1);
        }
    }
    waitCommits(NC * BM);
    TCGEN05_FENCE_AFTER();

    {
        const int sp = wid & 3;
        const int cb = wid >> 2;
        const int t0 = bn * 128 + cb * 32;
#pragma unroll
        for (int bm = 0; bm < BM; bm++) {
            const int m = (mblk0 + bm) * 128 + sp * 32 + lane;
            const float bv = p.bias[m];
            uint32_t dr[32];
            TCGEN05_LD_X32(dr, tmem + bm * 128 + cb * 32);
            TCGEN05_WAIT_LD();
            if (p.mode == 0) {
#pragma unroll
                for (int j = 0; j < 32; j++)
                    p.out[(size_t)(t0 + j) * p.J + m] = __uint_as_float(dr[j]) + bv;
            } else {
                float* orow = p.out + (size_t)m * p.T + t0;
#pragma unroll
                for (int j = 0; j < 8; j++) {
                    float4* cp = reinterpret_cast<float4*>(orow + j * 4);
                    float4 o = *cp;
                    o.x += __uint_as_float(dr[j * 4 + 0]) + bv;
                    o.y += __uint_as_float(dr[j * 4 + 1]) + bv;
                    o.z += __uint_as_float(dr[j * 4 + 2]) + bv;
                    o.w += __uint_as_float(dr[j * 4 + 3]) + bv;
                    *cp = o;
                }
            }
        }
        TCGEN05_FENCE_BEFORE();
    }
    __syncthreads();
    if (tid == 0) {
#pragma unroll
        for (int i = 0; i < 4; i++) MBARRIER_INVAL(mbar + 8 * i);
    }
    if (wid == 0) TCGEN05_DEALLOC(tmem, 512);

#else  // FFMA fallback
    for (int bm = 0; bm < BM; bm++) {
        int m_base = (mblk0 + bm) * 128;
        for (int idx = tid; idx < 128 * 128; idx += 512) {
            int tl = idx >> 7, jl = idx & 127;
            int t = bn * 128 + tl, j = m_base + jl;
            float s = 0.f;
            for (int k = 0; k < p.Kdim; k++)
                s += unpack_hl(p.bpk[(size_t)t * p.Kdim + k]) * p.wf[(size_t)k * p.J + j];
            s += p.bias[j];
            if (p.mode == 0) p.out[(size_t)t * p.J + j] = s;
            else p.out[(size_t)j * p.T + t] += s;
        }
    }
#endif
}

// ---------------------------------------------------------------------------
// LayerNorm: fp32 channel-major -> packed token-major
// ---------------------------------------------------------------------------
__global__ __launch_bounds__(256) void layernorm_kernel(
    const float* __restrict__ x, const float* __restrict__ g,
    const float* __restrict__ b, uint32_t* __restrict__ ypk, int T) {
    const int tx = threadIdx.x;
    const int ty = threadIdx.y;
    const int t = blockIdx.x * 32 + tx;

    float s = 0.f, ss = 0.f;
#pragma unroll
    for (int i = 0; i < 64; i++) {
        int c = ty * 64 + i;
        float v = x[(size_t)c * T + t];
        s += v; ss += v * v;
    }
    __shared__ float shs[8][32], shss[8][32];
    __shared__ float smu[32], srs[32];
    shs[ty][tx] = s; shss[ty][tx] = ss;
    __syncthreads();
    if (ty == 0) {
        float S = 0.f, SS = 0.f;
#pragma unroll
        for (int j = 0; j < 8; j++) { S += shs[j][tx]; SS += shss[j][tx]; }
        float mu = S * (1.f / 512.f);
        float var = SS * (1.f / 512.f) - mu * mu;
        smu[tx] = mu;
        srs[tx] = rsqrtf(var + 1e-5f);
    }
    __syncthreads();
    float mu = smu[tx], rs = srs[tx];
    uint32_t* yrow = ypk + (size_t)t * 512 + ty * 64;
#pragma unroll
    for (int i = 0; i < 64; i++) {
        int c = ty * 64 + i;
        float v = x[(size_t)c * T + t];
        yrow[i] = pack_hl((v - mu) * rs * g[c] + b[c]);
    }
}

// ---------------------------------------------------------------------------
// Neighborhood attention — smem-staged, transposed K(bf16)/V(fp32).
// Block = 8-token w-strip x 1 head. Grid (1024, 8). Block 256.
// ---------------------------------------------------------------------------
__global__ __launch_bounds__(256) void natt_kernel(
    const float* __restrict__ qkv, uint32_t* __restrict__ atpk) {
    extern __shared__ char nsm[];
    uint32_t* ksm = reinterpret_cast<uint32_t*>(nsm + NSM_K);   // [32][491]
    float* vsm = reinterpret_cast<float*>(nsm + NSM_V);         // [64][491]
    float* psh = reinterpret_cast<float*>(nsm + NSM_P);         // [8][248]
    float* qsh = reinterpret_cast<float*>(nsm + NSM_Q);         // [8][64]

    const int tid = threadIdx.x;
    const int warp = tid >> 5;
    const int lane = tid & 31;
    const int t0 = blockIdx.x * 8;
    const int head = blockIdx.y;
    const int d = t0 >> 11;
    const int h = (t0 >> 6) & 31;
    const int w0 = t0 & 63;

    const int dlo = max(d - 2, 0), dhi = min(d + 2, 3);
    const int hlo = max(h - 3, 0), hhi = min(h + 3, 31);
    const int wlo = max(w0 - 3, 0), whi = min(w0 + 10, 63);
    const int nhc = hhi - hlo + 1, nwc = whi - wlo + 1;
    const int nhw = nhc * nwc;
    const int rows = (dhi - dlo + 1) * nhw;

    // cooperative staged load: K bf16 transposed, V fp32 transposed
    for (int row = warp; row < rows; row += 8) {
        int rd = row / nhw; int rem = row - rd * nhw;
        int rh = rem / nwc; int rw = rem - rh * nwc;
        int tok = (((dlo + rd) * 32) + (hlo + rh)) * 64 + (wlo + rw);
        const float* kb = qkv + (size_t)tok * 1536 + 512 + head * 64;
        float2 kf = *reinterpret_cast<const float2*>(kb + 2 * lane);
        __nv_bfloat162 kb2 = __float22bfloat162_rn(kf);
        ksm[lane * 491 + row] = *reinterpret_cast<uint32_t*>(&kb2);
        const float* vb = kb + 512;
        vsm[lane * 491 + row] = vb[lane];
        vsm[(lane + 32) * 491 + row] = vb[lane + 32];
    }
    {
        const float* qp = qkv + (size_t)(t0 + warp) * 1536 + head * 64;
        qsh[warp * 64 + lane] = qp[lane] * 0.125f;
        qsh[warp * 64 + lane + 32] = qp[lane + 32] * 0.125f;
    }
    __syncthreads();

    const int tw = w0 + warp;

    // score phase: LDS-only
    float sc[8];
    float m = -1e30f;
#pragma unroll
    for (int it = 0; it < 8; it++) {
        int nb = it * 32 + lane;
        float dot = -1e30f;
        if (nb < 245) {
            int pk = g_npack[nb];
            int nd = d + (pk >> 16) - 2;
            int nh = h + ((pk >> 8) & 255) - 3;
            int nw = tw + (pk & 255) - 3;
            if ((unsigned)nd < 4u && (unsigned)nh < 32u && (unsigned)nw < 64u) {
                int uidx = (nd - dlo) * nhw + (nh - hlo) * nwc + (nw - wlo);
                float s = 0.f;
#pragma unroll
                for (int j = 0; j < 32; j++) {
                    uint32_t kv = ksm[j * 491 + uidx];
                    float2 qv = *reinterpret_cast<const float2*>(qsh + warp * 64 + 2 * j);
                    float2 kfv = __bfloat1622float2(
                        *reinterpret_cast<__nv_bfloat162*>(&kv));
                    s = fmaf(qv.x, kfv.x, s);
                    s = fmaf(qv.y, kfv.y, s);
                }
                dot = s;
            }
        }
        sc[it] = dot;
        m = fmaxf(m, dot);
    }
#pragma unroll
    for (int o = 16; o; o >>= 1) m = fmaxf(m, __shfl_xor_sync(0xffffffffu, m, o));

    float l = 0.f;
#pragma unroll
    for (int it = 0; it < 8; it++) {
        int nb = it * 32 + lane;
        float e = (sc[it] > -1e29f) ? __expf(sc[it] - m) : 0.f;
        if (nb < 248) psh[warp * 248 + nb] = e;
        l += e;
    }
#pragma unroll
    for (int o = 16; o; o >>= 1) l += __shfl_xor_sync(0xffffffffu, l, o);
    __syncwarp();

    // PV phase: LDS-only, conflict-free transposed V
    float acc0 = 0.f, acc1 = 0.f;
    for (int nb = 0; nb < 245; nb++) {
        float pb = psh[warp * 248 + nb];
        if (pb > 0.f) {
            int pk = g_npack[nb];
            int nd = d + (pk >> 16) - 2;
            int nh = h + ((pk >> 8) & 255) - 3;
            int nw = tw + (pk & 255) - 3;
            int uidx = (nd - dlo) * nhw + (nh - hlo) * nwc + (nw - wlo);
            acc0 = fmaf(pb, vsm[lane * 491 + uidx], acc0);
            acc1 = fmaf(pb, vsm[(lane + 32) * 491 + uidx], acc1);
        }
    }
    float inv = 1.f / l;
    uint32_t* op = atpk + (size_t)(t0 + warp) * 512 + head * 64;
    op[lane] = pack_hl(acc0 * inv);
    op[lane + 32] = pack_hl(acc1 * inv);
}

// ---------------------------------------------------------------------------
// Host launcher
// ---------------------------------------------------------------------------
extern "C" void kernel_launch(void* const* d_in, const int* in_sizes, int n_in,
                              void* d_out, int out_size) {
    const float* x2d  = (const float*)d_in[0];
    const float* x3d  = (const float*)d_in[1];
    const float* sw0  = (const float*)d_in[2];  const float* sb0 = (const float*)d_in[3];
    const float* sw1  = (const float*)d_in[4];  const float* sb1 = (const float*)d_in[5];
    const float* sw2  = (const float*)d_in[6];  const float* sb2 = (const float*)d_in[7];
    const float* pw0  = (const float*)d_in[8];  const float* pb0 = (const float*)d_in[9];
    const float* pw1  = (const float*)d_in[10]; const float* pb1 = (const float*)d_in[11];
    const float* pw2  = (const float*)d_in[12]; const float* pb2 = (const float*)d_in[13];
    const float* latw = (const float*)d_in[14]; const float* latb = (const float*)d_in[15];
    const float* lng  = (const float*)d_in[16]; const float* lnb  = (const float*)d_in[17];
    const float* qkvw = (const float*)d_in[18]; const float* qkvb = (const float*)d_in[19];
    const float* pjw  = (const float*)d_in[20]; const float* pjb  = (const float*)d_in[21];
    float* lat = (float*)d_out;

    uint32_t *pkA, *pkB, *pkF, *pkX, *ynpk, *atpk;
    float *qkvB;
    uint8_t *wpk2;
    cudaGetSymbolAddress((void**)&pkA, g_pk_a);
    cudaGetSymbolAddress((void**)&pkB, g_pk_b);
    cudaGetSymbolAddress((void**)&pkF, g_pk_f);
    cudaGetSymbolAddress((void**)&pkX, g_pk_x2d);
    cudaGetSymbolAddress((void**)&ynpk, g_ynpk);
    cudaGetSymbolAddress((void**)&qkvB, g_qkv);
    cudaGetSymbolAddress((void**)&atpk, g_atpk);
    cudaGetSymbolAddress((void**)&wpk2, g_wpk2);

    cudaFuncSetAttribute(conv_mma_kernel<1>,
                         cudaFuncAttributeMaxDynamicSharedMemorySize, CONV_SMEM_BYTES);
    cudaFuncSetAttribute(conv_mma_kernel<2>,
                         cudaFuncAttributeMaxDynamicSharedMemorySize, CONV_SMEM_BYTES);
    cudaFuncSetAttribute(conv_mma_kernel<4>,
                         cudaFuncAttributeMaxDynamicSharedMemorySize, CONV_SMEM_BYTES);
    cudaFuncSetAttribute(tok_mma_kernel<1>,
                         cudaFuncAttributeMaxDynamicSharedMemorySize, CONV_SMEM_BYTES);
    cudaFuncSetAttribute(tok_mma_kernel<4>,
                         cudaFuncAttributeMaxDynamicSharedMemorySize, CONV_SMEM_BYTES);
    cudaFuncSetAttribute(natt_kernel,
                         cudaFuncAttributeMaxDynamicSharedMemorySize, NATT_SMEM_BYTES);

    auto run_conv = [&](const uint32_t* xpk, const float* wf, const float* bias,
                        uint32_t* outpk, float* outf,
                        int Cin, int D, int H, int W, int Dout, int Hout, int Wout,
                        int KD, int KH, int KW, int sd, int sh, int sw,
                        int pd, int ph, int pw, int Cout,
                        int outStrideC, int outOffset, int gelu) {
        int K = Cin * KD * KH * KW;
        int NC = (K + 63) / 64;
        int Kp = NC * 64;
        conv_decode_kernel<<<(Kp + 255) / 256, 256>>>(K, Kp, KD * KH * KW, KH * KW,
                                                      KW, D, H, W);
        wpack_kernel<<<dim3(NC, Cout / 128), 256>>>(wf, K, NC);
        int Nvox = Dout * Hout * Wout;
        ConvParams p{ xpk, wf, bias, outpk, outf,
                      D, H, W, Hout, Wout, sd, sh, sw, pd, ph, pw,
                      K, NC, outStrideC, outOffset, gelu };
        int nblk = Cout / 128;
        int bn = Nvox / 128;
        if (nblk % 4 == 0 && bn * (nblk / 4) >= 148)
            conv_mma_kernel<4><<<dim3(bn, nblk / 4), 512, CONV_SMEM_BYTES>>>(p);
        else if (nblk % 2 == 0 && bn * (nblk / 2) >= 148)
            conv_mma_kernel<2><<<dim3(bn, nblk / 2), 512, CONV_SMEM_BYTES>>>(p);
        else
            conv_mma_kernel<1><<<dim3(bn, nblk), 512, CONV_SMEM_BYTES>>>(p);
    };

    // launch order arranged so ncu (-s 5 -c 1) captures the big 3D conv (launch #6)
    natt_table_kernel<<<1, 256>>>();                                       // 1
    xpack_kernel<<<(5 * 24 * 256 * 512 / 4 + 255) / 256, 256>>>(
        x3d, pkA, 5 * 24 * 256 * 512 / 4);                                 // 2
    xpack_kernel<<<(8 * 256 * 512 / 4 + 255) / 256, 256>>>(
        x2d, pkX, 8 * 256 * 512 / 4);                                      // 3

    // ---- 3D tower (launches 4,5,6 = decode, wpack, conv3d0) ----
    run_conv(pkA, pw0, pb0, pkB, nullptr, 5, 24, 256, 512, 12, 128, 256,
             3, 3, 3, 2, 2, 2, 1, 1, 1, 128, 393216, 0, 1);
    run_conv(pkB, pw1, pb1, pkA, nullptr, 128, 12, 128, 256, 6, 64, 128,
             3, 3, 3, 2, 2, 2, 1, 1, 1, 256, 49152, 0, 1);
    run_conv(pkA, pw2, pb2, pkF, nullptr, 256, 6, 64, 128, 3, 32, 64,
             3, 3, 3, 2, 2, 2, 1, 1, 1, 512, 8192, 0, 1);

    // ---- 2D tower (buffers pkB/pkA free after 3D consumers done) ----
    run_conv(pkX, sw0, sb0, pkB, nullptr, 8, 1, 256, 512, 1, 128, 256,
             1, 3, 3, 1, 2, 2, 0, 1, 1, 128, 32768, 0, 1);
    run_conv(pkB, sw1, sb1, pkA, nullptr, 128, 1, 128, 256, 1, 64, 128,
             1, 3, 3, 1, 2, 2, 0, 1, 1, 256, 8192, 0, 1);
    run_conv(pkA, sw2, sb2, pkF, nullptr, 256, 1, 64, 128, 1, 32, 64,
             1, 3, 3, 1, 2, 2, 0, 1, 1, 512, 8192, 3 * 2048, 1);

    // ---- lateral 1x1x1 -> d_out fp32 ----
    run_conv(pkF, latw, latb, nullptr, lat, 512, 4, 32, 64, 4, 32, 64,
             1, 1, 1, 1, 1, 1, 0, 0, 0, 512, 8192, 0, 0);

    // ---- attention weight prepack ----
    const size_t QKV_PK = 8 * 12 * 32768;
    const size_t PRJ_PK = 8 * 4 * 32768;
    for (int i = 0; i < 3; i++) {
        wpackT_kernel<<<dim3(8, 12), 256>>>(qkvw + (size_t)i * 512 * 1536,
                                            wpk2 + i * QKV_PK, 512, 8, 1536);
        wpackT_kernel<<<dim3(8, 4), 256>>>(pjw + (size_t)i * 512 * 512,
                                           wpk2 + 3 * QKV_PK + i * PRJ_PK, 512, 8, 512);
    }

    // ---- 3 neighborhood-attention blocks ----
    for (int i = 0; i < 3; i++) {
        layernorm_kernel<<<8192 / 32, dim3(32, 8)>>>(lat, lng + i * 512, lnb + i * 512,
                                                     ynpk, 8192);
        TokParams pq{ ynpk, wpk2 + i * QKV_PK, qkvw + (size_t)i * 512 * 1536,
                      qkvb + i * 1536, qkvB, 8192, 1536, 512, 8, 0 };
        tok_mma_kernel<4><<<dim3(8192 / 128, 3), 512, CONV_SMEM_BYTES>>>(pq);
        natt_kernel<<<dim3(1024, 8), 256, NATT_SMEM_BYTES>>>(qkvB, atpk);
        TokParams pp{ atpk, wpk2 + 3 * QKV_PK + i * PRJ_PK,
                      pjw + (size_t)i * 512 * 512,
                      pjb + i * 512, lat, 8192, 512, 512, 8, 1 };
        tok_mma_kernel<1><<<dim3(8192 / 128, 4), 512, CONV_SMEM_BYTES>>>(pp);
    }
}

// round 10
// speedup vs baseline: 1.1471x; 1.1471x over previous
#include <cuda_runtime.h>
#include <cuda_bf16.h>
#include <math.h>
#include <cstdint>

#if defined(__CUDA_ARCH_SPECIFIC__) || defined(__CUDA_ARCH_FEAT_SM103_ALL)
#define HAS_TCGEN05 1
#else
#define HAS_TCGEN05 0
#endif

// ---------------------------------------------------------------------------
// Scratch buffers (packed u32 = bf16 hi << 16 | bf16 lo)
// ---------------------------------------------------------------------------
__device__ uint32_t g_pk_a[15728640];
__device__ uint32_t g_pk_b[50331648];
__device__ uint32_t g_pk_f[4194304];
__device__ uint32_t g_pk_x2d[1048576];
__device__ uint8_t  g_wpk[14155776];
__device__ uint8_t  g_wpk2[12582912];
__device__ uint32_t g_ynpk[8192 * 512];
__device__ float    g_qkv[8192 * 1536];
__device__ uint32_t g_atpk[8192 * 512];
__device__ int2     g_dec[8192];
__device__ int      g_ndelta[256];
__device__ int      g_npack[256];

// ---------------------------------------------------------------------------
// Common helpers
// ---------------------------------------------------------------------------
__device__ __forceinline__ uint32_t smem_u32(const void* p) {
    uint32_t a;
    asm("{ .reg .u64 t; cvta.to.shared.u64 t, %1; cvt.u32.u64 %0, t; }"
        : "=r"(a) : "l"(p));
    return a;
}
__device__ __forceinline__ float gelu_tanh(float x) {
    float x3 = x * x * x;
    float t = tanhf(0.7978845608028654f * (x + 0.044715f * x3));
    return 0.5f * x * (1.0f + t);
}
__device__ __forceinline__ uint32_t pack_hl(float f) {
    __nv_bfloat16 h = __float2bfloat16(f);
    __nv_bfloat16 l = __float2bfloat16(f - __bfloat162float(h));
    return ((uint32_t)__bfloat16_as_ushort(h) << 16) | __bfloat16_as_ushort(l);
}
__device__ __forceinline__ float unpack_hl(uint32_t v) {
    float h = __bfloat162float(__ushort_as_bfloat16((unsigned short)(v >> 16)));
    float l = __bfloat162float(__ushort_as_bfloat16((unsigned short)(v & 0xFFFF)));
    return h + l;
}

#if HAS_TCGEN05
__device__ __forceinline__ uint32_t elect_one() {
    uint32_t pred;
    asm volatile("{ .reg .pred p; elect.sync _|p, 0xFFFFFFFF; selp.b32 %0, 1, 0, p; }"
                 : "=r"(pred));
    return pred;
}
#define TCGEN05_ALLOC(a, n) \
    asm volatile("tcgen05.alloc.cta_group::1.sync.aligned.shared::cta.b32 [%0], %1;" \
                 :: "r"((uint32_t)(a)), "r"((uint32_t)(n)) : "memory")
#define TCGEN05_DEALLOC(t, n) \
    asm volatile("tcgen05.dealloc.cta_group::1.sync.aligned.b32 %0, %1;" :: "r"(t), "r"(n))
#define TCGEN05_RELINQ() \
    asm volatile("tcgen05.relinquish_alloc_permit.cta_group::1.sync.aligned;")
#define TCGEN05_COMMIT(m) \
    asm volatile("tcgen05.commit.cta_group::1.mbarrier::arrive::one.shared::cluster.b64 [%0];" \
                 :: "r"((uint32_t)(m)) : "memory")
#define TCGEN05_FENCE_AFTER() \
    asm volatile("tcgen05.fence::after_thread_sync;" ::: "memory")
#define TCGEN05_FENCE_BEFORE() \
    asm volatile("tcgen05.fence::before_thread_sync;" ::: "memory")
#define TCGEN05_WAIT_LD() asm volatile("tcgen05.wait::ld.sync.aligned;" ::: "memory")
#define FENCE_PROXY_ASYNC() asm volatile("fence.proxy.async.shared::cta;" ::: "memory")
#define MBARRIER_INIT(m, c) \
    asm volatile("mbarrier.init.shared.b64 [%0], %1;" :: "r"((uint32_t)(m)), "r"((uint32_t)(c)) : "memory")
#define MBARRIER_INVAL(m) \
    asm volatile("mbarrier.inval.shared.b64 [%0];" :: "r"((uint32_t)(m)) : "memory")
#define MBARRIER_WAIT_PARITY(m, ph) do {                                           \
    uint32_t _m = (uint32_t)(m), _p = (uint32_t)(ph), _d;                          \
    asm volatile("{ .reg .pred p; mbarrier.try_wait.parity.acquire.cta.shared::cta.b64 p, [%1], %2;" \
                 " selp.b32 %0, 1, 0, p; }" : "=r"(_d) : "r"(_m), "r"(_p) : "memory"); \
    if (!_d) {                                                                     \
        asm volatile("{ .reg .pred P1; WL_%=: mbarrier.try_wait.parity.acquire.cta.shared::cta.b64 P1, [%0], %1, 0x989680;" \
                     " @P1 bra.uni WD_%=; bra.uni WL_%=; WD_%=: }"                 \
                     :: "r"(_m), "r"(_p) : "memory");                              \
    }                                                                              \
} while (0)
#define TCGEN05_LD_X32(r, a)                                                       \
    asm volatile("tcgen05.ld.sync.aligned.32x32b.x32.b32 "                         \
        "{%0, %1, %2, %3, %4, %5, %6, %7, %8, %9, %10, %11, %12, %13, %14, %15, "  \
        " %16, %17, %18, %19, %20, %21, %22, %23, %24, %25, %26, %27, %28, %29, %30, %31}, [%32];" \
        : "=r"((r)[0]), "=r"((r)[1]), "=r"((r)[2]), "=r"((r)[3]),                  \
          "=r"((r)[4]), "=r"((r)[5]), "=r"((r)[6]), "=r"((r)[7]),                  \
          "=r"((r)[8]), "=r"((r)[9]), "=r"((r)[10]), "=r"((r)[11]),                \
          "=r"((r)[12]), "=r"((r)[13]), "=r"((r)[14]), "=r"((r)[15]),              \
          "=r"((r)[16]), "=r"((r)[17]), "=r"((r)[18]), "=r"((r)[19]),              \
          "=r"((r)[20]), "=r"((r)[21]), "=r"((r)[22]), "=r"((r)[23]),              \
          "=r"((r)[24]), "=r"((r)[25]), "=r"((r)[26]), "=r"((r)[27]),              \
          "=r"((r)[28]), "=r"((r)[29]), "=r"((r)[30]), "=r"((r)[31])               \
        : "r"(a))

static constexpr uint64_t SMEM_DESC_BASE_SW128 =
    (uint64_t(2) << 61) | (uint64_t(1) << 46) | (uint64_t(64) << 32) | (uint64_t(1) << 16);
__device__ __forceinline__ uint64_t make_desc(uint32_t addr) {
    return SMEM_DESC_BASE_SW128 | ((uint64_t)(addr >> 4) & 0x3FFF);
}
__device__ __forceinline__ void mma_f16_ss(uint32_t d, uint64_t ad, uint64_t bd,
                                           uint32_t idesc, uint32_t en) {
    asm volatile(
        "{ .reg .pred p; setp.ne.u32 p, %5, 0;\n\t"
        "tcgen05.mma.cta_group::1.kind::f16 [%0], %1, %2, %3, {%4, %4, %4, %4}, p; }"
        :: "r"(d), "l"(ad), "l"(bd), "r"(idesc), "r"(0u), "r"(en) : "memory");
}
static constexpr uint32_t CONV_IDESC =
    (1u << 4) | (1u << 7) | (1u << 10) | ((128u / 8) << 17) | ((128u / 16) << 24);
#endif // HAS_TCGEN05

#define SME_A0 0
#define SME_A1 32768
#define SME_B0 65536
#define SME_B1 98304
#define SME_MBAR 131072
#define SME_TSLOT 131104
#define CONV_SMEM_BYTES (1024 + 131072 + 128)

// ---------------------------------------------------------------------------
// Init / pack kernels
// ---------------------------------------------------------------------------
__global__ void conv_decode_kernel(int K, int Kpad, int KV, int KHW, int KW,
                                   int D, int H, int W) {
    int k = blockIdx.x * 256 + threadIdx.x;
    if (k >= Kpad) return;
    if (k < K) {
        int ci = k / KV; int tap = k - ci * KV;
        int kd = tap / KHW; int t2 = tap - kd * KHW;
        int kh = t2 / KW; int kw = t2 - kh * KW;
        g_dec[k] = make_int2(((ci * D + kd) * H + kh) * W + kw,
                             (kd << 20) | (kh << 10) | kw);
    } else {
        g_dec[k] = make_int2(0, 1023 << 20);
    }
}

__global__ void natt_table_kernel() {
    int nb = threadIdx.x;
    if (nb < 245) {
        int od = nb / 49; int r = nb - od * 49;
        int oh = r / 7;   int ow = r - oh * 7;
        g_ndelta[nb] = (od - 2) * 2048 + (oh - 3) * 64 + (ow - 3);
        g_npack[nb]  = (od << 16) | (oh << 8) | ow;
    }
}

__global__ void xpack_kernel(const float* __restrict__ x,
                             uint32_t* __restrict__ dst, int n4) {
    int i = blockIdx.x * 256 + threadIdx.x;
    if (i >= n4) return;
    float4 v = reinterpret_cast<const float4*>(x)[i];
    uint4 o;
    o.x = pack_hl(v.x); o.y = pack_hl(v.y);
    o.z = pack_hl(v.z); o.w = pack_hl(v.w);
    reinterpret_cast<uint4*>(dst)[i] = o;
}

__global__ void wpack_kernel(const float* __restrict__ w, int K, int NC) {
    int kc = blockIdx.x, bm = blockIdx.y;
    int tid = threadIdx.x;
    int r = tid >> 1, half = tid & 1;
    const float* wrow = w + (size_t)(bm * 128 + r) * K;
    uint8_t* hi = g_wpk + (size_t)(bm * NC + kc) * 32768;
    uint8_t* lo = hi + 16384;
#pragma unroll
    for (int i = 0; i < 16; i++) {
        int kk = half * 32 + 2 * i;
        int k = kc * 64 + kk;
        float a0 = (k < K) ? wrow[k] : 0.f;
        float a1 = (k + 1 < K) ? wrow[k + 1] : 0.f;
        uint32_t p0 = pack_hl(a0), p1 = pack_hl(a1);
        uint32_t hp = __byte_perm(p0, p1, 0x7632);
        uint32_t lp = __byte_perm(p0, p1, 0x5410);
        uint32_t off = r * 128 + kk * 2;
        uint32_t sw = off ^ ((off >> 3) & 0x70);
        *reinterpret_cast<uint32_t*>(hi + sw) = hp;
        *reinterpret_cast<uint32_t*>(lo + sw) = lp;
    }
}

__global__ void wpackT_kernel(const float* __restrict__ w, uint8_t* dst,
                              int K, int NC, int J) {
    int kc = blockIdx.x, bm = blockIdx.y;
    int tid = threadIdx.x;
    int r = tid >> 1, half = tid & 1;
    int m = bm * 128 + r;
    uint8_t* hi = dst + (size_t)(bm * NC + kc) * 32768;
    uint8_t* lo = hi + 16384;
#pragma unroll
    for (int i = 0; i < 16; i++) {
        int kk = half * 32 + 2 * i;
        int k = kc * 64 + kk;
        float a0 = (k < K) ? w[(size_t)k * J + m] : 0.f;
        float a1 = (k + 1 < K) ? w[(size_t)(k + 1) * J + m] : 0.f;
        uint32_t p0 = pack_hl(a0), p1 = pack_hl(a1);
        uint32_t hp = __byte_perm(p0, p1, 0x7632);
        uint32_t lp = __byte_perm(p0, p1, 0x5410);
        uint32_t off = r * 128 + kk * 2;
        uint32_t sw = off ^ ((off >> 3) & 0x70);
        *reinterpret_cast<uint32_t*>(hi + sw) = hp;
        *reinterpret_cast<uint32_t*>(lo + sw) = lp;
    }
}

// ---------------------------------------------------------------------------
// Conv kernel (R8 structure, mbarrier ring of 4)
// ---------------------------------------------------------------------------
struct ConvParams {
    const uint32_t* xpk;
    const float* wf;
    const float* bias;
    uint32_t* outpk;
    float* outf;
    int D, H, W;
    int Hout, Wout;
    int sd, sh, sw, pd, ph, pw;
    int K, NC;
    int outStrideC, outOffset;
    int gelu;
};

template <int BM>
__global__ __launch_bounds__(512) void conv_mma_kernel(ConvParams p) {
    extern __shared__ char smem_raw[];
    char* smem_al = (char*)(((uintptr_t)smem_raw + 1023) & ~(uintptr_t)1023);

    const int tid = threadIdx.x;
    const int bn = blockIdx.x;
    const int mblk0 = blockIdx.y * BM;
    const int HWo = p.Hout * p.Wout;

#if HAS_TCGEN05
    const uint32_t sb = smem_u32(smem_al);
    const uint32_t mbar = sb + SME_MBAR;
    const uint32_t tmem_slot = sb + SME_TSLOT;
    const int wid = tid >> 5;
    const int lane = tid & 31;

    if (wid == 0) {
        TCGEN05_ALLOC(tmem_slot, 512);
        TCGEN05_RELINQ();
    }
    if (tid == 0) {
#pragma unroll
        for (int i = 0; i < 4; i++) MBARRIER_INIT(mbar + 8 * i, 1);
    }
    __syncthreads();
    uint32_t tmem;
    asm volatile("ld.shared.b32 %0, [%1];" : "=r"(tmem) : "r"(tmem_slot));

    const int r = tid >> 2;
    const int q = tid & 3;
    const int n = bn * 128 + r;
    const int od = n / HWo; int rr2 = n - od * HWo;
    const int oh = rr2 / p.Wout; const int ow = rr2 - oh * p.Wout;
    const int id0 = od * p.sd - p.pd;
    const int ih0 = oh * p.sh - p.ph;
    const int iw0 = ow * p.sw - p.pw;
    const int gbase = (id0 * p.H + ih0) * p.W + iw0;
    const int NC = p.NC;

    auto fillA = [&](int ab, int kc, int bm) {
        const uint8_t* src = g_wpk + ((size_t)(mblk0 + bm) * NC + kc) * 32768 + tid * 16;
        char* dst = smem_al + (ab ? SME_A1 : SME_A0) + tid * 16;
#pragma unroll
        for (int i = 0; i < 4; i++) {
            uint4 v = *reinterpret_cast<const uint4*>(src + i * 8192);
            *reinterpret_cast<uint4*>(dst + i * 8192) = v;
        }
    };
    auto fillB = [&](int st, int kc) {
        char* Bhi = smem_al + (st ? SME_B1 : SME_B0);
        char* Blo = Bhi + 16384;
        const int kt = kc * 64;
#pragma unroll
        for (int i = 0; i < 8; i++) {
            int kk = q * 16 + 2 * i;
            int k = kt + kk;
            int4 dv = *reinterpret_cast<const int4*>(&g_dec[k]);
            uint32_t v0 = 0, v1 = 0;
            {
                int kd = dv.y >> 20, kh = (dv.y >> 10) & 1023, kw = dv.y & 1023;
                if ((unsigned)(id0 + kd) < (unsigned)p.D &&
                    (unsigned)(ih0 + kh) < (unsigned)p.H &&
                    (unsigned)(iw0 + kw) < (unsigned)p.W)
                    v0 = p.xpk[gbase + dv.x];
            }
            {
                int kd = dv.w >> 20, kh = (dv.w >> 10) & 1023, kw = dv.w & 1023;
                if ((unsigned)(id0 + kd) < (unsigned)p.D &&
                    (unsigned)(ih0 + kh) < (unsigned)p.H &&
                    (unsigned)(iw0 + kw) < (unsigned)p.W)
                    v1 = p.xpk[gbase + dv.z];
            }
            uint32_t off = r * 128 + kk * 2;
            uint32_t sw = off ^ ((off >> 3) & 0x70);
            *reinterpret_cast<uint32_t*>(Bhi + sw) = __byte_perm(v0, v1, 0x7632);
            *reinterpret_cast<uint32_t*>(Blo + sw) = __byte_perm(v0, v1, 0x5410);
        }
    };

    int wpar = 0;
    auto waitCommits = [&](int target) {
        while (wpar < target) {
            MBARRIER_WAIT_PARITY(mbar + 8 * (wpar & 3), (wpar >> 2) & 1);
            wpar++;
        }
    };

    fillB(0, 0);

    for (int kc = 0; kc < NC; kc++) {
        int st = kc & 1;
#pragma unroll
        for (int bm = 0; bm < BM; bm++) {
            int ni = kc * BM + bm;
            if (ni >= 2) waitCommits(ni - 1);
            fillA(ni & 1, kc, bm);
            FENCE_PROXY_ASYNC();
            __syncthreads();
            if (wid == 0 && elect_one()) {
                uint64_t dAh = make_desc(sb + ((ni & 1) ? SME_A1 : SME_A0));
                uint64_t dAl = dAh + (16384 >> 4);
                uint64_t dBh = make_desc(sb + (st ? SME_B1 : SME_B0));
                uint64_t dBl = dBh + (16384 >> 4);
                uint32_t d = tmem + bm * 128;
                uint32_t first = (kc == 0) ? 0u : 1u;
#pragma unroll
                for (int s = 0; s < 4; s++) {
                    uint64_t o = s * 2;
                    mma_f16_ss(d, dAh + o, dBh + o, CONV_IDESC, first); first = 1;
                    mma_f16_ss(d, dAh + o, dBl + o, CONV_IDESC, 1);
                    mma_f16_ss(d, dAl + o, dBh + o, CONV_IDESC, 1);
                }
                TCGEN05_COMMIT(mbar + 8 * (ni & 3));
            }
        }
        if (kc + 1 < NC) {
            waitCommits(kc * BM);
            fillB(st ^ 1, kc + 1);
        }
    }
    waitCommits(NC * BM);
    TCGEN05_FENCE_AFTER();

    {
        const int sp = wid & 3;
        const int cb = wid >> 2;
#pragma unroll
        for (int bm = 0; bm < BM; bm++) {
            const int m = (mblk0 + bm) * 128 + sp * 32 + lane;
            const float bv = p.bias[m];
            uint32_t dr[32];
            TCGEN05_LD_X32(dr, tmem + bm * 128 + cb * 32);
            TCGEN05_WAIT_LD();
            size_t obase = (size_t)m * p.outStrideC + p.outOffset + bn * 128 + cb * 32;
            if (p.outpk) {
                uint32_t* orow = p.outpk + obase;
#pragma unroll
                for (int j = 0; j < 32; j++) {
                    float v = __uint_as_float(dr[j]) + bv;
                    if (p.gelu) v = gelu_tanh(v);
                    orow[j] = pack_hl(v);
                }
            } else {
                float* orow = p.outf + obase;
#pragma unroll
                for (int j = 0; j < 32; j++) {
                    float v = __uint_as_float(dr[j]) + bv;
                    if (p.gelu) v = gelu_tanh(v);
                    orow[j] = v;
                }
            }
        }
        TCGEN05_FENCE_BEFORE();
    }
    __syncthreads();
    if (tid == 0) {
#pragma unroll
        for (int i = 0; i < 4; i++) MBARRIER_INVAL(mbar + 8 * i);
    }
    if (wid == 0) TCGEN05_DEALLOC(tmem, 512);

#else  // FFMA fallback (never executes on GB300)
    for (int bm = 0; bm < BM; bm++) {
        const int m_base = (mblk0 + bm) * 128;
        for (int idx = tid; idx < 128 * 128; idx += 512) {
            int ml = idx >> 7, nl = idx & 127;
            int m = m_base + ml;
            int nn = bn * 128 + nl;
            int od = nn / HWo; int rr2 = nn - od * HWo;
            int oh = rr2 / p.Wout; int ow = rr2 - oh * p.Wout;
            int id0 = od * p.sd - p.pd, ih0 = oh * p.sh - p.ph, iw0 = ow * p.sw - p.pw;
            int gb = (id0 * p.H + ih0) * p.W + iw0;
            float s = 0.f;
            for (int k = 0; k < p.K; k++) {
                int2 dv = g_dec[k];
                int kd = dv.y >> 20, kh = (dv.y >> 10) & 1023, kw = dv.y & 1023;
                if ((unsigned)(id0 + kd) < (unsigned)p.D &&
                    (unsigned)(ih0 + kh) < (unsigned)p.H &&
                    (unsigned)(iw0 + kw) < (unsigned)p.W)
                    s += p.wf[(size_t)m * p.K + k] * unpack_hl(p.xpk[gb + dv.x]);
            }
            s += p.bias[m];
            if (p.gelu) s = gelu_tanh(s);
            size_t ob = (size_t)m * p.outStrideC + p.outOffset + nn;
            if (p.outpk) p.outpk[ob] = pack_hl(s);
            else p.outf[ob] = s;
        }
    }
#endif
}

// ---------------------------------------------------------------------------
// Token GEMM (R8 structure, mbarrier ring of 4)
// ---------------------------------------------------------------------------
struct TokParams {
    const uint32_t* bpk;
    const uint8_t* wpk;
    const float* wf;
    const float* bias;
    float* out;
    int T, J, Kdim, NC, mode;
};

template <int BM>
__global__ __launch_bounds__(512) void tok_mma_kernel(TokParams p) {
    extern __shared__ char smem_raw[];
    char* smem_al = (char*)(((uintptr_t)smem_raw + 1023) & ~(uintptr_t)1023);

    const int tid = threadIdx.x;
    const int bn = blockIdx.x;
    const int mblk0 = blockIdx.y * BM;

#if HAS_TCGEN05
    const uint32_t sb = smem_u32(smem_al);
    const uint32_t mbar = sb + SME_MBAR;
    const uint32_t tmem_slot = sb + SME_TSLOT;
    const int wid = tid >> 5;
    const int lane = tid & 31;

    if (wid == 0) {
        TCGEN05_ALLOC(tmem_slot, 512);
        TCGEN05_RELINQ();
    }
    if (tid == 0) {
#pragma unroll
        for (int i = 0; i < 4; i++) MBARRIER_INIT(mbar + 8 * i, 1);
    }
    __syncthreads();
    uint32_t tmem;
    asm volatile("ld.shared.b32 %0, [%1];" : "=r"(tmem) : "r"(tmem_slot));

    const int r = tid >> 2;
    const int q = tid & 3;
    const uint32_t* bsrc = p.bpk + (size_t)(bn * 128 + r) * p.Kdim;
    const int NC = p.NC;

    auto fillA = [&](int ab, int kc, int bm) {
        const uint8_t* src = p.wpk + ((size_t)(mblk0 + bm) * NC + kc) * 32768 + tid * 16;
        char* dst = smem_al + (ab ? SME_A1 : SME_A0) + tid * 16;
#pragma unroll
        for (int i = 0; i < 4; i++) {
            uint4 v = *reinterpret_cast<const uint4*>(src + i * 8192);
            *reinterpret_cast<uint4*>(dst + i * 8192) = v;
        }
    };
    auto fillB = [&](int st, int kc) {
        char* Bhi = smem_al + (st ? SME_B1 : SME_B0);
        char* Blo = Bhi + 16384;
        const uint32_t* src = bsrc + kc * 64 + q * 16;
        uint32_t buf[16];
#pragma unroll
        for (int i = 0; i < 4; i++)
            *reinterpret_cast<uint4*>(&buf[i * 4]) =
                *reinterpret_cast<const uint4*>(src + i * 4);
#pragma unroll
        for (int i = 0; i < 8; i++) {
            int kk = q * 16 + 2 * i;
            uint32_t v0 = buf[2 * i], v1 = buf[2 * i + 1];
            uint32_t off = r * 128 + kk * 2;
            uint32_t sw = off ^ ((off >> 3) & 0x70);
            *reinterpret_cast<uint32_t*>(Bhi + sw) = __byte_perm(v0, v1, 0x7632);
            *reinterpret_cast<uint32_t*>(Blo + sw) = __byte_perm(v0, v1, 0x5410);
        }
    };

    int wpar = 0;
    auto waitCommits = [&](int target) {
        while (wpar < target) {
            MBARRIER_WAIT_PARITY(mbar + 8 * (wpar & 3), (wpar >> 2) & 1);
            wpar++;
        }
    };

    fillB(0, 0);

    for (int kc = 0; kc < NC; kc++) {
        int st = kc & 1;
#pragma unroll
        for (int bm = 0; bm < BM; bm++) {
            int ni = kc * BM + bm;
            if (ni >= 2) waitCommits(ni - 1);
            fillA(ni & 1, kc, bm);
            FENCE_PROXY_ASYNC();
            __syncthreads();
            if (wid == 0 && elect_one()) {
                uint64_t dAh = make_desc(sb + ((ni & 1) ? SME_A1 : SME_A0));
                uint64_t dAl = dAh + (16384 >> 4);
                uint64_t dBh = make_desc(sb + (st ? SME_B1 : SME_B0));
                uint64_t dBl = dBh + (16384 >> 4);
                uint32_t d = tmem + bm * 128;
                uint32_t first = (kc == 0) ? 0u : 1u;
#pragma unroll
                for (int s = 0; s < 4; s++) {
                    uint64_t o = s * 2;
                    mma_f16_ss(d, dAh + o, dBh + o, CONV_IDESC, first); first = 1;
                    mma_f16_ss(d, dAh + o, dBl + o, CONV_IDESC, 1);
                    mma_f16_ss(d, dAl + o, dBh + o, CONV_IDESC, 1);
                }
                TCGEN05_COMMIT(mbar + 8 * (ni & 3));
            }
        }
        if (kc + 1 < NC) {
            waitCommits(kc * BM);
            fillB(st ^ 1, kc + 1);
        }
    }
    waitCommits(NC * BM);
    TCGEN05_FENCE_AFTER();

    {
        const int sp = wid & 3;
        const int cb = wid >> 2;
        const int t0 = bn * 128 + cb * 32;
#pragma unroll
        for (int bm = 0; bm < BM; bm++) {
            const int m = (mblk0 + bm) * 128 + sp * 32 + lane;
            const float bv = p.bias[m];
            uint32_t dr[32];
            TCGEN05_LD_X32(dr, tmem + bm * 128 + cb * 32);
            TCGEN05_WAIT_LD();
            if (p.mode == 0) {
#pragma unroll
                for (int j = 0; j < 32; j++)
                    p.out[(size_t)(t0 + j) * p.J + m] = __uint_as_float(dr[j]) + bv;
            } else {
                float* orow = p.out + (size_t)m * p.T + t0;
#pragma unroll
                for (int j = 0; j < 8; j++) {
                    float4* cp = reinterpret_cast<float4*>(orow + j * 4);
                    float4 o = *cp;
                    o.x += __uint_as_float(dr[j * 4 + 0]) + bv;
                    o.y += __uint_as_float(dr[j * 4 + 1]) + bv;
                    o.z += __uint_as_float(dr[j * 4 + 2]) + bv;
                    o.w += __uint_as_float(dr[j * 4 + 3]) + bv;
                    *cp = o;
                }
            }
        }
        TCGEN05_FENCE_BEFORE();
    }
    __syncthreads();
    if (tid == 0) {
#pragma unroll
        for (int i = 0; i < 4; i++) MBARRIER_INVAL(mbar + 8 * i);
    }
    if (wid == 0) TCGEN05_DEALLOC(tmem, 512);

#else  // FFMA fallback
    for (int bm = 0; bm < BM; bm++) {
        int m_base = (mblk0 + bm) * 128;
        for (int idx = tid; idx < 128 * 128; idx += 512) {
            int tl = idx >> 7, jl = idx & 127;
            int t = bn * 128 + tl, j = m_base + jl;
            float s = 0.f;
            for (int k = 0; k < p.Kdim; k++)
                s += unpack_hl(p.bpk[(size_t)t * p.Kdim + k]) * p.wf[(size_t)k * p.J + j];
            s += p.bias[j];
            if (p.mode == 0) p.out[(size_t)t * p.J + j] = s;
            else p.out[(size_t)j * p.T + t] += s;
        }
    }
#endif
}

// ---------------------------------------------------------------------------
// LayerNorm: fp32 channel-major -> packed token-major
// ---------------------------------------------------------------------------
__global__ __launch_bounds__(256) void layernorm_kernel(
    const float* __restrict__ x, const float* __restrict__ g,
    const float* __restrict__ b, uint32_t* __restrict__ ypk, int T) {
    const int tx = threadIdx.x;
    const int ty = threadIdx.y;
    const int t = blockIdx.x * 32 + tx;

    float s = 0.f, ss = 0.f;
#pragma unroll
    for (int i = 0; i < 64; i++) {
        int c = ty * 64 + i;
        float v = x[(size_t)c * T + t];
        s += v; ss += v * v;
    }
    __shared__ float shs[8][32], shss[8][32];
    __shared__ float smu[32], srs[32];
    shs[ty][tx] = s; shss[ty][tx] = ss;
    __syncthreads();
    if (ty == 0) {
        float S = 0.f, SS = 0.f;
#pragma unroll
        for (int j = 0; j < 8; j++) { S += shs[j][tx]; SS += shss[j][tx]; }
        float mu = S * (1.f / 512.f);
        float var = SS * (1.f / 512.f) - mu * mu;
        smu[tx] = mu;
        srs[tx] = rsqrtf(var + 1e-5f);
    }
    __syncthreads();
    float mu = smu[tx], rs = srs[tx];
    uint32_t* yrow = ypk + (size_t)t * 512 + ty * 64;
#pragma unroll
    for (int i = 0; i < 64; i++) {
        int c = ty * 64 + i;
        float v = x[(size_t)c * T + t];
        yrow[i] = pack_hl((v - mu) * rs * g[c] + b[c]);
    }
}

// ---------------------------------------------------------------------------
// Neighborhood attention — coalesced score phase (lane = channel pair,
// smem-transpose batch reduce), R8-style softmax + PV.
// Block 256 = 8 warps, warp = one (token, head). Grid (1024, 8).
// ---------------------------------------------------------------------------
__global__ __launch_bounds__(256) void natt_kernel(
    const float* __restrict__ qkv, uint32_t* __restrict__ atpk) {
    __shared__ float psh[8][248];
    __shared__ float tsh[8][32][33];   // transpose buffer per warp

    const int warp = threadIdx.x >> 5;
    const int lane = threadIdx.x & 31;
    const int t = blockIdx.x * 8 + warp;
    const int head = blockIdx.y;
    const int d = t >> 11;
    const int hh = (t >> 6) & 31;
    const int ww = t & 63;

    // lane owns K/Q channels 2*lane, 2*lane+1
    float2 q2 = *reinterpret_cast<const float2*>(
        qkv + (size_t)t * 1536 + head * 64 + 2 * lane);
    q2.x *= 0.125f; q2.y *= 0.125f;

    float sc[8];
    float m = -1e30f;
#pragma unroll
    for (int it = 0; it < 8; it++) {
        // compute partial dots for 32 neighbors of this batch (coalesced loads)
#pragma unroll
        for (int j = 0; j < 32; j++) {
            int nb = it * 32 + j;
            float pv = 0.f;
            if (nb < 245) {
                int pk = g_npack[nb];
                int nd = d + (pk >> 16) - 2;
                int nh = hh + ((pk >> 8) & 255) - 3;
                int nw = ww + (pk & 255) - 3;
                if ((unsigned)nd < 4u && (unsigned)nh < 32u && (unsigned)nw < 64u) {
                    int nt = (nd * 32 + nh) * 64 + nw;
                    float2 kv = *reinterpret_cast<const float2*>(
                        qkv + (size_t)nt * 1536 + 512 + head * 64 + 2 * lane);
                    pv = fmaf(q2.x, kv.x, q2.y * kv.y);
                }
            }
            tsh[warp][j][lane] = pv;      // conflict-free (consecutive lanes)
        }
        __syncwarp();
        // lane sums column `lane`: full dot of neighbor it*32+lane
        float s = 0.f;
#pragma unroll
        for (int j = 0; j < 32; j++) s += tsh[warp][lane][j];   // stride 33: conflict-free
        __syncwarp();

        // validity for own neighbor
        int nb = it * 32 + lane;
        float dot = -1e30f;
        if (nb < 245) {
            int pk = g_npack[nb];
            int nd = d + (pk >> 16) - 2;
            int nh = hh + ((pk >> 8) & 255) - 3;
            int nw = ww + (pk & 255) - 3;
            if ((unsigned)nd < 4u && (unsigned)nh < 32u && (unsigned)nw < 64u)
                dot = s;
        }
        sc[it] = dot;
        m = fmaxf(m, dot);
    }
#pragma unroll
    for (int o = 16; o; o >>= 1) m = fmaxf(m, __shfl_xor_sync(0xffffffffu, m, o));

    float l = 0.f;
#pragma unroll
    for (int it = 0; it < 8; it++) {
        int nb = it * 32 + lane;
        float e = (sc[it] > -1e29f) ? __expf(sc[it] - m) : 0.f;
        if (nb < 248) psh[warp][nb] = e;
        l += e;
    }
#pragma unroll
    for (int o = 16; o; o >>= 1) l += __shfl_xor_sync(0xffffffffu, l, o);
    __syncwarp();

    // PV phase (coalesced: lane = channel)
    float acc0 = 0.f, acc1 = 0.f;
    for (int nb = 0; nb < 245; nb++) {
        float pb = psh[warp][nb];
        if (pb > 0.f) {
            int nt = t + g_ndelta[nb];
            const float* vp = qkv + (size_t)nt * 1536 + 1024 + head * 64;
            acc0 = fmaf(pb, vp[lane], acc0);
            acc1 = fmaf(pb, vp[lane + 32], acc1);
        }
    }
    float inv = 1.f / l;
    uint32_t* op = atpk + (size_t)t * 512 + head * 64;
    op[lane] = pack_hl(acc0 * inv);
    op[lane + 32] = pack_hl(acc1 * inv);
}

// ---------------------------------------------------------------------------
// Host launcher
// ---------------------------------------------------------------------------
extern "C" void kernel_launch(void* const* d_in, const int* in_sizes, int n_in,
                              void* d_out, int out_size) {
    const float* x2d  = (const float*)d_in[0];
    const float* x3d  = (const float*)d_in[1];
    const float* sw0  = (const float*)d_in[2];  const float* sb0 = (const float*)d_in[3];
    const float* sw1  = (const float*)d_in[4];  const float* sb1 = (const float*)d_in[5];
    const float* sw2  = (const float*)d_in[6];  const float* sb2 = (const float*)d_in[7];
    const float* pw0  = (const float*)d_in[8];  const float* pb0 = (const float*)d_in[9];
    const float* pw1  = (const float*)d_in[10]; const float* pb1 = (const float*)d_in[11];
    const float* pw2  = (const float*)d_in[12]; const float* pb2 = (const float*)d_in[13];
    const float* latw = (const float*)d_in[14]; const float* latb = (const float*)d_in[15];
    const float* lng  = (const float*)d_in[16]; const float* lnb  = (const float*)d_in[17];
    const float* qkvw = (const float*)d_in[18]; const float* qkvb = (const float*)d_in[19];
    const float* pjw  = (const float*)d_in[20]; const float* pjb  = (const float*)d_in[21];
    float* lat = (float*)d_out;

    uint32_t *pkA, *pkB, *pkF, *pkX, *ynpk, *atpk;
    float *qkvB;
    uint8_t *wpk2;
    cudaGetSymbolAddress((void**)&pkA, g_pk_a);
    cudaGetSymbolAddress((void**)&pkB, g_pk_b);
    cudaGetSymbolAddress((void**)&pkF, g_pk_f);
    cudaGetSymbolAddress((void**)&pkX, g_pk_x2d);
    cudaGetSymbolAddress((void**)&ynpk, g_ynpk);
    cudaGetSymbolAddress((void**)&qkvB, g_qkv);
    cudaGetSymbolAddress((void**)&atpk, g_atpk);
    cudaGetSymbolAddress((void**)&wpk2, g_wpk2);

    cudaFuncSetAttribute(conv_mma_kernel<1>,
                         cudaFuncAttributeMaxDynamicSharedMemorySize, CONV_SMEM_BYTES);
    cudaFuncSetAttribute(conv_mma_kernel<2>,
                         cudaFuncAttributeMaxDynamicSharedMemorySize, CONV_SMEM_BYTES);
    cudaFuncSetAttribute(conv_mma_kernel<4>,
                         cudaFuncAttributeMaxDynamicSharedMemorySize, CONV_SMEM_BYTES);
    cudaFuncSetAttribute(tok_mma_kernel<1>,
                         cudaFuncAttributeMaxDynamicSharedMemorySize, CONV_SMEM_BYTES);
    cudaFuncSetAttribute(tok_mma_kernel<4>,
                         cudaFuncAttributeMaxDynamicSharedMemorySize, CONV_SMEM_BYTES);

    auto run_conv = [&](const uint32_t* xpk, const float* wf, const float* bias,
                        uint32_t* outpk, float* outf,
                        int Cin, int D, int H, int W, int Dout, int Hout, int Wout,
                        int KD, int KH, int KW, int sd, int sh, int sw,
                        int pd, int ph, int pw, int Cout,
                        int outStrideC, int outOffset, int gelu) {
        int K = Cin * KD * KH * KW;
        int NC = (K + 63) / 64;
        int Kp = NC * 64;
        conv_decode_kernel<<<(Kp + 255) / 256, 256>>>(K, Kp, KD * KH * KW, KH * KW,
                                                      KW, D, H, W);
        wpack_kernel<<<dim3(NC, Cout / 128), 256>>>(wf, K, NC);
        int Nvox = Dout * Hout * Wout;
        ConvParams p{ xpk, wf, bias, outpk, outf,
                      D, H, W, Hout, Wout, sd, sh, sw, pd, ph, pw,
                      K, NC, outStrideC, outOffset, gelu };
        int nblk = Cout / 128;
        int bn = Nvox / 128;
        if (nblk % 4 == 0 && bn * (nblk / 4) >= 148)
            conv_mma_kernel<4><<<dim3(bn, nblk / 4), 512, CONV_SMEM_BYTES>>>(p);
        else if (nblk % 2 == 0 && bn * (nblk / 2) >= 148)
            conv_mma_kernel<2><<<dim3(bn, nblk / 2), 512, CONV_SMEM_BYTES>>>(p);
        else
            conv_mma_kernel<1><<<dim3(bn, nblk), 512, CONV_SMEM_BYTES>>>(p);
    };

    natt_table_kernel<<<1, 256>>>();
    xpack_kernel<<<(5 * 24 * 256 * 512 / 4 + 255) / 256, 256>>>(
        x3d, pkA, 5 * 24 * 256 * 512 / 4);
    xpack_kernel<<<(8 * 256 * 512 / 4 + 255) / 256, 256>>>(
        x2d, pkX, 8 * 256 * 512 / 4);

    // ---- 3D tower ----
    run_conv(pkA, pw0, pb0, pkB, nullptr, 5, 24, 256, 512, 12, 128, 256,
             3, 3, 3, 2, 2, 2, 1, 1, 1, 128, 393216, 0, 1);
    run_conv(pkB, pw1, pb1, pkA, nullptr, 128, 12, 128, 256, 6, 64, 128,
             3, 3, 3, 2, 2, 2, 1, 1, 1, 256, 49152, 0, 1);
    run_conv(pkA, pw2, pb2, pkF, nullptr, 256, 6, 64, 128, 3, 32, 64,
             3, 3, 3, 2, 2, 2, 1, 1, 1, 512, 8192, 0, 1);

    // ---- 2D tower ----
    run_conv(pkX, sw0, sb0, pkB, nullptr, 8, 1, 256, 512, 1, 128, 256,
             1, 3, 3, 1, 2, 2, 0, 1, 1, 128, 32768, 0, 1);
    run_conv(pkB, sw1, sb1, pkA, nullptr, 128, 1, 128, 256, 1, 64, 128,
             1, 3, 3, 1, 2, 2, 0, 1, 1, 256, 8192, 0, 1);
    run_conv(pkA, sw2, sb2, pkF, nullptr, 256, 1, 64, 128, 1, 32, 64,
             1, 3, 3, 1, 2, 2, 0, 1, 1, 512, 8192, 3 * 2048, 1);

    // ---- lateral 1x1x1 -> d_out fp32 ----
    run_conv(pkF, latw, latb, nullptr, lat, 512, 4, 32, 64, 4, 32, 64,
             1, 1, 1, 1, 1, 1, 0, 0, 0, 512, 8192, 0, 0);

    // ---- attention weight prepack ----
    const size_t QKV_PK = 8 * 12 * 32768;
    const size_t PRJ_PK = 8 * 4 * 32768;
    for (int i = 0; i < 3; i++) {
        wpackT_kernel<<<dim3(8, 12), 256>>>(qkvw + (size_t)i * 512 * 1536,
                                            wpk2 + i * QKV_PK, 512, 8, 1536);
        wpackT_kernel<<<dim3(8, 4), 256>>>(pjw + (size_t)i * 512 * 512,
                                           wpk2 + 3 * QKV_PK + i * PRJ_PK, 512, 8, 512);
    }

    // ---- 3 neighborhood-attention blocks ----
    for (int i = 0; i < 3; i++) {
        layernorm_kernel<<<8192 / 32, dim3(32, 8)>>>(lat, lng + i * 512, lnb + i * 512,
                                                     ynpk, 8192);
        TokParams pq{ ynpk, wpk2 + i * QKV_PK, qkvw + (size_t)i * 512 * 1536,
                      qkvb + i * 1536, qkvB, 8192, 1536, 512, 8, 0 };
        tok_mma_kernel<4><<<dim3(8192 / 128, 3), 512, CONV_SMEM_BYTES>>>(pq);
        natt_kernel<<<dim3(1024, 8), 256>>>(qkvB, atpk);
        TokParams pp{ atpk, wpk2 + 3 * QKV_PK + i * PRJ_PK,
                      pjw + (size_t)i * 512 * 512,
                      pjb + i * 512, lat, 8192, 512, 512, 8, 1 };
        tok_mma_kernel<1><<<dim3(8192 / 128, 4), 512, CONV_SMEM_BYTES>>>(pp);
    }
}

// round 11
// speedup vs baseline: 1.3809x; 1.2038x over previous
#include <cuda_runtime.h>
#include <cuda_bf16.h>
#include <math.h>
#include <cstdint>

#if defined(__CUDA_ARCH_SPECIFIC__) || defined(__CUDA_ARCH_FEAT_SM103_ALL)
#define HAS_TCGEN05 1
#else
#define HAS_TCGEN05 0
#endif

// ---------------------------------------------------------------------------
// Scratch buffers (packed u32 = bf16 hi << 16 | bf16 lo)
// ---------------------------------------------------------------------------
__device__ uint32_t g_pk_a[15728640];
__device__ uint32_t g_pk_b[50331648];
__device__ uint32_t g_pk_f[4194304];
__device__ uint32_t g_pk_x2d[1048576];
__device__ uint8_t  g_wpk[14155776];
__device__ uint8_t  g_wpk2[12582912];
__device__ uint32_t g_ynpk[8192 * 512];
__device__ float    g_qkv[8192 * 1536];
__device__ uint32_t g_atpk[8192 * 512];
__device__ int2     g_dec[8192];
__device__ int      g_ndelta[256];
__device__ int      g_npack[256];

// ---------------------------------------------------------------------------
// Common helpers
// ---------------------------------------------------------------------------
__device__ __forceinline__ uint32_t smem_u32(const void* p) {
    uint32_t a;
    asm("{ .reg .u64 t; cvta.to.shared.u64 t, %1; cvt.u32.u64 %0, t; }"
        : "=r"(a) : "l"(p));
    return a;
}
__device__ __forceinline__ float gelu_tanh(float x) {
    float x3 = x * x * x;
    float t = tanhf(0.7978845608028654f * (x + 0.044715f * x3));
    return 0.5f * x * (1.0f + t);
}
__device__ __forceinline__ uint32_t pack_hl(float f) {
    __nv_bfloat16 h = __float2bfloat16(f);
    __nv_bfloat16 l = __float2bfloat16(f - __bfloat162float(h));
    return ((uint32_t)__bfloat16_as_ushort(h) << 16) | __bfloat16_as_ushort(l);
}
__device__ __forceinline__ float unpack_hl(uint32_t v) {
    float h = __bfloat162float(__ushort_as_bfloat16((unsigned short)(v >> 16)));
    float l = __bfloat162float(__ushort_as_bfloat16((unsigned short)(v & 0xFFFF)));
    return h + l;
}

#if HAS_TCGEN05
__device__ __forceinline__ uint32_t elect_one() {
    uint32_t pred;
    asm volatile("{ .reg .pred p; elect.sync _|p, 0xFFFFFFFF; selp.b32 %0, 1, 0, p; }"
                 : "=r"(pred));
    return pred;
}
#define TCGEN05_ALLOC(a, n) \
    asm volatile("tcgen05.alloc.cta_group::1.sync.aligned.shared::cta.b32 [%0], %1;" \
                 :: "r"((uint32_t)(a)), "r"((uint32_t)(n)) : "memory")
#define TCGEN05_DEALLOC(t, n) \
    asm volatile("tcgen05.dealloc.cta_group::1.sync.aligned.b32 %0, %1;" :: "r"(t), "r"(n))
#define TCGEN05_RELINQ() \
    asm volatile("tcgen05.relinquish_alloc_permit.cta_group::1.sync.aligned;")
#define TCGEN05_COMMIT(m) \
    asm volatile("tcgen05.commit.cta_group::1.mbarrier::arrive::one.shared::cluster.b64 [%0];" \
                 :: "r"((uint32_t)(m)) : "memory")
#define TCGEN05_FENCE_AFTER() \
    asm volatile("tcgen05.fence::after_thread_sync;" ::: "memory")
#define TCGEN05_FENCE_BEFORE() \
    asm volatile("tcgen05.fence::before_thread_sync;" ::: "memory")
#define TCGEN05_WAIT_LD() asm volatile("tcgen05.wait::ld.sync.aligned;" ::: "memory")
#define FENCE_PROXY_ASYNC() asm volatile("fence.proxy.async.shared::cta;" ::: "memory")
#define MBARRIER_INIT(m, c) \
    asm volatile("mbarrier.init.shared.b64 [%0], %1;" :: "r"((uint32_t)(m)), "r"((uint32_t)(c)) : "memory")
#define MBARRIER_INVAL(m) \
    asm volatile("mbarrier.inval.shared.b64 [%0];" :: "r"((uint32_t)(m)) : "memory")
#define MBARRIER_WAIT_PARITY(m, ph) do {                                           \
    uint32_t _m = (uint32_t)(m), _p = (uint32_t)(ph), _d;                          \
    asm volatile("{ .reg .pred p; mbarrier.try_wait.parity.acquire.cta.shared::cta.b64 p, [%1], %2;" \
                 " selp.b32 %0, 1, 0, p; }" : "=r"(_d) : "r"(_m), "r"(_p) : "memory"); \
    if (!_d) {                                                                     \
        asm volatile("{ .reg .pred P1; WL_%=: mbarrier.try_wait.parity.acquire.cta.shared::cta.b64 P1, [%0], %1, 0x989680;" \
                     " @P1 bra.uni WD_%=; bra.uni WL_%=; WD_%=: }"                 \
                     :: "r"(_m), "r"(_p) : "memory");                              \
    }                                                                              \
} while (0)
#define TCGEN05_LD_X32(r, a)                                                       \
    asm volatile("tcgen05.ld.sync.aligned.32x32b.x32.b32 "                         \
        "{%0, %1, %2, %3, %4, %5, %6, %7, %8, %9, %10, %11, %12, %13, %14, %15, "  \
        " %16, %17, %18, %19, %20, %21, %22, %23, %24, %25, %26, %27, %28, %29, %30, %31}, [%32];" \
        : "=r"((r)[0]), "=r"((r)[1]), "=r"((r)[2]), "=r"((r)[3]),                  \
          "=r"((r)[4]), "=r"((r)[5]), "=r"((r)[6]), "=r"((r)[7]),                  \
          "=r"((r)[8]), "=r"((r)[9]), "=r"((r)[10]), "=r"((r)[11]),                \
          "=r"((r)[12]), "=r"((r)[13]), "=r"((r)[14]), "=r"((r)[15]),              \
          "=r"((r)[16]), "=r"((r)[17]), "=r"((r)[18]), "=r"((r)[19]),              \
          "=r"((r)[20]), "=r"((r)[21]), "=r"((r)[22]), "=r"((r)[23]),              \
          "=r"((r)[24]), "=r"((r)[25]), "=r"((r)[26]), "=r"((r)[27]),              \
          "=r"((r)[28]), "=r"((r)[29]), "=r"((r)[30]), "=r"((r)[31])               \
        : "r"(a))

static constexpr uint64_t SMEM_DESC_BASE_SW128 =
    (uint64_t(2) << 61) | (uint64_t(1) << 46) | (uint64_t(64) << 32) | (uint64_t(1) << 16);
__device__ __forceinline__ uint64_t make_desc(uint32_t addr) {
    return SMEM_DESC_BASE_SW128 | ((uint64_t)(addr >> 4) & 0x3FFF);
}
__device__ __forceinline__ void mma_f16_ss(uint32_t d, uint64_t ad, uint64_t bd,
                                           uint32_t idesc, uint32_t en) {
    asm volatile(
        "{ .reg .pred p; setp.ne.u32 p, %5, 0;\n\t"
        "tcgen05.mma.cta_group::1.kind::f16 [%0], %1, %2, %3, {%4, %4, %4, %4}, p; }"
        :: "r"(d), "l"(ad), "l"(bd), "r"(idesc), "r"(0u), "r"(en) : "memory");
}
static constexpr uint32_t CONV_IDESC =
    (1u << 4) | (1u << 7) | (1u << 10) | ((128u / 8) << 17) | ((128u / 16) << 24);
#endif // HAS_TCGEN05

// smem layout (after 1024-align): A @0 (32KB, single-buffered),
// B0 @32K (hi/lo), B1 @64K (hi/lo), mbar ring @96K, tmem slot.
#define SME_A 0
#define SME_B0 32768
#define SME_B1 65536
#define SME_MBAR 98304
#define SME_TSLOT 98336
#define CONV_SMEM_BYTES (1024 + 98304 + 128)

// ---------------------------------------------------------------------------
// Init / pack kernels
// ---------------------------------------------------------------------------
__global__ void conv_decode_kernel(int K, int Kpad, int KV, int KHW, int KW,
                                   int D, int H, int W) {
    int k = blockIdx.x * 256 + threadIdx.x;
    if (k >= Kpad) return;
    if (k < K) {
        int ci = k / KV; int tap = k - ci * KV;
        int kd = tap / KHW; int t2 = tap - kd * KHW;
        int kh = t2 / KW; int kw = t2 - kh * KW;
        g_dec[k] = make_int2(((ci * D + kd) * H + kh) * W + kw,
                             (kd << 20) | (kh << 10) | kw);
    } else {
        g_dec[k] = make_int2(0, 1023 << 20);
    }
}

__global__ void natt_table_kernel() {
    int nb = threadIdx.x;
    if (nb < 245) {
        int od = nb / 49; int r = nb - od * 49;
        int oh = r / 7;   int ow = r - oh * 7;
        g_ndelta[nb] = (od - 2) * 2048 + (oh - 3) * 64 + (ow - 3);
        g_npack[nb]  = (od << 16) | (oh << 8) | ow;
    }
}

__global__ void xpack_kernel(const float* __restrict__ x,
                             uint32_t* __restrict__ dst, int n4) {
    int i = blockIdx.x * 256 + threadIdx.x;
    if (i >= n4) return;
    float4 v = reinterpret_cast<const float4*>(x)[i];
    uint4 o;
    o.x = pack_hl(v.x); o.y = pack_hl(v.y);
    o.z = pack_hl(v.z); o.w = pack_hl(v.w);
    reinterpret_cast<uint4*>(dst)[i] = o;
}

__global__ void wpack_kernel(const float* __restrict__ w, int K, int NC) {
    int kc = blockIdx.x, bm = blockIdx.y;
    int tid = threadIdx.x;
    int r = tid >> 1, half = tid & 1;
    const float* wrow = w + (size_t)(bm * 128 + r) * K;
    uint8_t* hi = g_wpk + (size_t)(bm * NC + kc) * 32768;
    uint8_t* lo = hi + 16384;
#pragma unroll
    for (int i = 0; i < 16; i++) {
        int kk = half * 32 + 2 * i;
        int k = kc * 64 + kk;
        float a0 = (k < K) ? wrow[k] : 0.f;
        float a1 = (k + 1 < K) ? wrow[k + 1] : 0.f;
        uint32_t p0 = pack_hl(a0), p1 = pack_hl(a1);
        uint32_t hp = __byte_perm(p0, p1, 0x7632);
        uint32_t lp = __byte_perm(p0, p1, 0x5410);
        uint32_t off = r * 128 + kk * 2;
        uint32_t sw = off ^ ((off >> 3) & 0x70);
        *reinterpret_cast<uint32_t*>(hi + sw) = hp;
        *reinterpret_cast<uint32_t*>(lo + sw) = lp;
    }
}

__global__ void wpackT_kernel(const float* __restrict__ w, uint8_t* dst,
                              int K, int NC, int J) {
    int kc = blockIdx.x, bm = blockIdx.y;
    int tid = threadIdx.x;
    int r = tid >> 1, half = tid & 1;
    int m = bm * 128 + r;
    uint8_t* hi = dst + (size_t)(bm * NC + kc) * 32768;
    uint8_t* lo = hi + 16384;
#pragma unroll
    for (int i = 0; i < 16; i++) {
        int kk = half * 32 + 2 * i;
        int k = kc * 64 + kk;
        float a0 = (k < K) ? w[(size_t)k * J + m] : 0.f;
        float a1 = (k + 1 < K) ? w[(size_t)(k + 1) * J + m] : 0.f;
        uint32_t p0 = pack_hl(a0), p1 = pack_hl(a1);
        uint32_t hp = __byte_perm(p0, p1, 0x7632);
        uint32_t lp = __byte_perm(p0, p1, 0x5410);
        uint32_t off = r * 128 + kk * 2;
        uint32_t sw = off ^ ((off >> 3) & 0x70);
        *reinterpret_cast<uint32_t*>(hi + sw) = hp;
        *reinterpret_cast<uint32_t*>(lo + sw) = lp;
    }
}

// ---------------------------------------------------------------------------
// Conv kernel: single-buffered A, double-buffered B, TMEM 256 cols, 2 CTA/SM.
// Commit ring of 4; wait all commits <= ni-1 before overwriting A.
// ---------------------------------------------------------------------------
struct ConvParams {
    const uint32_t* xpk;
    const float* wf;
    const float* bias;
    uint32_t* outpk;
    float* outf;
    int D, H, W;
    int Hout, Wout;
    int sd, sh, sw, pd, ph, pw;
    int K, NC;
    int outStrideC, outOffset;
    int gelu;
};

template <int BM>
__global__ __launch_bounds__(512, 2) void conv_mma_kernel(ConvParams p) {
    extern __shared__ char smem_raw[];
    char* smem_al = (char*)(((uintptr_t)smem_raw + 1023) & ~(uintptr_t)1023);

    const int tid = threadIdx.x;
    const int bn = blockIdx.x;
    const int mblk0 = blockIdx.y * BM;
    const int HWo = p.Hout * p.Wout;

#if HAS_TCGEN05
    const uint32_t sb = smem_u32(smem_al);
    const uint32_t mbar = sb + SME_MBAR;
    const uint32_t tmem_slot = sb + SME_TSLOT;
    const int wid = tid >> 5;
    const int lane = tid & 31;

    if (wid == 0) {
        TCGEN05_ALLOC(tmem_slot, 256);
        TCGEN05_RELINQ();
    }
    if (tid == 0) {
#pragma unroll
        for (int i = 0; i < 4; i++) MBARRIER_INIT(mbar + 8 * i, 1);
    }
    __syncthreads();
    uint32_t tmem;
    asm volatile("ld.shared.b32 %0, [%1];" : "=r"(tmem) : "r"(tmem_slot));

    const int r = tid >> 2;
    const int q = tid & 3;
    const int n = bn * 128 + r;
    const int od = n / HWo; int rr2 = n - od * HWo;
    const int oh = rr2 / p.Wout; const int ow = rr2 - oh * p.Wout;
    const int id0 = od * p.sd - p.pd;
    const int ih0 = oh * p.sh - p.ph;
    const int iw0 = ow * p.sw - p.pw;
    const int gbase = (id0 * p.H + ih0) * p.W + iw0;
    const int NC = p.NC;

    auto fillA = [&](int kc, int bm) {
        const uint8_t* src = g_wpk + ((size_t)(mblk0 + bm) * NC + kc) * 32768 + tid * 16;
        char* dst = smem_al + SME_A + tid * 16;
#pragma unroll
        for (int i = 0; i < 4; i++) {
            uint4 v = *reinterpret_cast<const uint4*>(src + i * 8192);
            *reinterpret_cast<uint4*>(dst + i * 8192) = v;
        }
    };
    auto fillB = [&](int st, int kc) {
        char* Bhi = smem_al + (st ? SME_B1 : SME_B0);
        char* Blo = Bhi + 16384;
        const int kt = kc * 64;
#pragma unroll
        for (int i = 0; i < 8; i++) {
            int kk = q * 16 + 2 * i;
            int k = kt + kk;
            int4 dv = *reinterpret_cast<const int4*>(&g_dec[k]);
            uint32_t v0 = 0, v1 = 0;
            {
                int kd = dv.y >> 20, kh = (dv.y >> 10) & 1023, kw = dv.y & 1023;
                if ((unsigned)(id0 + kd) < (unsigned)p.D &&
                    (unsigned)(ih0 + kh) < (unsigned)p.H &&
                    (unsigned)(iw0 + kw) < (unsigned)p.W)
                    v0 = p.xpk[gbase + dv.x];
            }
            {
                int kd = dv.w >> 20, kh = (dv.w >> 10) & 1023, kw = dv.w & 1023;
                if ((unsigned)(id0 + kd) < (unsigned)p.D &&
                    (unsigned)(ih0 + kh) < (unsigned)p.H &&
                    (unsigned)(iw0 + kw) < (unsigned)p.W)
                    v1 = p.xpk[gbase + dv.z];
            }
            uint32_t off = r * 128 + kk * 2;
            uint32_t sw = off ^ ((off >> 3) & 0x70);
            *reinterpret_cast<uint32_t*>(Bhi + sw) = __byte_perm(v0, v1, 0x7632);
            *reinterpret_cast<uint32_t*>(Blo + sw) = __byte_perm(v0, v1, 0x5410);
        }
    };

    int wpar = 0;
    auto waitCommits = [&](int target) {
        while (wpar < target) {
            MBARRIER_WAIT_PARITY(mbar + 8 * (wpar & 3), (wpar >> 2) & 1);
            wpar++;
        }
    };

    fillB(0, 0);

    for (int kc = 0; kc < NC; kc++) {
        int st = kc & 1;
#pragma unroll
        for (int bm = 0; bm < BM; bm++) {
            int ni = kc * BM + bm;
            if (ni >= 1) waitCommits(ni);   // prev MMA batch done -> A free
            fillA(kc, bm);
            FENCE_PROXY_ASYNC();
            __syncthreads();
            if (wid == 0 && elect_one()) {
                uint64_t dAh = make_desc(sb + SME_A);
                uint64_t dAl = dAh + (16384 >> 4);
                uint64_t dBh = make_desc(sb + (st ? SME_B1 : SME_B0));
                uint64_t dBl = dBh + (16384 >> 4);
                uint32_t d = tmem + bm * 128;
                uint32_t first = (kc == 0) ? 0u : 1u;
#pragma unroll
                for (int s = 0; s < 4; s++) {
                    uint64_t o = s * 2;
                    mma_f16_ss(d, dAh + o, dBh + o, CONV_IDESC, first); first = 1;
                    mma_f16_ss(d, dAh + o, dBl + o, CONV_IDESC, 1);
                    mma_f16_ss(d, dAl + o, dBh + o, CONV_IDESC, 1);
                }
                TCGEN05_COMMIT(mbar + 8 * (ni & 3));
            }
        }
        if (kc + 1 < NC) fillB(st ^ 1, kc + 1);  // overlaps last MMA batch
    }
    waitCommits(NC * BM);
    TCGEN05_FENCE_AFTER();

    {
        const int sp = wid & 3;
        const int cb = wid >> 2;
#pragma unroll
        for (int bm = 0; bm < BM; bm++) {
            const int m = (mblk0 + bm) * 128 + sp * 32 + lane;
            const float bv = p.bias[m];
            uint32_t dr[32];
            TCGEN05_LD_X32(dr, tmem + bm * 128 + cb * 32);
            TCGEN05_WAIT_LD();
            size_t obase = (size_t)m * p.outStrideC + p.outOffset + bn * 128 + cb * 32;
            if (p.outpk) {
                uint32_t* orow = p.outpk + obase;
#pragma unroll
                for (int j = 0; j < 32; j++) {
                    float v = __uint_as_float(dr[j]) + bv;
                    if (p.gelu) v = gelu_tanh(v);
                    orow[j] = pack_hl(v);
                }
            } else {
                float* orow = p.outf + obase;
#pragma unroll
                for (int j = 0; j < 32; j++) {
                    float v = __uint_as_float(dr[j]) + bv;
                    if (p.gelu) v = gelu_tanh(v);
                    orow[j] = v;
                }
            }
        }
        TCGEN05_FENCE_BEFORE();
    }
    __syncthreads();
    if (tid == 0) {
#pragma unroll
        for (int i = 0; i < 4; i++) MBARRIER_INVAL(mbar + 8 * i);
    }
    if (wid == 0) TCGEN05_DEALLOC(tmem, 256);

#else  // FFMA fallback (never executes on GB300)
    for (int bm = 0; bm < BM; bm++) {
        const int m_base = (mblk0 + bm) * 128;
        for (int idx = tid; idx < 128 * 128; idx += 512) {
            int ml = idx >> 7, nl = idx & 127;
            int m = m_base + ml;
            int nn = bn * 128 + nl;
            int od = nn / HWo; int rr2 = nn - od * HWo;
            int oh = rr2 / p.Wout; int ow = rr2 - oh * p.Wout;
            int id0 = od * p.sd - p.pd, ih0 = oh * p.sh - p.ph, iw0 = ow * p.sw - p.pw;
            int gb = (id0 * p.H + ih0) * p.W + iw0;
            float s = 0.f;
            for (int k = 0; k < p.K; k++) {
                int2 dv = g_dec[k];
                int kd = dv.y >> 20, kh = (dv.y >> 10) & 1023, kw = dv.y & 1023;
                if ((unsigned)(id0 + kd) < (unsigned)p.D &&
                    (unsigned)(ih0 + kh) < (unsigned)p.H &&
                    (unsigned)(iw0 + kw) < (unsigned)p.W)
                    s += p.wf[(size_t)m * p.K + k] * unpack_hl(p.xpk[gb + dv.x]);
            }
            s += p.bias[m];
            if (p.gelu) s = gelu_tanh(s);
            size_t ob = (size_t)m * p.outStrideC + p.outOffset + nn;
            if (p.outpk) p.outpk[ob] = pack_hl(s);
            else p.outf[ob] = s;
        }
    }
#endif
}

// ---------------------------------------------------------------------------
// Token GEMM: same structure (A single, B double, TMEM 256)
// ---------------------------------------------------------------------------
struct TokParams {
    const uint32_t* bpk;
    const uint8_t* wpk;
    const float* wf;
    const float* bias;
    float* out;
    int T, J, Kdim, NC, mode;
};

template <int BM>
__global__ __launch_bounds__(512, 2) void tok_mma_kernel(TokParams p) {
    extern __shared__ char smem_raw[];
    char* smem_al = (char*)(((uintptr_t)smem_raw + 1023) & ~(uintptr_t)1023);

    const int tid = threadIdx.x;
    const int bn = blockIdx.x;
    const int mblk0 = blockIdx.y * BM;

#if HAS_TCGEN05
    const uint32_t sb = smem_u32(smem_al);
    const uint32_t mbar = sb + SME_MBAR;
    const uint32_t tmem_slot = sb + SME_TSLOT;
    const int wid = tid >> 5;
    const int lane = tid & 31;

    if (wid == 0) {
        TCGEN05_ALLOC(tmem_slot, 256);
        TCGEN05_RELINQ();
    }
    if (tid == 0) {
#pragma unroll
        for (int i = 0; i < 4; i++) MBARRIER_INIT(mbar + 8 * i, 1);
    }
    __syncthreads();
    uint32_t tmem;
    asm volatile("ld.shared.b32 %0, [%1];" : "=r"(tmem) : "r"(tmem_slot));

    const int r = tid >> 2;
    const int q = tid & 3;
    const uint32_t* bsrc = p.bpk + (size_t)(bn * 128 + r) * p.Kdim;
    const int NC = p.NC;

    auto fillA = [&](int kc, int bm) {
        const uint8_t* src = p.wpk + ((size_t)(mblk0 + bm) * NC + kc) * 32768 + tid * 16;
        char* dst = smem_al + SME_A + tid * 16;
#pragma unroll
        for (int i = 0; i < 4; i++) {
            uint4 v = *reinterpret_cast<const uint4*>(src + i * 8192);
            *reinterpret_cast<uint4*>(dst + i * 8192) = v;
        }
    };
    auto fillB = [&](int st, int kc) {
        char* Bhi = smem_al + (st ? SME_B1 : SME_B0);
        char* Blo = Bhi + 16384;
        const uint32_t* src = bsrc + kc * 64 + q * 16;
        uint32_t buf[16];
#pragma unroll
        for (int i = 0; i < 4; i++)
            *reinterpret_cast<uint4*>(&buf[i * 4]) =
                *reinterpret_cast<const uint4*>(src + i * 4);
#pragma unroll
        for (int i = 0; i < 8; i++) {
            int kk = q * 16 + 2 * i;
            uint32_t v0 = buf[2 * i], v1 = buf[2 * i + 1];
            uint32_t off = r * 128 + kk * 2;
            uint32_t sw = off ^ ((off >> 3) & 0x70);
            *reinterpret_cast<uint32_t*>(Bhi + sw) = __byte_perm(v0, v1, 0x7632);
            *reinterpret_cast<uint32_t*>(Blo + sw) = __byte_perm(v0, v1, 0x5410);
        }
    };

    int wpar = 0;
    auto waitCommits = [&](int target) {
        while (wpar < target) {
            MBARRIER_WAIT_PARITY(mbar + 8 * (wpar & 3), (wpar >> 2) & 1);
            wpar++;
        }
    };

    fillB(0, 0);

    for (int kc = 0; kc < NC; kc++) {
        int st = kc & 1;
#pragma unroll
        for (int bm = 0; bm < BM; bm++) {
            int ni = kc * BM + bm;
            if (ni >= 1) waitCommits(ni);
            fillA(kc, bm);
            FENCE_PROXY_ASYNC();
            __syncthreads();
            if (wid == 0 && elect_one()) {
                uint64_t dAh = make_desc(sb + SME_A);
                uint64_t dAl = dAh + (16384 >> 4);
                uint64_t dBh = make_desc(sb + (st ? SME_B1 : SME_B0));
                uint64_t dBl = dBh + (16384 >> 4);
                uint32_t d = tmem + bm * 128;
                uint32_t first = (kc == 0) ? 0u : 1u;
#pragma unroll
                for (int s = 0; s < 4; s++) {
                    uint64_t o = s * 2;
                    mma_f16_ss(d, dAh + o, dBh + o, CONV_IDESC, first); first = 1;
                    mma_f16_ss(d, dAh + o, dBl + o, CONV_IDESC, 1);
                    mma_f16_ss(d, dAl + o, dBh + o, CONV_IDESC, 1);
                }
                TCGEN05_COMMIT(mbar + 8 * (ni & 3));
            }
        }
        if (kc + 1 < NC) fillB(st ^ 1, kc + 1);
    }
    waitCommits(NC * BM);
    TCGEN05_FENCE_AFTER();

    {
        const int sp = wid & 3;
        const int cb = wid >> 2;
        const int t0 = bn * 128 + cb * 32;
#pragma unroll
        for (int bm = 0; bm < BM; bm++) {
            const int m = (mblk0 + bm) * 128 + sp * 32 + lane;
            const float bv = p.bias[m];
            uint32_t dr[32];
            TCGEN05_LD_X32(dr, tmem + bm * 128 + cb * 32);
            TCGEN05_WAIT_LD();
            if (p.mode == 0) {
#pragma unroll
                for (int j = 0; j < 32; j++)
                    p.out[(size_t)(t0 + j) * p.J + m] = __uint_as_float(dr[j]) + bv;
            } else {
                float* orow = p.out + (size_t)m * p.T + t0;
#pragma unroll
                for (int j = 0; j < 8; j++) {
                    float4* cp = reinterpret_cast<float4*>(orow + j * 4);
                    float4 o = *cp;
                    o.x += __uint_as_float(dr[j * 4 + 0]) + bv;
                    o.y += __uint_as_float(dr[j * 4 + 1]) + bv;
                    o.z += __uint_as_float(dr[j * 4 + 2]) + bv;
                    o.w += __uint_as_float(dr[j * 4 + 3]) + bv;
                    *cp = o;
                }
            }
        }
        TCGEN05_FENCE_BEFORE();
    }
    __syncthreads();
    if (tid == 0) {
#pragma unroll
        for (int i = 0; i < 4; i++) MBARRIER_INVAL(mbar + 8 * i);
    }
    if (wid == 0) TCGEN05_DEALLOC(tmem, 256);

#else  // FFMA fallback
    for (int bm = 0; bm < BM; bm++) {
        int m_base = (mblk0 + bm) * 128;
        for (int idx = tid; idx < 128 * 128; idx += 512) {
            int tl = idx >> 7, jl = idx & 127;
            int t = bn * 128 + tl, j = m_base + jl;
            float s = 0.f;
            for (int k = 0; k < p.Kdim; k++)
                s += unpack_hl(p.bpk[(size_t)t * p.Kdim + k]) * p.wf[(size_t)k * p.J + j];
            s += p.bias[j];
            if (p.mode == 0) p.out[(size_t)t * p.J + j] = s;
            else p.out[(size_t)j * p.T + t] += s;
        }
    }
#endif
}

// ---------------------------------------------------------------------------
// LayerNorm: fp32 channel-major -> packed token-major
// ---------------------------------------------------------------------------
__global__ __launch_bounds__(256) void layernorm_kernel(
    const float* __restrict__ x, const float* __restrict__ g,
    const float* __restrict__ b, uint32_t* __restrict__ ypk, int T) {
    const int tx = threadIdx.x;
    const int ty = threadIdx.y;
    const int t = blockIdx.x * 32 + tx;

    float s = 0.f, ss = 0.f;
#pragma unroll
    for (int i = 0; i < 64; i++) {
        int c = ty * 64 + i;
        float v = x[(size_t)c * T + t];
        s += v; ss += v * v;
    }
    __shared__ float shs[8][32], shss[8][32];
    __shared__ float smu[32], srs[32];
    shs[ty][tx] = s; shss[ty][tx] = ss;
    __syncthreads();
    if (ty == 0) {
        float S = 0.f, SS = 0.f;
#pragma unroll
        for (int j = 0; j < 8; j++) { S += shs[j][tx]; SS += shss[j][tx]; }
        float mu = S * (1.f / 512.f);
        float var = SS * (1.f / 512.f) - mu * mu;
        smu[tx] = mu;
        srs[tx] = rsqrtf(var + 1e-5f);
    }
    __syncthreads();
    float mu = smu[tx], rs = srs[tx];
    uint32_t* yrow = ypk + (size_t)t * 512 + ty * 64;
#pragma unroll
    for (int i = 0; i < 64; i++) {
        int c = ty * 64 + i;
        float v = x[(size_t)c * T + t];
        yrow[i] = pack_hl((v - mu) * rs * g[c] + b[c]);
    }
}

// ---------------------------------------------------------------------------
// Neighborhood attention — coalesced score phase (R10, unchanged)
// ---------------------------------------------------------------------------
__global__ __launch_bounds__(256) void natt_kernel(
    const float* __restrict__ qkv, uint32_t* __restrict__ atpk) {
    __shared__ float psh[8][248];
    __shared__ float tsh[8][32][33];

    const int warp = threadIdx.x >> 5;
    const int lane = threadIdx.x & 31;
    const int t = blockIdx.x * 8 + warp;
    const int head = blockIdx.y;
    const int d = t >> 11;
    const int hh = (t >> 6) & 31;
    const int ww = t & 63;

    float2 q2 = *reinterpret_cast<const float2*>(
        qkv + (size_t)t * 1536 + head * 64 + 2 * lane);
    q2.x *= 0.125f; q2.y *= 0.125f;

    float sc[8];
    float m = -1e30f;
#pragma unroll
    for (int it = 0; it < 8; it++) {
#pragma unroll
        for (int j = 0; j < 32; j++) {
            int nb = it * 32 + j;
            float pv = 0.f;
            if (nb < 245) {
                int pk = g_npack[nb];
                int nd = d + (pk >> 16) - 2;
                int nh = hh + ((pk >> 8) & 255) - 3;
                int nw = ww + (pk & 255) - 3;
                if ((unsigned)nd < 4u && (unsigned)nh < 32u && (unsigned)nw < 64u) {
                    int nt = (nd * 32 + nh) * 64 + nw;
                    float2 kv = *reinterpret_cast<const float2*>(
                        qkv + (size_t)nt * 1536 + 512 + head * 64 + 2 * lane);
                    pv = fmaf(q2.x, kv.x, q2.y * kv.y);
                }
            }
            tsh[warp][j][lane] = pv;
        }
        __syncwarp();
        float s = 0.f;
#pragma unroll
        for (int j = 0; j < 32; j++) s += tsh[warp][lane][j];
        __syncwarp();

        int nb = it * 32 + lane;
        float dot = -1e30f;
        if (nb < 245) {
            int pk = g_npack[nb];
            int nd = d + (pk >> 16) - 2;
            int nh = hh + ((pk >> 8) & 255) - 3;
            int nw = ww + (pk & 255) - 3;
            if ((unsigned)nd < 4u && (unsigned)nh < 32u && (unsigned)nw < 64u)
                dot = s;
        }
        sc[it] = dot;
        m = fmaxf(m, dot);
    }
#pragma unroll
    for (int o = 16; o; o >>= 1) m = fmaxf(m, __shfl_xor_sync(0xffffffffu, m, o));

    float l = 0.f;
#pragma unroll
    for (int it = 0; it < 8; it++) {
        int nb = it * 32 + lane;
        float e = (sc[it] > -1e29f) ? __expf(sc[it] - m) : 0.f;
        if (nb < 248) psh[warp][nb] = e;
        l += e;
    }
#pragma unroll
    for (int o = 16; o; o >>= 1) l += __shfl_xor_sync(0xffffffffu, l, o);
    __syncwarp();

    float acc0 = 0.f, acc1 = 0.f;
    for (int nb = 0; nb < 245; nb++) {
        float pb = psh[warp][nb];
        if (pb > 0.f) {
            int nt = t + g_ndelta[nb];
            const float* vp = qkv + (size_t)nt * 1536 + 1024 + head * 64;
            acc0 = fmaf(pb, vp[lane], acc0);
            acc1 = fmaf(pb, vp[lane + 32], acc1);
        }
    }
    float inv = 1.f / l;
    uint32_t* op = atpk + (size_t)t * 512 + head * 64;
    op[lane] = pack_hl(acc0 * inv);
    op[lane + 32] = pack_hl(acc1 * inv);
}

// ---------------------------------------------------------------------------
// Host launcher
// ---------------------------------------------------------------------------
extern "C" void kernel_launch(void* const* d_in, const int* in_sizes, int n_in,
                              void* d_out, int out_size) {
    const float* x2d  = (const float*)d_in[0];
    const float* x3d  = (const float*)d_in[1];
    const float* sw0  = (const float*)d_in[2];  const float* sb0 = (const float*)d_in[3];
    const float* sw1  = (const float*)d_in[4];  const float* sb1 = (const float*)d_in[5];
    const float* sw2  = (const float*)d_in[6];  const float* sb2 = (const float*)d_in[7];
    const float* pw0  = (const float*)d_in[8];  const float* pb0 = (const float*)d_in[9];
    const float* pw1  = (const float*)d_in[10]; const float* pb1 = (const float*)d_in[11];
    const float* pw2  = (const float*)d_in[12]; const float* pb2 = (const float*)d_in[13];
    const float* latw = (const float*)d_in[14]; const float* latb = (const float*)d_in[15];
    const float* lng  = (const float*)d_in[16]; const float* lnb  = (const float*)d_in[17];
    const float* qkvw = (const float*)d_in[18]; const float* qkvb = (const float*)d_in[19];
    const float* pjw  = (const float*)d_in[20]; const float* pjb  = (const float*)d_in[21];
    float* lat = (float*)d_out;

    uint32_t *pkA, *pkB, *pkF, *pkX, *ynpk, *atpk;
    float *qkvB;
    uint8_t *wpk2;
    cudaGetSymbolAddress((void**)&pkA, g_pk_a);
    cudaGetSymbolAddress((void**)&pkB, g_pk_b);
    cudaGetSymbolAddress((void**)&pkF, g_pk_f);
    cudaGetSymbolAddress((void**)&pkX, g_pk_x2d);
    cudaGetSymbolAddress((void**)&ynpk, g_ynpk);
    cudaGetSymbolAddress((void**)&qkvB, g_qkv);
    cudaGetSymbolAddress((void**)&atpk, g_atpk);
    cudaGetSymbolAddress((void**)&wpk2, g_wpk2);

    cudaFuncSetAttribute(conv_mma_kernel<1>,
                         cudaFuncAttributeMaxDynamicSharedMemorySize, CONV_SMEM_BYTES);
    cudaFuncSetAttribute(conv_mma_kernel<2>,
                         cudaFuncAttributeMaxDynamicSharedMemorySize, CONV_SMEM_BYTES);
    cudaFuncSetAttribute(tok_mma_kernel<1>,
                         cudaFuncAttributeMaxDynamicSharedMemorySize, CONV_SMEM_BYTES);
    cudaFuncSetAttribute(tok_mma_kernel<2>,
                         cudaFuncAttributeMaxDynamicSharedMemorySize, CONV_SMEM_BYTES);

    auto run_conv = [&](const uint32_t* xpk, const float* wf, const float* bias,
                        uint32_t* outpk, float* outf,
                        int Cin, int D, int H, int W, int Dout, int Hout, int Wout,
                        int KD, int KH, int KW, int sd, int sh, int sw,
                        int pd, int ph, int pw, int Cout,
                        int outStrideC, int outOffset, int gelu) {
        int K = Cin * KD * KH * KW;
        int NC = (K + 63) / 64;
        int Kp = NC * 64;
        conv_decode_kernel<<<(Kp + 255) / 256, 256>>>(K, Kp, KD * KH * KW, KH * KW,
                                                      KW, D, H, W);
        wpack_kernel<<<dim3(NC, Cout / 128), 256>>>(wf, K, NC);
        int Nvox = Dout * Hout * Wout;
        ConvParams p{ xpk, wf, bias, outpk, outf,
                      D, H, W, Hout, Wout, sd, sh, sw, pd, ph, pw,
                      K, NC, outStrideC, outOffset, gelu };
        int nblk = Cout / 128;
        int bn = Nvox / 128;
        if (nblk % 2 == 0 && bn * (nblk / 2) >= 256)
            conv_mma_kernel<2><<<dim3(bn, nblk / 2), 512, CONV_SMEM_BYTES>>>(p);
        else
            conv_mma_kernel<1><<<dim3(bn, nblk), 512, CONV_SMEM_BYTES>>>(p);
    };

    natt_table_kernel<<<1, 256>>>();
    xpack_kernel<<<(5 * 24 * 256 * 512 / 4 + 255) / 256, 256>>>(
        x3d, pkA, 5 * 24 * 256 * 512 / 4);
    xpack_kernel<<<(8 * 256 * 512 / 4 + 255) / 256, 256>>>(
        x2d, pkX, 8 * 256 * 512 / 4);

    // ---- 3D tower ----
    run_conv(pkA, pw0, pb0, pkB, nullptr, 5, 24, 256, 512, 12, 128, 256,
             3, 3, 3, 2, 2, 2, 1, 1, 1, 128, 393216, 0, 1);
    run_conv(pkB, pw1, pb1, pkA, nullptr, 128, 12, 128, 256, 6, 64, 128,
             3, 3, 3, 2, 2, 2, 1, 1, 1, 256, 49152, 0, 1);
    run_conv(pkA, pw2, pb2, pkF, nullptr, 256, 6, 64, 128, 3, 32, 64,
             3, 3, 3, 2, 2, 2, 1, 1, 1, 512, 8192, 0, 1);

    // ---- 2D tower ----
    run_conv(pkX, sw0, sb0, pkB, nullptr, 8, 1, 256, 512, 1, 128, 256,
             1, 3, 3, 1, 2, 2, 0, 1, 1, 128, 32768, 0, 1);
    run_conv(pkB, sw1, sb1, pkA, nullptr, 128, 1, 128, 256, 1, 64, 128,
             1, 3, 3, 1, 2, 2, 0, 1, 1, 256, 8192, 0, 1);
    run_conv(pkA, sw2, sb2, pkF, nullptr, 256, 1, 64, 128, 1, 32, 64,
             1, 3, 3, 1, 2, 2, 0, 1, 1, 512, 8192, 3 * 2048, 1);

    // ---- lateral 1x1x1 -> d_out fp32 ----
    run_conv(pkF, latw, latb, nullptr, lat, 512, 4, 32, 64, 4, 32, 64,
             1, 1, 1, 1, 1, 1, 0, 0, 0, 512, 8192, 0, 0);

    // ---- attention weight prepack ----
    const size_t QKV_PK = 8 * 12 * 32768;
    const size_t PRJ_PK = 8 * 4 * 32768;
    for (int i = 0; i < 3; i++) {
        wpackT_kernel<<<dim3(8, 12), 256>>>(qkvw + (size_t)i * 512 * 1536,
                                            wpk2 + i * QKV_PK, 512, 8, 1536);
        wpackT_kernel<<<dim3(8, 4), 256>>>(pjw + (size_t)i * 512 * 512,
                                           wpk2 + 3 * QKV_PK + i * PRJ_PK, 512, 8, 512);
    }

    // ---- 3 neighborhood-attention blocks ----
    for (int i = 0; i < 3; i++) {
        layernorm_kernel<<<8192 / 32, dim3(32, 8)>>>(lat, lng + i * 512, lnb + i * 512,
                                                     ynpk, 8192);
        TokParams pq{ ynpk, wpk2 + i * QKV_PK, qkvw + (size_t)i * 512 * 1536,
                      qkvb + i * 1536, qkvB, 8192, 1536, 512, 8, 0 };
        tok_mma_kernel<2><<<dim3(8192 / 128, 6), 512, CONV_SMEM_BYTES>>>(pq);
        natt_kernel<<<dim3(1024, 8), 256>>>(qkvB, atpk);
        TokParams pp{ atpk, wpk2 + 3 * QKV_PK + i * PRJ_PK,
                      pjw + (size_t)i * 512 * 512,
                      pjb + i * 512, lat, 8192, 512, 512, 8, 1 };
        tok_mma_kernel<1><<<dim3(8192 / 128, 4), 512, CONV_SMEM_BYTES>>>(pp);
    }
}

// round 12
// speedup vs baseline: 1.5297x; 1.1078x over previous
#include <cuda_runtime.h>
#include <cuda_bf16.h>
#include <math.h>
#include <cstdint>

#if defined(__CUDA_ARCH_SPECIFIC__) || defined(__CUDA_ARCH_FEAT_SM103_ALL)
#define HAS_TCGEN05 1
#else
#define HAS_TCGEN05 0
#endif

// ---------------------------------------------------------------------------
// Scratch buffers (packed u32 = bf16 hi << 16 | bf16 lo)
// ---------------------------------------------------------------------------
__device__ uint32_t g_pk_a[15728640];
__device__ uint32_t g_pk_b[50331648];
__device__ uint32_t g_pk_f[4194304];
__device__ uint32_t g_pk_x2d[1048576];
__device__ uint8_t  g_wpk[14155776];
__device__ uint8_t  g_wpk2[12582912];
__device__ uint32_t g_ynpk[8192 * 512];
__device__ float    g_qkv[8192 * 1536];
__device__ uint32_t g_atpk[8192 * 512];
__device__ int2     g_dec[8192];
__device__ int      g_ndelta[256];
__device__ int      g_npack[256];

// ---------------------------------------------------------------------------
// Common helpers
// ---------------------------------------------------------------------------
__device__ __forceinline__ uint32_t smem_u32(const void* p) {
    uint32_t a;
    asm("{ .reg .u64 t; cvta.to.shared.u64 t, %1; cvt.u32.u64 %0, t; }"
        : "=r"(a) : "l"(p));
    return a;
}
__device__ __forceinline__ float gelu_tanh(float x) {
    float x3 = x * x * x;
    float t = tanhf(0.7978845608028654f * (x + 0.044715f * x3));
    return 0.5f * x * (1.0f + t);
}
__device__ __forceinline__ uint32_t pack_hl(float f) {
    __nv_bfloat16 h = __float2bfloat16(f);
    __nv_bfloat16 l = __float2bfloat16(f - __bfloat162float(h));
    return ((uint32_t)__bfloat16_as_ushort(h) << 16) | __bfloat16_as_ushort(l);
}
__device__ __forceinline__ float unpack_hl(uint32_t v) {
    float h = __bfloat162float(__ushort_as_bfloat16((unsigned short)(v >> 16)));
    float l = __bfloat162float(__ushort_as_bfloat16((unsigned short)(v & 0xFFFF)));
    return h + l;
}

#if HAS_TCGEN05
__device__ __forceinline__ uint32_t elect_one() {
    uint32_t pred;
    asm volatile("{ .reg .pred p; elect.sync _|p, 0xFFFFFFFF; selp.b32 %0, 1, 0, p; }"
                 : "=r"(pred));
    return pred;
}
#define TCGEN05_ALLOC(a, n) \
    asm volatile("tcgen05.alloc.cta_group::1.sync.aligned.shared::cta.b32 [%0], %1;" \
                 :: "r"((uint32_t)(a)), "r"((uint32_t)(n)) : "memory")
#define TCGEN05_DEALLOC(t, n) \
    asm volatile("tcgen05.dealloc.cta_group::1.sync.aligned.b32 %0, %1;" :: "r"(t), "r"(n))
#define TCGEN05_RELINQ() \
    asm volatile("tcgen05.relinquish_alloc_permit.cta_group::1.sync.aligned;")
#define TCGEN05_COMMIT(m) \
    asm volatile("tcgen05.commit.cta_group::1.mbarrier::arrive::one.shared::cluster.b64 [%0];" \
                 :: "r"((uint32_t)(m)) : "memory")
#define TCGEN05_FENCE_AFTER() \
    asm volatile("tcgen05.fence::after_thread_sync;" ::: "memory")
#define TCGEN05_FENCE_BEFORE() \
    asm volatile("tcgen05.fence::before_thread_sync;" ::: "memory")
#define TCGEN05_WAIT_LD() asm volatile("tcgen05.wait::ld.sync.aligned;" ::: "memory")
#define FENCE_PROXY_ASYNC() asm volatile("fence.proxy.async.shared::cta;" ::: "memory")
#define MBARRIER_INIT(m, c) \
    asm volatile("mbarrier.init.shared.b64 [%0], %1;" :: "r"((uint32_t)(m)), "r"((uint32_t)(c)) : "memory")
#define MBARRIER_INVAL(m) \
    asm volatile("mbarrier.inval.shared.b64 [%0];" :: "r"((uint32_t)(m)) : "memory")
#define MBARRIER_WAIT_PARITY(m, ph) do {                                           \
    uint32_t _m = (uint32_t)(m), _p = (uint32_t)(ph), _d;                          \
    asm volatile("{ .reg .pred p; mbarrier.try_wait.parity.acquire.cta.shared::cta.b64 p, [%1], %2;" \
                 " selp.b32 %0, 1, 0, p; }" : "=r"(_d) : "r"(_m), "r"(_p) : "memory"); \
    if (!_d) {                                                                     \
        asm volatile("{ .reg .pred P1; WL_%=: mbarrier.try_wait.parity.acquire.cta.shared::cta.b64 P1, [%0], %1, 0x989680;" \
                     " @P1 bra.uni WD_%=; bra.uni WL_%=; WD_%=: }"                 \
                     :: "r"(_m), "r"(_p) : "memory");                              \
    }                                                                              \
} while (0)
#define TCGEN05_LD_X32(r, a)                                                       \
    asm volatile("tcgen05.ld.sync.aligned.32x32b.x32.b32 "                         \
        "{%0, %1, %2, %3, %4, %5, %6, %7, %8, %9, %10, %11, %12, %13, %14, %15, "  \
        " %16, %17, %18, %19, %20, %21, %22, %23, %24, %25, %26, %27, %28, %29, %30, %31}, [%32];" \
        : "=r"((r)[0]), "=r"((r)[1]), "=r"((r)[2]), "=r"((r)[3]),                  \
          "=r"((r)[4]), "=r"((r)[5]), "=r"((r)[6]), "=r"((r)[7]),                  \
          "=r"((r)[8]), "=r"((r)[9]), "=r"((r)[10]), "=r"((r)[11]),                \
          "=r"((r)[12]), "=r"((r)[13]), "=r"((r)[14]), "=r"((r)[15]),              \
          "=r"((r)[16]), "=r"((r)[17]), "=r"((r)[18]), "=r"((r)[19]),              \
          "=r"((r)[20]), "=r"((r)[21]), "=r"((r)[22]), "=r"((r)[23]),              \
          "=r"((r)[24]), "=r"((r)[25]), "=r"((r)[26]), "=r"((r)[27]),              \
          "=r"((r)[28]), "=r"((r)[29]), "=r"((r)[30]), "=r"((r)[31])               \
        : "r"(a))

static constexpr uint64_t SMEM_DESC_BASE_SW128 =
    (uint64_t(2) << 61) | (uint64_t(1) << 46) | (uint64_t(64) << 32) | (uint64_t(1) << 16);
__device__ __forceinline__ uint64_t make_desc(uint32_t addr) {
    return SMEM_DESC_BASE_SW128 | ((uint64_t)(addr >> 4) & 0x3FFF);
}
__device__ __forceinline__ void mma_f16_ss(uint32_t d, uint64_t ad, uint64_t bd,
                                           uint32_t idesc, uint32_t en) {
    asm volatile(
        "{ .reg .pred p; setp.ne.u32 p, %5, 0;\n\t"
        "tcgen05.mma.cta_group::1.kind::f16 [%0], %1, %2, %3, {%4, %4, %4, %4}, p; }"
        :: "r"(d), "l"(ad), "l"(bd), "r"(idesc), "r"(0u), "r"(en) : "memory");
}
static constexpr uint32_t CONV_IDESC =
    (1u << 4) | (1u << 7) | (1u << 10) | ((128u / 8) << 17) | ((128u / 16) << 24);
#endif // HAS_TCGEN05

// smem layout (after 1024-align): A @0 (32KB), B0 @32K, B1 @64K, mbar @96K.
// Epilogue reuses [0..66K) as fp32 stage with stride 129.
#define SME_A 0
#define SME_B0 32768
#define SME_B1 65536
#define SME_MBAR 98304
#define SME_TSLOT 98336
#define CONV_SMEM_BYTES (1024 + 98304 + 128)

// ---------------------------------------------------------------------------
// Init / pack kernels
// ---------------------------------------------------------------------------
__global__ void conv_decode_kernel(int K, int Kpad, int KV, int KHW, int KW,
                                   int D, int H, int W) {
    int k = blockIdx.x * 256 + threadIdx.x;
    if (k >= Kpad) return;
    if (k < K) {
        int ci = k / KV; int tap = k - ci * KV;
        int kd = tap / KHW; int t2 = tap - kd * KHW;
        int kh = t2 / KW; int kw = t2 - kh * KW;
        g_dec[k] = make_int2(((ci * D + kd) * H + kh) * W + kw,
                             (kd << 20) | (kh << 10) | kw);
    } else {
        g_dec[k] = make_int2(0, 1023 << 20);
    }
}

__global__ void natt_table_kernel() {
    int nb = threadIdx.x;
    if (nb < 245) {
        int od = nb / 49; int r = nb - od * 49;
        int oh = r / 7;   int ow = r - oh * 7;
        g_ndelta[nb] = (od - 2) * 2048 + (oh - 3) * 64 + (ow - 3);
        g_npack[nb]  = (od << 16) | (oh << 8) | ow;
    }
}

__global__ void xpack_kernel(const float* __restrict__ x,
                             uint32_t* __restrict__ dst, int n4) {
    int i = blockIdx.x * 256 + threadIdx.x;
    if (i >= n4) return;
    float4 v = reinterpret_cast<const float4*>(x)[i];
    uint4 o;
    o.x = pack_hl(v.x); o.y = pack_hl(v.y);
    o.z = pack_hl(v.z); o.w = pack_hl(v.w);
    reinterpret_cast<uint4*>(dst)[i] = o;
}

__global__ void wpack_kernel(const float* __restrict__ w, int K, int NC) {
    int kc = blockIdx.x, bm = blockIdx.y;
    int tid = threadIdx.x;
    int r = tid >> 1, half = tid & 1;
    const float* wrow = w + (size_t)(bm * 128 + r) * K;
    uint8_t* hi = g_wpk + (size_t)(bm * NC + kc) * 32768;
    uint8_t* lo = hi + 16384;
#pragma unroll
    for (int i = 0; i < 16; i++) {
        int kk = half * 32 + 2 * i;
        int k = kc * 64 + kk;
        float a0 = (k < K) ? wrow[k] : 0.f;
        float a1 = (k + 1 < K) ? wrow[k + 1] : 0.f;
        uint32_t p0 = pack_hl(a0), p1 = pack_hl(a1);
        uint32_t hp = __byte_perm(p0, p1, 0x7632);
        uint32_t lp = __byte_perm(p0, p1, 0x5410);
        uint32_t off = r * 128 + kk * 2;
        uint32_t sw = off ^ ((off >> 3) & 0x70);
        *reinterpret_cast<uint32_t*>(hi + sw) = hp;
        *reinterpret_cast<uint32_t*>(lo + sw) = lp;
    }
}

__global__ void wpackT_kernel(const float* __restrict__ w, uint8_t* dst,
                              int K, int NC, int J) {
    int kc = blockIdx.x, bm = blockIdx.y;
    int tid = threadIdx.x;
    int r = tid >> 1, half = tid & 1;
    int m = bm * 128 + r;
    uint8_t* hi = dst + (size_t)(bm * NC + kc) * 32768;
    uint8_t* lo = hi + 16384;
#pragma unroll
    for (int i = 0; i < 16; i++) {
        int kk = half * 32 + 2 * i;
        int k = kc * 64 + kk;
        float a0 = (k < K) ? w[(size_t)k * J + m] : 0.f;
        float a1 = (k + 1 < K) ? w[(size_t)(k + 1) * J + m] : 0.f;
        uint32_t p0 = pack_hl(a0), p1 = pack_hl(a1);
        uint32_t hp = __byte_perm(p0, p1, 0x7632);
        uint32_t lp = __byte_perm(p0, p1, 0x5410);
        uint32_t off = r * 128 + kk * 2;
        uint32_t sw = off ^ ((off >> 3) & 0x70);
        *reinterpret_cast<uint32_t*>(hi + sw) = hp;
        *reinterpret_cast<uint32_t*>(lo + sw) = lp;
    }
}

// ---------------------------------------------------------------------------
// Conv kernel: single-buffered A, double-buffered B, TMEM 256 cols, 2 CTA/SM.
// Smem-staged coalesced epilogue.
// ---------------------------------------------------------------------------
struct ConvParams {
    const uint32_t* xpk;
    const float* wf;
    const float* bias;
    uint32_t* outpk;
    float* outf;
    int D, H, W;
    int Hout, Wout;
    int sd, sh, sw, pd, ph, pw;
    int K, NC;
    int outStrideC, outOffset;
    int gelu;
};

template <int BM>
__global__ __launch_bounds__(512, 2) void conv_mma_kernel(ConvParams p) {
    extern __shared__ char smem_raw[];
    char* smem_al = (char*)(((uintptr_t)smem_raw + 1023) & ~(uintptr_t)1023);

    const int tid = threadIdx.x;
    const int bn = blockIdx.x;
    const int mblk0 = blockIdx.y * BM;
    const int HWo = p.Hout * p.Wout;

#if HAS_TCGEN05
    const uint32_t sb = smem_u32(smem_al);
    const uint32_t mbar = sb + SME_MBAR;
    const uint32_t tmem_slot = sb + SME_TSLOT;
    const int wid = tid >> 5;
    const int lane = tid & 31;

    if (wid == 0) {
        TCGEN05_ALLOC(tmem_slot, 256);
        TCGEN05_RELINQ();
    }
    if (tid == 0) {
#pragma unroll
        for (int i = 0; i < 4; i++) MBARRIER_INIT(mbar + 8 * i, 1);
    }
    __syncthreads();
    uint32_t tmem;
    asm volatile("ld.shared.b32 %0, [%1];" : "=r"(tmem) : "r"(tmem_slot));

    const int r = tid >> 2;
    const int q = tid & 3;
    const int n = bn * 128 + r;
    const int od = n / HWo; int rr2 = n - od * HWo;
    const int oh = rr2 / p.Wout; const int ow = rr2 - oh * p.Wout;
    const int id0 = od * p.sd - p.pd;
    const int ih0 = oh * p.sh - p.ph;
    const int iw0 = ow * p.sw - p.pw;
    const int gbase = (id0 * p.H + ih0) * p.W + iw0;
    const int NC = p.NC;

    auto fillA = [&](int kc, int bm) {
        const uint8_t* src = g_wpk + ((size_t)(mblk0 + bm) * NC + kc) * 32768 + tid * 16;
        char* dst = smem_al + SME_A + tid * 16;
#pragma unroll
        for (int i = 0; i < 4; i++) {
            uint4 v = *reinterpret_cast<const uint4*>(src + i * 8192);
            *reinterpret_cast<uint4*>(dst + i * 8192) = v;
        }
    };
    auto fillB = [&](int st, int kc) {
        char* Bhi = smem_al + (st ? SME_B1 : SME_B0);
        char* Blo = Bhi + 16384;
        const int kt = kc * 64;
#pragma unroll
        for (int i = 0; i < 8; i++) {
            int kk = q * 16 + 2 * i;
            int k = kt + kk;
            int4 dv = *reinterpret_cast<const int4*>(&g_dec[k]);
            uint32_t v0 = 0, v1 = 0;
            {
                int kd = dv.y >> 20, kh = (dv.y >> 10) & 1023, kw = dv.y & 1023;
                if ((unsigned)(id0 + kd) < (unsigned)p.D &&
                    (unsigned)(ih0 + kh) < (unsigned)p.H &&
                    (unsigned)(iw0 + kw) < (unsigned)p.W)
                    v0 = p.xpk[gbase + dv.x];
            }
            {
                int kd = dv.w >> 20, kh = (dv.w >> 10) & 1023, kw = dv.w & 1023;
                if ((unsigned)(id0 + kd) < (unsigned)p.D &&
                    (unsigned)(ih0 + kh) < (unsigned)p.H &&
                    (unsigned)(iw0 + kw) < (unsigned)p.W)
                    v1 = p.xpk[gbase + dv.z];
            }
            uint32_t off = r * 128 + kk * 2;
            uint32_t sw = off ^ ((off >> 3) & 0x70);
            *reinterpret_cast<uint32_t*>(Bhi + sw) = __byte_perm(v0, v1, 0x7632);
            *reinterpret_cast<uint32_t*>(Blo + sw) = __byte_perm(v0, v1, 0x5410);
        }
    };

    int wpar = 0;
    auto waitCommits = [&](int target) {
        while (wpar < target) {
            MBARRIER_WAIT_PARITY(mbar + 8 * (wpar & 3), (wpar >> 2) & 1);
            wpar++;
        }
    };

    fillB(0, 0);

    for (int kc = 0; kc < NC; kc++) {
        int st = kc & 1;
#pragma unroll
        for (int bm = 0; bm < BM; bm++) {
            int ni = kc * BM + bm;
            if (ni >= 1) waitCommits(ni);
            fillA(kc, bm);
            FENCE_PROXY_ASYNC();
            __syncthreads();
            if (wid == 0 && elect_one()) {
                uint64_t dAh = make_desc(sb + SME_A);
                uint64_t dAl = dAh + (16384 >> 4);
                uint64_t dBh = make_desc(sb + (st ? SME_B1 : SME_B0));
                uint64_t dBl = dBh + (16384 >> 4);
                uint32_t d = tmem + bm * 128;
                uint32_t first = (kc == 0) ? 0u : 1u;
#pragma unroll
                for (int s = 0; s < 4; s++) {
                    uint64_t o = s * 2;
                    mma_f16_ss(d, dAh + o, dBh + o, CONV_IDESC, first); first = 1;
                    mma_f16_ss(d, dAh + o, dBl + o, CONV_IDESC, 1);
                    mma_f16_ss(d, dAl + o, dBh + o, CONV_IDESC, 1);
                }
                TCGEN05_COMMIT(mbar + 8 * (ni & 3));
            }
        }
        if (kc + 1 < NC) fillB(st ^ 1, kc + 1);
    }
    waitCommits(NC * BM);
    TCGEN05_FENCE_AFTER();

    // ---- smem-staged coalesced epilogue ----
    {
        float* stage = reinterpret_cast<float*>(smem_al);   // [128][129]
        const int sp = wid & 3;
        const int cb = wid >> 2;
#pragma unroll
        for (int bm = 0; bm < BM; bm++) {
            uint32_t dr[32];
            TCGEN05_LD_X32(dr, tmem + bm * 128 + cb * 32);
            TCGEN05_WAIT_LD();
            __syncthreads();            // stage area free (prev iter done)
            int srow = sp * 32 + lane;
#pragma unroll
            for (int j = 0; j < 32; j++)
                stage[srow * 129 + cb * 32 + j] = __uint_as_float(dr[j]);
            __syncthreads();
            // warp wid writes rows 8*wid .. 8*wid+7, lane = column
#pragma unroll
            for (int rr = 0; rr < 8; rr++) {
                int ml = wid * 8 + rr;
                int m = (mblk0 + bm) * 128 + ml;
                float bv = p.bias[m];
                size_t obase = (size_t)m * p.outStrideC + p.outOffset + bn * 128;
#pragma unroll
                for (int part = 0; part < 4; part++) {
                    float v = stage[ml * 129 + part * 32 + lane] + bv;
                    if (p.gelu) v = gelu_tanh(v);
                    if (p.outpk) p.outpk[obase + part * 32 + lane] = pack_hl(v);
                    else p.outf[obase + part * 32 + lane] = v;
                }
            }
        }
        TCGEN05_FENCE_BEFORE();
    }
    __syncthreads();
    if (tid == 0) {
#pragma unroll
        for (int i = 0; i < 4; i++) MBARRIER_INVAL(mbar + 8 * i);
    }
    if (wid == 0) TCGEN05_DEALLOC(tmem, 256);

#else  // FFMA fallback (never executes on GB300)
    for (int bm = 0; bm < BM; bm++) {
        const int m_base = (mblk0 + bm) * 128;
        for (int idx = tid; idx < 128 * 128; idx += 512) {
            int ml = idx >> 7, nl = idx & 127;
            int m = m_base + ml;
            int nn = bn * 128 + nl;
            int od = nn / HWo; int rr2 = nn - od * HWo;
            int oh = rr2 / p.Wout; int ow = rr2 - oh * p.Wout;
            int id0 = od * p.sd - p.pd, ih0 = oh * p.sh - p.ph, iw0 = ow * p.sw - p.pw;
            int gb = (id0 * p.H + ih0) * p.W + iw0;
            float s = 0.f;
            for (int k = 0; k < p.K; k++) {
                int2 dv = g_dec[k];
                int kd = dv.y >> 20, kh = (dv.y >> 10) & 1023, kw = dv.y & 1023;
                if ((unsigned)(id0 + kd) < (unsigned)p.D &&
                    (unsigned)(ih0 + kh) < (unsigned)p.H &&
                    (unsigned)(iw0 + kw) < (unsigned)p.W)
                    s += p.wf[(size_t)m * p.K + k] * unpack_hl(p.xpk[gb + dv.x]);
            }
            s += p.bias[m];
            if (p.gelu) s = gelu_tanh(s);
            size_t ob = (size_t)m * p.outStrideC + p.outOffset + nn;
            if (p.outpk) p.outpk[ob] = pack_hl(s);
            else p.outf[ob] = s;
        }
    }
#endif
}

// ---------------------------------------------------------------------------
// Token GEMM: same pipeline; mode-1 epilogue smem-staged.
// ---------------------------------------------------------------------------
struct TokParams {
    const uint32_t* bpk;
    const uint8_t* wpk;
    const float* wf;
    const float* bias;
    float* out;
    int T, J, Kdim, NC, mode;
};

template <int BM>
__global__ __launch_bounds__(512, 2) void tok_mma_kernel(TokParams p) {
    extern __shared__ char smem_raw[];
    char* smem_al = (char*)(((uintptr_t)smem_raw + 1023) & ~(uintptr_t)1023);

    const int tid = threadIdx.x;
    const int bn = blockIdx.x;
    const int mblk0 = blockIdx.y * BM;

#if HAS_TCGEN05
    const uint32_t sb = smem_u32(smem_al);
    const uint32_t mbar = sb + SME_MBAR;
    const uint32_t tmem_slot = sb + SME_TSLOT;
    const int wid = tid >> 5;
    const int lane = tid & 31;

    if (wid == 0) {
        TCGEN05_ALLOC(tmem_slot, 256);
        TCGEN05_RELINQ();
    }
    if (tid == 0) {
#pragma unroll
        for (int i = 0; i < 4; i++) MBARRIER_INIT(mbar + 8 * i, 1);
    }
    __syncthreads();
    uint32_t tmem;
    asm volatile("ld.shared.b32 %0, [%1];" : "=r"(tmem) : "r"(tmem_slot));

    const int r = tid >> 2;
    const int q = tid & 3;
    const uint32_t* bsrc = p.bpk + (size_t)(bn * 128 + r) * p.Kdim;
    const int NC = p.NC;

    auto fillA = [&](int kc, int bm) {
        const uint8_t* src = p.wpk + ((size_t)(mblk0 + bm) * NC + kc) * 32768 + tid * 16;
        char* dst = smem_al + SME_A + tid * 16;
#pragma unroll
        for (int i = 0; i < 4; i++) {
            uint4 v = *reinterpret_cast<const uint4*>(src + i * 8192);
            *reinterpret_cast<uint4*>(dst + i * 8192) = v;
        }
    };
    auto fillB = [&](int st, int kc) {
        char* Bhi = smem_al + (st ? SME_B1 : SME_B0);
        char* Blo = Bhi + 16384;
        const uint32_t* src = bsrc + kc * 64 + q * 16;
        uint32_t buf[16];
#pragma unroll
        for (int i = 0; i < 4; i++)
            *reinterpret_cast<uint4*>(&buf[i * 4]) =
                *reinterpret_cast<const uint4*>(src + i * 4);
#pragma unroll
        for (int i = 0; i < 8; i++) {
            int kk = q * 16 + 2 * i;
            uint32_t v0 = buf[2 * i], v1 = buf[2 * i + 1];
            uint32_t off = r * 128 + kk * 2;
            uint32_t sw = off ^ ((off >> 3) & 0x70);
            *reinterpret_cast<uint32_t*>(Bhi + sw) = __byte_perm(v0, v1, 0x7632);
            *reinterpret_cast<uint32_t*>(Blo + sw) = __byte_perm(v0, v1, 0x5410);
        }
    };

    int wpar = 0;
    auto waitCommits = [&](int target) {
        while (wpar < target) {
            MBARRIER_WAIT_PARITY(mbar + 8 * (wpar & 3), (wpar >> 2) & 1);
            wpar++;
        }
    };

    fillB(0, 0);

    for (int kc = 0; kc < NC; kc++) {
        int st = kc & 1;
#pragma unroll
        for (int bm = 0; bm < BM; bm++) {
            int ni = kc * BM + bm;
            if (ni >= 1) waitCommits(ni);
            fillA(kc, bm);
            FENCE_PROXY_ASYNC();
            __syncthreads();
            if (wid == 0 && elect_one()) {
                uint64_t dAh = make_desc(sb + SME_A);
                uint64_t dAl = dAh + (16384 >> 4);
                uint64_t dBh = make_desc(sb + (st ? SME_B1 : SME_B0));
                uint64_t dBl = dBh + (16384 >> 4);
                uint32_t d = tmem + bm * 128;
                uint32_t first = (kc == 0) ? 0u : 1u;
#pragma unroll
                for (int s = 0; s < 4; s++) {
                    uint64_t o = s * 2;
                    mma_f16_ss(d, dAh + o, dBh + o, CONV_IDESC, first); first = 1;
                    mma_f16_ss(d, dAh + o, dBl + o, CONV_IDESC, 1);
                    mma_f16_ss(d, dAl + o, dBh + o, CONV_IDESC, 1);
                }
                TCGEN05_COMMIT(mbar + 8 * (ni & 3));
            }
        }
        if (kc + 1 < NC) fillB(st ^ 1, kc + 1);
    }
    waitCommits(NC * BM);
    TCGEN05_FENCE_AFTER();

    {
        const int sp = wid & 3;
        const int cb = wid >> 2;
        const int t0 = bn * 128 + cb * 32;
        if (p.mode == 0) {
            // already coalesced: lane = channel m
#pragma unroll
            for (int bm = 0; bm < BM; bm++) {
                const int m = (mblk0 + bm) * 128 + sp * 32 + lane;
                const float bv = p.bias[m];
                uint32_t dr[32];
                TCGEN05_LD_X32(dr, tmem + bm * 128 + cb * 32);
                TCGEN05_WAIT_LD();
#pragma unroll
                for (int j = 0; j < 32; j++)
                    p.out[(size_t)(t0 + j) * p.J + m] = __uint_as_float(dr[j]) + bv;
            }
        } else {
            // staged residual add: warp writes rows with lane = token column
            float* stage = reinterpret_cast<float*>(smem_al);   // [128][129]
#pragma unroll
            for (int bm = 0; bm < BM; bm++) {
                uint32_t dr[32];
                TCGEN05_LD_X32(dr, tmem + bm * 128 + cb * 32);
                TCGEN05_WAIT_LD();
                __syncthreads();
                int srow = sp * 32 + lane;
#pragma unroll
                for (int j = 0; j < 32; j++)
                    stage[srow * 129 + cb * 32 + j] = __uint_as_float(dr[j]);
                __syncthreads();
#pragma unroll
                for (int rr = 0; rr < 8; rr++) {
                    int ml = wid * 8 + rr;
                    int m = (mblk0 + bm) * 128 + ml;
                    float bv = p.bias[m];
                    float* orow = p.out + (size_t)m * p.T + bn * 128;
#pragma unroll
                    for (int part = 0; part < 4; part++) {
                        int col = part * 32 + lane;
                        orow[col] += stage[ml * 129 + col] + bv;
                    }
                }
            }
        }
        TCGEN05_FENCE_BEFORE();
    }
    __syncthreads();
    if (tid == 0) {
#pragma unroll
        for (int i = 0; i < 4; i++) MBARRIER_INVAL(mbar + 8 * i);
    }
    if (wid == 0) TCGEN05_DEALLOC(tmem, 256);

#else  // FFMA fallback
    for (int bm = 0; bm < BM; bm++) {
        int m_base = (mblk0 + bm) * 128;
        for (int idx = tid; idx < 128 * 128; idx += 512) {
            int tl = idx >> 7, jl = idx & 127;
            int t = bn * 128 + tl, j = m_base + jl;
            float s = 0.f;
            for (int k = 0; k < p.Kdim; k++)
                s += unpack_hl(p.bpk[(size_t)t * p.Kdim + k]) * p.wf[(size_t)k * p.J + j];
            s += p.bias[j];
            if (p.mode == 0) p.out[(size_t)t * p.J + j] = s;
            else p.out[(size_t)j * p.T + t] += s;
        }
    }
#endif
}

// ---------------------------------------------------------------------------
// LayerNorm: fp32 channel-major -> packed token-major
// ---------------------------------------------------------------------------
__global__ __launch_bounds__(256) void layernorm_kernel(
    const float* __restrict__ x, const float* __restrict__ g,
    const float* __restrict__ b, uint32_t* __restrict__ ypk, int T) {
    const int tx = threadIdx.x;
    const int ty = threadIdx.y;
    const int t = blockIdx.x * 32 + tx;

    float s = 0.f, ss = 0.f;
#pragma unroll
    for (int i = 0; i < 64; i++) {
        int c = ty * 64 + i;
        float v = x[(size_t)c * T + t];
        s += v; ss += v * v;
    }
    __shared__ float shs[8][32], shss[8][32];
    __shared__ float smu[32], srs[32];
    shs[ty][tx] = s; shss[ty][tx] = ss;
    __syncthreads();
    if (ty == 0) {
        float S = 0.f, SS = 0.f;
#pragma unroll
        for (int j = 0; j < 8; j++) { S += shs[j][tx]; SS += shss[j][tx]; }
        float mu = S * (1.f / 512.f);
        float var = SS * (1.f / 512.f) - mu * mu;
        smu[tx] = mu;
        srs[tx] = rsqrtf(var + 1e-5f);
    }
    __syncthreads();
    float mu = smu[tx], rs = srs[tx];
    uint32_t* yrow = ypk + (size_t)t * 512 + ty * 64;
#pragma unroll
    for (int i = 0; i < 64; i++) {
        int c = ty * 64 + i;
        float v = x[(size_t)c * T + t];
        yrow[i] = pack_hl((v - mu) * rs * g[c] + b[c]);
    }
}

// ---------------------------------------------------------------------------
// Neighborhood attention — coalesced score phase (R10, unchanged)
// ---------------------------------------------------------------------------
__global__ __launch_bounds__(256) void natt_kernel(
    const float* __restrict__ qkv, uint32_t* __restrict__ atpk) {
    __shared__ float psh[8][248];
    __shared__ float tsh[8][32][33];

    const int warp = threadIdx.x >> 5;
    const int lane = threadIdx.x & 31;
    const int t = blockIdx.x * 8 + warp;
    const int head = blockIdx.y;
    const int d = t >> 11;
    const int hh = (t >> 6) & 31;
    const int ww = t & 63;

    float2 q2 = *reinterpret_cast<const float2*>(
        qkv + (size_t)t * 1536 + head * 64 + 2 * lane);
    q2.x *= 0.125f; q2.y *= 0.125f;

    float sc[8];
    float m = -1e30f;
#pragma unroll
    for (int it = 0; it < 8; it++) {
#pragma unroll
        for (int j = 0; j < 32; j++) {
            int nb = it * 32 + j;
            float pv = 0.f;
            if (nb < 245) {
                int pk = g_npack[nb];
                int nd = d + (pk >> 16) - 2;
                int nh = hh + ((pk >> 8) & 255) - 3;
                int nw = ww + (pk & 255) - 3;
                if ((unsigned)nd < 4u && (unsigned)nh < 32u && (unsigned)nw < 64u) {
                    int nt = (nd * 32 + nh) * 64 + nw;
                    float2 kv = *reinterpret_cast<const float2*>(
                        qkv + (size_t)nt * 1536 + 512 + head * 64 + 2 * lane);
                    pv = fmaf(q2.x, kv.x, q2.y * kv.y);
                }
            }
            tsh[warp][j][lane] = pv;
        }
        __syncwarp();
        float s = 0.f;
#pragma unroll
        for (int j = 0; j < 32; j++) s += tsh[warp][lane][j];
        __syncwarp();

        int nb = it * 32 + lane;
        float dot = -1e30f;
        if (nb < 245) {
            int pk = g_npack[nb];
            int nd = d + (pk >> 16) - 2;
            int nh = hh + ((pk >> 8) & 255) - 3;
            int nw = ww + (pk & 255) - 3;
            if ((unsigned)nd < 4u && (unsigned)nh < 32u && (unsigned)nw < 64u)
                dot = s;
        }
        sc[it] = dot;
        m = fmaxf(m, dot);
    }
#pragma unroll
    for (int o = 16; o; o >>= 1) m = fmaxf(m, __shfl_xor_sync(0xffffffffu, m, o));

    float l = 0.f;
#pragma unroll
    for (int it = 0; it < 8; it++) {
        int nb = it * 32 + lane;
        float e = (sc[it] > -1e29f) ? __expf(sc[it] - m) : 0.f;
        if (nb < 248) psh[warp][nb] = e;
        l += e;
    }
#pragma unroll
    for (int o = 16; o; o >>= 1) l += __shfl_xor_sync(0xffffffffu, l, o);
    __syncwarp();

    float acc0 = 0.f, acc1 = 0.f;
    for (int nb = 0; nb < 245; nb++) {
        float pb = psh[warp][nb];
        if (pb > 0.f) {
            int nt = t + g_ndelta[nb];
            const float* vp = qkv + (size_t)nt * 1536 + 1024 + head * 64;
            acc0 = fmaf(pb, vp[lane], acc0);
            acc1 = fmaf(pb, vp[lane + 32], acc1);
        }
    }
    float inv = 1.f / l;
    uint32_t* op = atpk + (size_t)t * 512 + head * 64;
    op[lane] = pack_hl(acc0 * inv);
    op[lane + 32] = pack_hl(acc1 * inv);
}

// ---------------------------------------------------------------------------
// Host launcher
// ---------------------------------------------------------------------------
extern "C" void kernel_launch(void* const* d_in, const int* in_sizes, int n_in,
                              void* d_out, int out_size) {
    const float* x2d  = (const float*)d_in[0];
    const float* x3d  = (const float*)d_in[1];
    const float* sw0  = (const float*)d_in[2];  const float* sb0 = (const float*)d_in[3];
    const float* sw1  = (const float*)d_in[4];  const float* sb1 = (const float*)d_in[5];
    const float* sw2  = (const float*)d_in[6];  const float* sb2 = (const float*)d_in[7];
    const float* pw0  = (const float*)d_in[8];  const float* pb0 = (const float*)d_in[9];
    const float* pw1  = (const float*)d_in[10]; const float* pb1 = (const float*)d_in[11];
    const float* pw2  = (const float*)d_in[12]; const float* pb2 = (const float*)d_in[13];
    const float* latw = (const float*)d_in[14]; const float* latb = (const float*)d_in[15];
    const float* lng  = (const float*)d_in[16]; const float* lnb  = (const float*)d_in[17];
    const float* qkvw = (const float*)d_in[18]; const float* qkvb = (const float*)d_in[19];
    const float* pjw  = (const float*)d_in[20]; const float* pjb  = (const float*)d_in[21];
    float* lat = (float*)d_out;

    uint32_t *pkA, *pkB, *pkF, *pkX, *ynpk, *atpk;
    float *qkvB;
    uint8_t *wpk2;
    cudaGetSymbolAddress((void**)&pkA, g_pk_a);
    cudaGetSymbolAddress((void**)&pkB, g_pk_b);
    cudaGetSymbolAddress((void**)&pkF, g_pk_f);
    cudaGetSymbolAddress((void**)&pkX, g_pk_x2d);
    cudaGetSymbolAddress((void**)&ynpk, g_ynpk);
    cudaGetSymbolAddress((void**)&qkvB, g_qkv);
    cudaGetSymbolAddress((void**)&atpk, g_atpk);
    cudaGetSymbolAddress((void**)&wpk2, g_wpk2);

    cudaFuncSetAttribute(conv_mma_kernel<1>,
                         cudaFuncAttributeMaxDynamicSharedMemorySize, CONV_SMEM_BYTES);
    cudaFuncSetAttribute(conv_mma_kernel<2>,
                         cudaFuncAttributeMaxDynamicSharedMemorySize, CONV_SMEM_BYTES);
    cudaFuncSetAttribute(tok_mma_kernel<1>,
                         cudaFuncAttributeMaxDynamicSharedMemorySize, CONV_SMEM_BYTES);
    cudaFuncSetAttribute(tok_mma_kernel<2>,
                         cudaFuncAttributeMaxDynamicSharedMemorySize, CONV_SMEM_BYTES);

    auto run_conv = [&](const uint32_t* xpk, const float* wf, const float* bias,
                        uint32_t* outpk, float* outf,
                        int Cin, int D, int H, int W, int Dout, int Hout, int Wout,
                        int KD, int KH, int KW, int sd, int sh, int sw,
                        int pd, int ph, int pw, int Cout,
                        int outStrideC, int outOffset, int gelu) {
        int K = Cin * KD * KH * KW;
        int NC = (K + 63) / 64;
        int Kp = NC * 64;
        conv_decode_kernel<<<(Kp + 255) / 256, 256>>>(K, Kp, KD * KH * KW, KH * KW,
                                                      KW, D, H, W);
        wpack_kernel<<<dim3(NC, Cout / 128), 256>>>(wf, K, NC);
        int Nvox = Dout * Hout * Wout;
        ConvParams p{ xpk, wf, bias, outpk, outf,
                      D, H, W, Hout, Wout, sd, sh, sw, pd, ph, pw,
                      K, NC, outStrideC, outOffset, gelu };
        int nblk = Cout / 128;
        int bn = Nvox / 128;
        if (nblk % 2 == 0 && bn * (nblk / 2) >= 256)
            conv_mma_kernel<2><<<dim3(bn, nblk / 2), 512, CONV_SMEM_BYTES>>>(p);
        else
            conv_mma_kernel<1><<<dim3(bn, nblk), 512, CONV_SMEM_BYTES>>>(p);
    };

    natt_table_kernel<<<1, 256>>>();
    xpack_kernel<<<(5 * 24 * 256 * 512 / 4 + 255) / 256, 256>>>(
        x3d, pkA, 5 * 24 * 256 * 512 / 4);
    xpack_kernel<<<(8 * 256 * 512 / 4 + 255) / 256, 256>>>(
        x2d, pkX, 8 * 256 * 512 / 4);

    // ---- 3D tower ----
    run_conv(pkA, pw0, pb0, pkB, nullptr, 5, 24, 256, 512, 12, 128, 256,
             3, 3, 3, 2, 2, 2, 1, 1, 1, 128, 393216, 0, 1);
    run_conv(pkB, pw1, pb1, pkA, nullptr, 128, 12, 128, 256, 6, 64, 128,
             3, 3, 3, 2, 2, 2, 1, 1, 1, 256, 49152, 0, 1);
    run_conv(pkA, pw2, pb2, pkF, nullptr, 256, 6, 64, 128, 3, 32, 64,
             3, 3, 3, 2, 2, 2, 1, 1, 1, 512, 8192, 0, 1);

    // ---- 2D tower ----
    run_conv(pkX, sw0, sb0, pkB, nullptr, 8, 1, 256, 512, 1, 128, 256,
             1, 3, 3, 1, 2, 2, 0, 1, 1, 128, 32768, 0, 1);
    run_conv(pkB, sw1, sb1, pkA, nullptr, 128, 1, 128, 256, 1, 64, 128,
             1, 3, 3, 1, 2, 2, 0, 1, 1, 256, 8192, 0, 1);
    run_conv(pkA, sw2, sb2, pkF, nullptr, 256, 1, 64, 128, 1, 32, 64,
             1, 3, 3, 1, 2, 2, 0, 1, 1, 512, 8192, 3 * 2048, 1);

    // ---- lateral 1x1x1 -> d_out fp32 ----
    run_conv(pkF, latw, latb, nullptr, lat, 512, 4, 32, 64, 4, 32, 64,
             1, 1, 1, 1, 1, 1, 0, 0, 0, 512, 8192, 0, 0);

    // ---- attention weight prepack ----
    const size_t QKV_PK = 8 * 12 * 32768;
    const size_t PRJ_PK = 8 * 4 * 32768;
    for (int i = 0; i < 3; i++) {
        wpackT_kernel<<<dim3(8, 12), 256>>>(qkvw + (size_t)i * 512 * 1536,
                                            wpk2 + i * QKV_PK, 512, 8, 1536);
        wpackT_kernel<<<dim3(8, 4), 256>>>(pjw + (size_t)i * 512 * 512,
                                           wpk2 + 3 * QKV_PK + i * PRJ_PK, 512, 8, 512);
    }

    // ---- 3 neighborhood-attention blocks ----
    for (int i = 0; i < 3; i++) {
        layernorm_kernel<<<8192 / 32, dim3(32, 8)>>>(lat, lng + i * 512, lnb + i * 512,
                                                     ynpk, 8192);
        TokParams pq{ ynpk, wpk2 + i * QKV_PK, qkvw + (size_t)i * 512 * 1536,
                      qkvb + i * 1536, qkvB, 8192, 1536, 512, 8, 0 };
        tok_mma_kernel<2><<<dim3(8192 / 128, 6), 512, CONV_SMEM_BYTES>>>(pq);
        natt_kernel<<<dim3(1024, 8), 256>>>(qkvB, atpk);
        TokParams pp{ atpk, wpk2 + 3 * QKV_PK + i * PRJ_PK,
                      pjw + (size_t)i * 512 * 512,
                      pjb + i * 512, lat, 8192, 512, 512, 8, 1 };
        tok_mma_kernel<1><<<dim3(8192 / 128, 4), 512, CONV_SMEM_BYTES>>>(pp);
    }
}

// round 13
// speedup vs baseline: 1.5974x; 1.0442x over previous
#include <cuda_runtime.h>
#include <cuda_bf16.h>
#include <math.h>
#include <cstdint>

#if defined(__CUDA_ARCH_SPECIFIC__) || defined(__CUDA_ARCH_FEAT_SM103_ALL)
#define HAS_TCGEN05 1
#else
#define HAS_TCGEN05 0
#endif

// ---------------------------------------------------------------------------
// Scratch buffers (packed u32 = bf16 hi << 16 | bf16 lo)
// ---------------------------------------------------------------------------
__device__ uint32_t g_pk_a[15728640];
__device__ uint32_t g_pk_b[50331648];
__device__ uint32_t g_pk_f[4194304];
__device__ uint32_t g_pk_x2d[1048576];
__device__ uint8_t  g_wpk[14155776];
__device__ uint8_t  g_wpk2[12582912];
__device__ uint32_t g_ynpk[8192 * 512];
__device__ float    g_qkv[8192 * 1536];
__device__ uint32_t g_kpl[8192 * 256];   // K-plane bf16x2 for natt score
__device__ uint32_t g_atpk[8192 * 512];
__device__ int2     g_dec[8192];
__device__ int      g_ndelta[256];
__device__ int      g_npack[256];

// ---------------------------------------------------------------------------
// Common helpers
// ---------------------------------------------------------------------------
__device__ __forceinline__ uint32_t smem_u32(const void* p) {
    uint32_t a;
    asm("{ .reg .u64 t; cvta.to.shared.u64 t, %1; cvt.u32.u64 %0, t; }"
        : "=r"(a) : "l"(p));
    return a;
}
__device__ __forceinline__ float gelu_tanh(float x) {
    float x3 = x * x * x;
    float t = tanhf(0.7978845608028654f * (x + 0.044715f * x3));
    return 0.5f * x * (1.0f + t);
}
__device__ __forceinline__ uint32_t pack_hl(float f) {
    __nv_bfloat16 h = __float2bfloat16(f);
    __nv_bfloat16 l = __float2bfloat16(f - __bfloat162float(h));
    return ((uint32_t)__bfloat16_as_ushort(h) << 16) | __bfloat16_as_ushort(l);
}
__device__ __forceinline__ float unpack_hl(uint32_t v) {
    float h = __bfloat162float(__ushort_as_bfloat16((unsigned short)(v >> 16)));
    float l = __bfloat162float(__ushort_as_bfloat16((unsigned short)(v & 0xFFFF)));
    return h + l;
}

#if HAS_TCGEN05
__device__ __forceinline__ uint32_t elect_one() {
    uint32_t pred;
    asm volatile("{ .reg .pred p; elect.sync _|p, 0xFFFFFFFF; selp.b32 %0, 1, 0, p; }"
                 : "=r"(pred));
    return pred;
}
#define TCGEN05_ALLOC(a, n) \
    asm volatile("tcgen05.alloc.cta_group::1.sync.aligned.shared::cta.b32 [%0], %1;" \
                 :: "r"((uint32_t)(a)), "r"((uint32_t)(n)) : "memory")
#define TCGEN05_DEALLOC(t, n) \
    asm volatile("tcgen05.dealloc.cta_group::1.sync.aligned.b32 %0, %1;" :: "r"(t), "r"(n))
#define TCGEN05_RELINQ() \
    asm volatile("tcgen05.relinquish_alloc_permit.cta_group::1.sync.aligned;")
#define TCGEN05_COMMIT(m) \
    asm volatile("tcgen05.commit.cta_group::1.mbarrier::arrive::one.shared::cluster.b64 [%0];" \
                 :: "r"((uint32_t)(m)) : "memory")
#define TCGEN05_FENCE_AFTER() \
    asm volatile("tcgen05.fence::after_thread_sync;" ::: "memory")
#define TCGEN05_FENCE_BEFORE() \
    asm volatile("tcgen05.fence::before_thread_sync;" ::: "memory")
#define TCGEN05_WAIT_LD() asm volatile("tcgen05.wait::ld.sync.aligned;" ::: "memory")
#define FENCE_PROXY_ASYNC() asm volatile("fence.proxy.async.shared::cta;" ::: "memory")
#define MBARRIER_INIT(m, c) \
    asm volatile("mbarrier.init.shared.b64 [%0], %1;" :: "r"((uint32_t)(m)), "r"((uint32_t)(c)) : "memory")
#define MBARRIER_INVAL(m) \
    asm volatile("mbarrier.inval.shared.b64 [%0];" :: "r"((uint32_t)(m)) : "memory")
#define MBARRIER_EXPECT_TX(m, b) \
    asm volatile("mbarrier.arrive.expect_tx.shared.b64 _, [%0], %1;" \
                 :: "r"((uint32_t)(m)), "r"((uint32_t)(b)) : "memory")
#define CP_BULK_G2S(dst, src, nbytes, mbar) \
    asm volatile("cp.async.bulk.shared::cta.global.mbarrier::complete_tx::bytes [%0], [%1], %2, [%3];" \
                 :: "r"((uint32_t)(dst)), "l"(src), "r"((uint32_t)(nbytes)), \
                    "r"((uint32_t)(mbar)) : "memory")
#define MBARRIER_WAIT_PARITY(m, ph) do {                                           \
    uint32_t _m = (uint32_t)(m), _p = (uint32_t)(ph), _d;                          \
    asm volatile("{ .reg .pred p; mbarrier.try_wait.parity.acquire.cta.shared::cta.b64 p, [%1], %2;" \
                 " selp.b32 %0, 1, 0, p; }" : "=r"(_d) : "r"(_m), "r"(_p) : "memory"); \
    if (!_d) {                                                                     \
        asm volatile("{ .reg .pred P1; WL_%=: mbarrier.try_wait.parity.acquire.cta.shared::cta.b64 P1, [%0], %1, 0x989680;" \
                     " @P1 bra.uni WD_%=; bra.uni WL_%=; WD_%=: }"                 \
                     :: "r"(_m), "r"(_p) : "memory");                              \
    }                                                                              \
} while (0)
#define TCGEN05_LD_X32(r, a)                                                       \
    asm volatile("tcgen05.ld.sync.aligned.32x32b.x32.b32 "                         \
        "{%0, %1, %2, %3, %4, %5, %6, %7, %8, %9, %10, %11, %12, %13, %14, %15, "  \
        " %16, %17, %18, %19, %20, %21, %22, %23, %24, %25, %26, %27, %28, %29, %30, %31}, [%32];" \
        : "=r"((r)[0]), "=r"((r)[1]), "=r"((r)[2]), "=r"((r)[3]),                  \
          "=r"((r)[4]), "=r"((r)[5]), "=r"((r)[6]), "=r"((r)[7]),                  \
          "=r"((r)[8]), "=r"((r)[9]), "=r"((r)[10]), "=r"((r)[11]),                \
          "=r"((r)[12]), "=r"((r)[13]), "=r"((r)[14]), "=r"((r)[15]),              \
          "=r"((r)[16]), "=r"((r)[17]), "=r"((r)[18]), "=r"((r)[19]),              \
          "=r"((r)[20]), "=r"((r)[21]), "=r"((r)[22]), "=r"((r)[23]),              \
          "=r"((r)[24]), "=r"((r)[25]), "=r"((r)[26]), "=r"((r)[27]),              \
          "=r"((r)[28]), "=r"((r)[29]), "=r"((r)[30]), "=r"((r)[31])               \
        : "r"(a))

static constexpr uint64_t SMEM_DESC_BASE_SW128 =
    (uint64_t(2) << 61) | (uint64_t(1) << 46) | (uint64_t(64) << 32) | (uint64_t(1) << 16);
__device__ __forceinline__ uint64_t make_desc(uint32_t addr) {
    return SMEM_DESC_BASE_SW128 | ((uint64_t)(addr >> 4) & 0x3FFF);
}
__device__ __forceinline__ void mma_f16_ss(uint32_t d, uint64_t ad, uint64_t bd,
                                           uint32_t idesc, uint32_t en) {
    asm volatile(
        "{ .reg .pred p; setp.ne.u32 p, %5, 0;\n\t"
        "tcgen05.mma.cta_group::1.kind::f16 [%0], %1, %2, %3, {%4, %4, %4, %4}, p; }"
        :: "r"(d), "l"(ad), "l"(bd), "r"(idesc), "r"(0u), "r"(en) : "memory");
}
static constexpr uint32_t CONV_IDESC =
    (1u << 4) | (1u << 7) | (1u << 10) | ((128u / 8) << 17) | ((128u / 16) << 24);
#endif // HAS_TCGEN05

// smem layout (after 1024-align): A @0 (32KB), B0 @32K, B1 @64K,
// commit-mbar ring @96K (4x8B), A-mbar @96K+32, tmem slot @96K+40.
#define SME_A 0
#define SME_B0 32768
#define SME_B1 65536
#define SME_MBAR 98304
#define SME_AMBAR 98336
#define SME_TSLOT 98344
#define CONV_SMEM_BYTES (1024 + 98304 + 128)

// ---------------------------------------------------------------------------
// Init / pack kernels
// ---------------------------------------------------------------------------
__global__ void conv_decode_kernel(int K, int Kpad, int KV, int KHW, int KW,
                                   int D, int H, int W) {
    int k = blockIdx.x * 256 + threadIdx.x;
    if (k >= Kpad) return;
    if (k < K) {
        int ci = k / KV; int tap = k - ci * KV;
        int kd = tap / KHW; int t2 = tap - kd * KHW;
        int kh = t2 / KW; int kw = t2 - kh * KW;
        g_dec[k] = make_int2(((ci * D + kd) * H + kh) * W + kw,
                             (kd << 20) | (kh << 10) | kw);
    } else {
        g_dec[k] = make_int2(0, 1023 << 20);
    }
}

__global__ void natt_table_kernel() {
    int nb = threadIdx.x;
    if (nb < 245) {
        int od = nb / 49; int r = nb - od * 49;
        int oh = r / 7;   int ow = r - oh * 7;
        g_ndelta[nb] = (od - 2) * 2048 + (oh - 3) * 64 + (ow - 3);
        g_npack[nb]  = (od << 16) | (oh << 8) | ow;
    }
}

__global__ void xpack_kernel(const float* __restrict__ x,
                             uint32_t* __restrict__ dst, int n4) {
    int i = blockIdx.x * 256 + threadIdx.x;
    if (i >= n4) return;
    float4 v = reinterpret_cast<const float4*>(x)[i];
    uint4 o;
    o.x = pack_hl(v.x); o.y = pack_hl(v.y);
    o.z = pack_hl(v.z); o.w = pack_hl(v.w);
    reinterpret_cast<uint4*>(dst)[i] = o;
}

// pack K third of qkv into bf16x2 plane [8192][256] u32
__global__ void kpack_kernel(const float* __restrict__ qkv,
                             uint32_t* __restrict__ kpl) {
    int i = blockIdx.x * 256 + threadIdx.x;     // over 8192*256
    int t = i >> 8, c2 = i & 255;
    float2 v = *reinterpret_cast<const float2*>(
        qkv + (size_t)t * 1536 + 512 + 2 * c2);
    __nv_bfloat162 b = __float22bfloat162_rn(v);
    kpl[i] = *reinterpret_cast<uint32_t*>(&b);
}

__global__ void wpack_kernel(const float* __restrict__ w, int K, int NC) {
    int kc = blockIdx.x, bm = blockIdx.y;
    int tid = threadIdx.x;
    int r = tid >> 1, half = tid & 1;
    const float* wrow = w + (size_t)(bm * 128 + r) * K;
    uint8_t* hi = g_wpk + (size_t)(bm * NC + kc) * 32768;
    uint8_t* lo = hi + 16384;
#pragma unroll
    for (int i = 0; i < 16; i++) {
        int kk = half * 32 + 2 * i;
        int k = kc * 64 + kk;
        float a0 = (k < K) ? wrow[k] : 0.f;
        float a1 = (k + 1 < K) ? wrow[k + 1] : 0.f;
        uint32_t p0 = pack_hl(a0), p1 = pack_hl(a1);
        uint32_t hp = __byte_perm(p0, p1, 0x7632);
        uint32_t lp = __byte_perm(p0, p1, 0x5410);
        uint32_t off = r * 128 + kk * 2;
        uint32_t sw = off ^ ((off >> 3) & 0x70);
        *reinterpret_cast<uint32_t*>(hi + sw) = hp;
        *reinterpret_cast<uint32_t*>(lo + sw) = lp;
    }
}

__global__ void wpackT_kernel(const float* __restrict__ w, uint8_t* dst,
                              int K, int NC, int J) {
    int kc = blockIdx.x, bm = blockIdx.y;
    int tid = threadIdx.x;
    int r = tid >> 1, half = tid & 1;
    int m = bm * 128 + r;
    uint8_t* hi = dst + (size_t)(bm * NC + kc) * 32768;
    uint8_t* lo = hi + 16384;
#pragma unroll
    for (int i = 0; i < 16; i++) {
        int kk = half * 32 + 2 * i;
        int k = kc * 64 + kk;
        float a0 = (k < K) ? w[(size_t)k * J + m] : 0.f;
        float a1 = (k + 1 < K) ? w[(size_t)(k + 1) * J + m] : 0.f;
        uint32_t p0 = pack_hl(a0), p1 = pack_hl(a1);
        uint32_t hp = __byte_perm(p0, p1, 0x7632);
        uint32_t lp = __byte_perm(p0, p1, 0x5410);
        uint32_t off = r * 128 + kk * 2;
        uint32_t sw = off ^ ((off >> 3) & 0x70);
        *reinterpret_cast<uint32_t*>(hi + sw) = hp;
        *reinterpret_cast<uint32_t*>(lo + sw) = lp;
    }
}

// ---------------------------------------------------------------------------
// Conv kernel: bulk-copied A, double-buffered B gather, TMEM 256, 2 CTA/SM.
// ---------------------------------------------------------------------------
struct ConvParams {
    const uint32_t* xpk;
    const float* wf;
    const float* bias;
    uint32_t* outpk;
    float* outf;
    int D, H, W;
    int Hout, Wout;
    int sd, sh, sw, pd, ph, pw;
    int K, NC;
    int outStrideC, outOffset;
    int gelu;
};

template <int BM>
__global__ __launch_bounds__(512, 2) void conv_mma_kernel(ConvParams p) {
    extern __shared__ char smem_raw[];
    char* smem_al = (char*)(((uintptr_t)smem_raw + 1023) & ~(uintptr_t)1023);

    const int tid = threadIdx.x;
    const int bn = blockIdx.x;
    const int mblk0 = blockIdx.y * BM;
    const int HWo = p.Hout * p.Wout;

#if HAS_TCGEN05
    const uint32_t sb = smem_u32(smem_al);
    const uint32_t mbar = sb + SME_MBAR;
    const uint32_t ambar = sb + SME_AMBAR;
    const uint32_t tmem_slot = sb + SME_TSLOT;
    const int wid = tid >> 5;
    const int lane = tid & 31;

    if (wid == 0) {
        TCGEN05_ALLOC(tmem_slot, 256);
        TCGEN05_RELINQ();
    }
    if (tid == 0) {
#pragma unroll
        for (int i = 0; i < 4; i++) MBARRIER_INIT(mbar + 8 * i, 1);
        MBARRIER_INIT(ambar, 1);
    }
    __syncthreads();
    uint32_t tmem;
    asm volatile("ld.shared.b32 %0, [%1];" : "=r"(tmem) : "r"(tmem_slot));

    const int r = tid >> 2;
    const int q = tid & 3;
    const int n = bn * 128 + r;
    const int od = n / HWo; int rr2 = n - od * HWo;
    const int oh = rr2 / p.Wout; const int ow = rr2 - oh * p.Wout;
    const int id0 = od * p.sd - p.pd;
    const int ih0 = oh * p.sh - p.ph;
    const int iw0 = ow * p.sw - p.pw;
    const int gbase = (id0 * p.H + ih0) * p.W + iw0;
    const int NC = p.NC;

    auto fillB = [&](int st, int kc) {
        char* Bhi = smem_al + (st ? SME_B1 : SME_B0);
        char* Blo = Bhi + 16384;
        const int kt = kc * 64;
#pragma unroll
        for (int i = 0; i < 8; i++) {
            int kk = q * 16 + 2 * i;
            int k = kt + kk;
            int4 dv = *reinterpret_cast<const int4*>(&g_dec[k]);
            uint32_t v0 = 0, v1 = 0;
            {
                int kd = dv.y >> 20, kh = (dv.y >> 10) & 1023, kw = dv.y & 1023;
                if ((unsigned)(id0 + kd) < (unsigned)p.D &&
                    (unsigned)(ih0 + kh) < (unsigned)p.H &&
                    (unsigned)(iw0 + kw) < (unsigned)p.W)
                    v0 = p.xpk[gbase + dv.x];
            }
            {
                int kd = dv.w >> 20, kh = (dv.w >> 10) & 1023, kw = dv.w & 1023;
                if ((unsigned)(id0 + kd) < (unsigned)p.D &&
                    (unsigned)(ih0 + kh) < (unsigned)p.H &&
                    (unsigned)(iw0 + kw) < (unsigned)p.W)
                    v1 = p.xpk[gbase + dv.z];
            }
            uint32_t off = r * 128 + kk * 2;
            uint32_t sw = off ^ ((off >> 3) & 0x70);
            *reinterpret_cast<uint32_t*>(Bhi + sw) = __byte_perm(v0, v1, 0x7632);
            *reinterpret_cast<uint32_t*>(Blo + sw) = __byte_perm(v0, v1, 0x5410);
        }
    };

    int wpar = 0;
    auto waitCommits = [&](int target) {
        while (wpar < target) {
            MBARRIER_WAIT_PARITY(mbar + 8 * (wpar & 3), (wpar >> 2) & 1);
            wpar++;
        }
    };

    fillB(0, 0);

    for (int kc = 0; kc < NC; kc++) {
        int st = kc & 1;
#pragma unroll
        for (int bm = 0; bm < BM; bm++) {
            int ni = kc * BM + bm;
            if (ni >= 1) waitCommits(ni);   // prev MMA batch done -> A free
            if (wid == 0 && elect_one()) {
                const uint8_t* asrc =
                    g_wpk + ((size_t)(mblk0 + bm) * NC + kc) * 32768;
                MBARRIER_EXPECT_TX(ambar, 32768);
                CP_BULK_G2S(sb + SME_A, asrc, 32768, ambar);
            }
            MBARRIER_WAIT_PARITY(ambar, ni & 1);
            FENCE_PROXY_ASYNC();
            __syncthreads();
            if (wid == 0 && elect_one()) {
                uint64_t dAh = make_desc(sb + SME_A);
                uint64_t dAl = dAh + (16384 >> 4);
                uint64_t dBh = make_desc(sb + (st ? SME_B1 : SME_B0));
                uint64_t dBl = dBh + (16384 >> 4);
                uint32_t d = tmem + bm * 128;
                uint32_t first = (kc == 0) ? 0u : 1u;
#pragma unroll
                for (int s = 0; s < 4; s++) {
                    uint64_t o = s * 2;
                    mma_f16_ss(d, dAh + o, dBh + o, CONV_IDESC, first); first = 1;
                    mma_f16_ss(d, dAh + o, dBl + o, CONV_IDESC, 1);
                    mma_f16_ss(d, dAl + o, dBh + o, CONV_IDESC, 1);
                }
                TCGEN05_COMMIT(mbar + 8 * (ni & 3));
            }
        }
        if (kc + 1 < NC) fillB(st ^ 1, kc + 1);
    }
    waitCommits(NC * BM);
    TCGEN05_FENCE_AFTER();

    // ---- smem-staged coalesced epilogue ----
    {
        float* stage = reinterpret_cast<float*>(smem_al);   // [128][129]
        const int sp = wid & 3;
        const int cb = wid >> 2;
#pragma unroll
        for (int bm = 0; bm < BM; bm++) {
            uint32_t dr[32];
            TCGEN05_LD_X32(dr, tmem + bm * 128 + cb * 32);
            TCGEN05_WAIT_LD();
            __syncthreads();
            int srow = sp * 32 + lane;
#pragma unroll
            for (int j = 0; j < 32; j++)
                stage[srow * 129 + cb * 32 + j] = __uint_as_float(dr[j]);
            __syncthreads();
#pragma unroll
            for (int rr = 0; rr < 8; rr++) {
                int ml = wid * 8 + rr;
                int m = (mblk0 + bm) * 128 + ml;
                float bv = p.bias[m];
                size_t obase = (size_t)m * p.outStrideC + p.outOffset + bn * 128;
#pragma unroll
                for (int part = 0; part < 4; part++) {
                    float v = stage[ml * 129 + part * 32 + lane] + bv;
                    if (p.gelu) v = gelu_tanh(v);
                    if (p.outpk) p.outpk[obase + part * 32 + lane] = pack_hl(v);
                    else p.outf[obase + part * 32 + lane] = v;
                }
            }
        }
        TCGEN05_FENCE_BEFORE();
    }
    __syncthreads();
    if (tid == 0) {
#pragma unroll
        for (int i = 0; i < 4; i++) MBARRIER_INVAL(mbar + 8 * i);
        MBARRIER_INVAL(ambar);
    }
    if (wid == 0) TCGEN05_DEALLOC(tmem, 256);

#else  // FFMA fallback (never executes on GB300)
    for (int bm = 0; bm < BM; bm++) {
        const int m_base = (mblk0 + bm) * 128;
        for (int idx = tid; idx < 128 * 128; idx += 512) {
            int ml = idx >> 7, nl = idx & 127;
            int m = m_base + ml;
            int nn = bn * 128 + nl;
            int od = nn / HWo; int rr2 = nn - od * HWo;
            int oh = rr2 / p.Wout; int ow = rr2 - oh * p.Wout;
            int id0 = od * p.sd - p.pd, ih0 = oh * p.sh - p.ph, iw0 = ow * p.sw - p.pw;
            int gb = (id0 * p.H + ih0) * p.W + iw0;
            float s = 0.f;
            for (int k = 0; k < p.K; k++) {
                int2 dv = g_dec[k];
                int kd = dv.y >> 20, kh = (dv.y >> 10) & 1023, kw = dv.y & 1023;
                if ((unsigned)(id0 + kd) < (unsigned)p.D &&
                    (unsigned)(ih0 + kh) < (unsigned)p.H &&
                    (unsigned)(iw0 + kw) < (unsigned)p.W)
                    s += p.wf[(size_t)m * p.K + k] * unpack_hl(p.xpk[gb + dv.x]);
            }
            s += p.bias[m];
            if (p.gelu) s = gelu_tanh(s);
            size_t ob = (size_t)m * p.outStrideC + p.outOffset + nn;
            if (p.outpk) p.outpk[ob] = pack_hl(s);
            else p.outf[ob] = s;
        }
    }
#endif
}

// ---------------------------------------------------------------------------
// Token GEMM: bulk-copied A, double-buffered B, staged mode-1 epilogue.
// ---------------------------------------------------------------------------
struct TokParams {
    const uint32_t* bpk;
    const uint8_t* wpk;
    const float* wf;
    const float* bias;
    float* out;
    int T, J, Kdim, NC, mode;
};

template <int BM>
__global__ __launch_bounds__(512, 2) void tok_mma_kernel(TokParams p) {
    extern __shared__ char smem_raw[];
    char* smem_al = (char*)(((uintptr_t)smem_raw + 1023) & ~(uintptr_t)1023);

    const int tid = threadIdx.x;
    const int bn = blockIdx.x;
    const int mblk0 = blockIdx.y * BM;

#if HAS_TCGEN05
    const uint32_t sb = smem_u32(smem_al);
    const uint32_t mbar = sb + SME_MBAR;
    const uint32_t ambar = sb + SME_AMBAR;
    const uint32_t tmem_slot = sb + SME_TSLOT;
    const int wid = tid >> 5;
    const int lane = tid & 31;

    if (wid == 0) {
        TCGEN05_ALLOC(tmem_slot, 256);
        TCGEN05_RELINQ();
    }
    if (tid == 0) {
#pragma unroll
        for (int i = 0; i < 4; i++) MBARRIER_INIT(mbar + 8 * i, 1);
        MBARRIER_INIT(ambar, 1);
    }
    __syncthreads();
    uint32_t tmem;
    asm volatile("ld.shared.b32 %0, [%1];" : "=r"(tmem) : "r"(tmem_slot));

    const int r = tid >> 2;
    const int q = tid & 3;
    const uint32_t* bsrc = p.bpk + (size_t)(bn * 128 + r) * p.Kdim;
    const int NC = p.NC;

    auto fillB = [&](int st, int kc) {
        char* Bhi = smem_al + (st ? SME_B1 : SME_B0);
        char* Blo = Bhi + 16384;
        const uint32_t* src = bsrc + kc * 64 + q * 16;
        uint32_t buf[16];
#pragma unroll
        for (int i = 0; i < 4; i++)
            *reinterpret_cast<uint4*>(&buf[i * 4]) =
                *reinterpret_cast<const uint4*>(src + i * 4);
#pragma unroll
        for (int i = 0; i < 8; i++) {
            int kk = q * 16 + 2 * i;
            uint32_t v0 = buf[2 * i], v1 = buf[2 * i + 1];
            uint32_t off = r * 128 + kk * 2;
            uint32_t sw = off ^ ((off >> 3) & 0x70);
            *reinterpret_cast<uint32_t*>(Bhi + sw) = __byte_perm(v0, v1, 0x7632);
            *reinterpret_cast<uint32_t*>(Blo + sw) = __byte_perm(v0, v1, 0x5410);
        }
    };

    int wpar = 0;
    auto waitCommits = [&](int target) {
        while (wpar < target) {
            MBARRIER_WAIT_PARITY(mbar + 8 * (wpar & 3), (wpar >> 2) & 1);
            wpar++;
        }
    };

    fillB(0, 0);

    for (int kc = 0; kc < NC; kc++) {
        int st = kc & 1;
#pragma unroll
        for (int bm = 0; bm < BM; bm++) {
            int ni = kc * BM + bm;
            if (ni >= 1) waitCommits(ni);
            if (wid == 0 && elect_one()) {
                const uint8_t* asrc =
                    p.wpk + ((size_t)(mblk0 + bm) * NC + kc) * 32768;
                MBARRIER_EXPECT_TX(ambar, 32768);
                CP_BULK_G2S(sb + SME_A, asrc, 32768, ambar);
            }
            MBARRIER_WAIT_PARITY(ambar, ni & 1);
            FENCE_PROXY_ASYNC();
            __syncthreads();
            if (wid == 0 && elect_one()) {
                uint64_t dAh = make_desc(sb + SME_A);
                uint64_t dAl = dAh + (16384 >> 4);
                uint64_t dBh = make_desc(sb + (st ? SME_B1 : SME_B0));
                uint64_t dBl = dBh + (16384 >> 4);
                uint32_t d = tmem + bm * 128;
                uint32_t first = (kc == 0) ? 0u : 1u;
#pragma unroll
                for (int s = 0; s < 4; s++) {
                    uint64_t o = s * 2;
                    mma_f16_ss(d, dAh + o, dBh + o, CONV_IDESC, first); first = 1;
                    mma_f16_ss(d, dAh + o, dBl + o, CONV_IDESC, 1);
                    mma_f16_ss(d, dAl + o, dBh + o, CONV_IDESC, 1);
                }
                TCGEN05_COMMIT(mbar + 8 * (ni & 3));
            }
        }
        if (kc + 1 < NC) fillB(st ^ 1, kc + 1);
    }
    waitCommits(NC * BM);
    TCGEN05_FENCE_AFTER();

    {
        const int sp = wid & 3;
        const int cb = wid >> 2;
        const int t0 = bn * 128 + cb * 32;
        if (p.mode == 0) {
#pragma unroll
            for (int bm = 0; bm < BM; bm++) {
                const int m = (mblk0 + bm) * 128 + sp * 32 + lane;
                const float bv = p.bias[m];
                uint32_t dr[32];
                TCGEN05_LD_X32(dr, tmem + bm * 128 + cb * 32);
                TCGEN05_WAIT_LD();
#pragma unroll
                for (int j = 0; j < 32; j++)
                    p.out[(size_t)(t0 + j) * p.J + m] = __uint_as_float(dr[j]) + bv;
            }
        } else {
            float* stage = reinterpret_cast<float*>(smem_al);   // [128][129]
#pragma unroll
            for (int bm = 0; bm < BM; bm++) {
                uint32_t dr[32];
                TCGEN05_LD_X32(dr, tmem + bm * 128 + cb * 32);
                TCGEN05_WAIT_LD();
                __syncthreads();
                int srow = sp * 32 + lane;
#pragma unroll
                for (int j = 0; j < 32; j++)
                    stage[srow * 129 + cb * 32 + j] = __uint_as_float(dr[j]);
                __syncthreads();
#pragma unroll
                for (int rr = 0; rr < 8; rr++) {
                    int ml = wid * 8 + rr;
                    int m = (mblk0 + bm) * 128 + ml;
                    float bv = p.bias[m];
                    float* orow = p.out + (size_t)m * p.T + bn * 128;
#pragma unroll
                    for (int part = 0; part < 4; part++) {
                        int col = part * 32 + lane;
                        orow[col] += stage[ml * 129 + col] + bv;
                    }
                }
            }
        }
        TCGEN05_FENCE_BEFORE();
    }
    __syncthreads();
    if (tid == 0) {
#pragma unroll
        for (int i = 0; i < 4; i++) MBARRIER_INVAL(mbar + 8 * i);
        MBARRIER_INVAL(ambar);
    }
    if (wid == 0) TCGEN05_DEALLOC(tmem, 256);

#else  // FFMA fallback
    for (int bm = 0; bm < BM; bm++) {
        int m_base = (mblk0 + bm) * 128;
        for (int idx = tid; idx < 128 * 128; idx += 512) {
            int tl = idx >> 7, jl = idx & 127;
            int t = bn * 128 + tl, j = m_base + jl;
            float s = 0.f;
            for (int k = 0; k < p.Kdim; k++)
                s += unpack_hl(p.bpk[(size_t)t * p.Kdim + k]) * p.wf[(size_t)k * p.J + j];
            s += p.bias[j];
            if (p.mode == 0) p.out[(size_t)t * p.J + j] = s;
            else p.out[(size_t)j * p.T + t] += s;
        }
    }
#endif
}

// ---------------------------------------------------------------------------
// LayerNorm: fp32 channel-major -> packed token-major
// ---------------------------------------------------------------------------
__global__ __launch_bounds__(256) void layernorm_kernel(
    const float* __restrict__ x, const float* __restrict__ g,
    const float* __restrict__ b, uint32_t* __restrict__ ypk, int T) {
    const int tx = threadIdx.x;
    const int ty = threadIdx.y;
    const int t = blockIdx.x * 32 + tx;

    float s = 0.f, ss = 0.f;
#pragma unroll
    for (int i = 0; i < 64; i++) {
        int c = ty * 64 + i;
        float v = x[(size_t)c * T + t];
        s += v; ss += v * v;
    }
    __shared__ float shs[8][32], shss[8][32];
    __shared__ float smu[32], srs[32];
    shs[ty][tx] = s; shss[ty][tx] = ss;
    __syncthreads();
    if (ty == 0) {
        float S = 0.f, SS = 0.f;
#pragma unroll
        for (int j = 0; j < 8; j++) { S += shs[j][tx]; SS += shss[j][tx]; }
        float mu = S * (1.f / 512.f);
        float var = SS * (1.f / 512.f) - mu * mu;
        smu[tx] = mu;
        srs[tx] = rsqrtf(var + 1e-5f);
    }
    __syncthreads();
    float mu = smu[tx], rs = srs[tx];
    uint32_t* yrow = ypk + (size_t)t * 512 + ty * 64;
#pragma unroll
    for (int i = 0; i < 64; i++) {
        int c = ty * 64 + i;
        float v = x[(size_t)c * T + t];
        yrow[i] = pack_hl((v - mu) * rs * g[c] + b[c]);
    }
}

// ---------------------------------------------------------------------------
// Neighborhood attention — bf16 K-plane score phase, fp32 V PV phase.
// ---------------------------------------------------------------------------
__global__ __launch_bounds__(256) void natt_kernel(
    const float* __restrict__ qkv, uint32_t* __restrict__ atpk) {
    __shared__ float psh[8][248];
    __shared__ float tsh[8][32][33];

    const int warp = threadIdx.x >> 5;
    const int lane = threadIdx.x & 31;
    const int t = blockIdx.x * 8 + warp;
    const int head = threadIdx.y + 0;   // unused pattern guard
    const int hd = blockIdx.y;
    const int d = t >> 11;
    const int hh = (t >> 6) & 31;
    const int ww = t & 63;
    (void)head;

    float2 q2 = *reinterpret_cast<const float2*>(
        qkv + (size_t)t * 1536 + hd * 64 + 2 * lane);
    q2.x *= 0.125f; q2.y *= 0.125f;

    float sc[8];
    float m = -1e30f;
#pragma unroll
    for (int it = 0; it < 8; it++) {
#pragma unroll
        for (int j = 0; j < 32; j++) {
            int nb = it * 32 + j;
            float pv = 0.f;
            if (nb < 245) {
                int pk = g_npack[nb];
                int nd = d + (pk >> 16) - 2;
                int nh = hh + ((pk >> 8) & 255) - 3;
                int nw = ww + (pk & 255) - 3;
                if ((unsigned)nd < 4u && (unsigned)nh < 32u && (unsigned)nw < 64u) {
                    int nt = (nd * 32 + nh) * 64 + nw;
                    uint32_t kw32 = g_kpl[(size_t)nt * 256 + hd * 32 + lane];
                    float2 kf = __bfloat1622float2(
                        *reinterpret_cast<__nv_bfloat162*>(&kw32));
                    pv = fmaf(q2.x, kf.x, q2.y * kf.y);
                }
            }
            tsh[warp][j][lane] = pv;
        }
        __syncwarp();
        float s = 0.f;
#pragma unroll
        for (int j = 0; j < 32; j++) s += tsh[warp][lane][j];
        __syncwarp();

        int nb = it * 32 + lane;
        float dot = -1e30f;
        if (nb < 245) {
            int pk = g_npack[nb];
            int nd = d + (pk >> 16) - 2;
            int nh = hh + ((pk >> 8) & 255) - 3;
            int nw = ww + (pk & 255) - 3;
            if ((unsigned)nd < 4u && (unsigned)nh < 32u && (unsigned)nw < 64u)
                dot = s;
        }
        sc[it] = dot;
        m = fmaxf(m, dot);
    }
#pragma unroll
    for (int o = 16; o; o >>= 1) m = fmaxf(m, __shfl_xor_sync(0xffffffffu, m, o));

    float l = 0.f;
#pragma unroll
    for (int it = 0; it < 8; it++) {
        int nb = it * 32 + lane;
        float e = (sc[it] > -1e29f) ? __expf(sc[it] - m) : 0.f;
        if (nb < 248) psh[warp][nb] = e;
        l += e;
    }
#pragma unroll
    for (int o = 16; o; o >>= 1) l += __shfl_xor_sync(0xffffffffu, l, o);
    __syncwarp();

    float acc0 = 0.f, acc1 = 0.f;
    for (int nb = 0; nb < 245; nb++) {
        float pb = psh[warp][nb];
        if (pb > 0.f) {
            int nt = t + g_ndelta[nb];
            const float* vp = qkv + (size_t)nt * 1536 + 1024 + hd * 64;
            acc0 = fmaf(pb, vp[lane], acc0);
            acc1 = fmaf(pb, vp[lane + 32], acc1);
        }
    }
    float inv = 1.f / l;
    uint32_t* op = atpk + (size_t)t * 512 + hd * 64;
    op[lane] = pack_hl(acc0 * inv);
    op[lane + 32] = pack_hl(acc1 * inv);
}

// ---------------------------------------------------------------------------
// Host launcher
// ---------------------------------------------------------------------------
extern "C" void kernel_launch(void* const* d_in, const int* in_sizes, int n_in,
                              void* d_out, int out_size) {
    const float* x2d  = (const float*)d_in[0];
    const float* x3d  = (const float*)d_in[1];
    const float* sw0  = (const float*)d_in[2];  const float* sb0 = (const float*)d_in[3];
    const float* sw1  = (const float*)d_in[4];  const float* sb1 = (const float*)d_in[5];
    const float* sw2  = (const float*)d_in[6];  const float* sb2 = (const float*)d_in[7];
    const float* pw0  = (const float*)d_in[8];  const float* pb0 = (const float*)d_in[9];
    const float* pw1  = (const float*)d_in[10]; const float* pb1 = (const float*)d_in[11];
    const float* pw2  = (const float*)d_in[12]; const float* pb2 = (const float*)d_in[13];
    const float* latw = (const float*)d_in[14]; const float* latb = (const float*)d_in[15];
    const float* lng  = (const float*)d_in[16]; const float* lnb  = (const float*)d_in[17];
    const float* qkvw = (const float*)d_in[18]; const float* qkvb = (const float*)d_in[19];
    const float* pjw  = (const float*)d_in[20]; const float* pjb  = (const float*)d_in[21];
    float* lat = (float*)d_out;

    uint32_t *pkA, *pkB, *pkF, *pkX, *ynpk, *atpk, *kpl;
    float *qkvB;
    uint8_t *wpk2;
    cudaGetSymbolAddress((void**)&pkA, g_pk_a);
    cudaGetSymbolAddress((void**)&pkB, g_pk_b);
    cudaGetSymbolAddress((void**)&pkF, g_pk_f);
    cudaGetSymbolAddress((void**)&pkX, g_pk_x2d);
    cudaGetSymbolAddress((void**)&ynpk, g_ynpk);
    cudaGetSymbolAddress((void**)&qkvB, g_qkv);
    cudaGetSymbolAddress((void**)&atpk, g_atpk);
    cudaGetSymbolAddress((void**)&kpl, g_kpl);
    cudaGetSymbolAddress((void**)&wpk2, g_wpk2);

    cudaFuncSetAttribute(conv_mma_kernel<1>,
                         cudaFuncAttributeMaxDynamicSharedMemorySize, CONV_SMEM_BYTES);
    cudaFuncSetAttribute(conv_mma_kernel<2>,
                         cudaFuncAttributeMaxDynamicSharedMemorySize, CONV_SMEM_BYTES);
    cudaFuncSetAttribute(tok_mma_kernel<1>,
                         cudaFuncAttributeMaxDynamicSharedMemorySize, CONV_SMEM_BYTES);
    cudaFuncSetAttribute(tok_mma_kernel<2>,
                         cudaFuncAttributeMaxDynamicSharedMemorySize, CONV_SMEM_BYTES);

    auto run_conv = [&](const uint32_t* xpk, const float* wf, const float* bias,
                        uint32_t* outpk, float* outf,
                        int Cin, int D, int H, int W, int Dout, int Hout, int Wout,
                        int KD, int KH, int KW, int sd, int sh, int sw,
                        int pd, int ph, int pw, int Cout,
                        int outStrideC, int outOffset, int gelu) {
        int K = Cin * KD * KH * KW;
        int NC = (K + 63) / 64;
        int Kp = NC * 64;
        conv_decode_kernel<<<(Kp + 255) / 256, 256>>>(K, Kp, KD * KH * KW, KH * KW,
                                                      KW, D, H, W);
        wpack_kernel<<<dim3(NC, Cout / 128), 256>>>(wf, K, NC);
        int Nvox = Dout * Hout * Wout;
        ConvParams p{ xpk, wf, bias, outpk, outf,
                      D, H, W, Hout, Wout, sd, sh, sw, pd, ph, pw,
                      K, NC, outStrideC, outOffset, gelu };
        int nblk = Cout / 128;
        int bn = Nvox / 128;
        if (nblk % 2 == 0 && bn * (nblk / 2) >= 256)
            conv_mma_kernel<2><<<dim3(bn, nblk / 2), 512, CONV_SMEM_BYTES>>>(p);
        else
            conv_mma_kernel<1><<<dim3(bn, nblk), 512, CONV_SMEM_BYTES>>>(p);
    };

    natt_table_kernel<<<1, 256>>>();
    xpack_kernel<<<(5 * 24 * 256 * 512 / 4 + 255) / 256, 256>>>(
        x3d, pkA, 5 * 24 * 256 * 512 / 4);
    xpack_kernel<<<(8 * 256 * 512 / 4 + 255) / 256, 256>>>(
        x2d, pkX, 8 * 256 * 512 / 4);

    // ---- 3D tower ----
    run_conv(pkA, pw0, pb0, pkB, nullptr, 5, 24, 256, 512, 12, 128, 256,
             3, 3, 3, 2, 2, 2, 1, 1, 1, 128, 393216, 0, 1);
    run_conv(pkB, pw1, pb1, pkA, nullptr, 128, 12, 128, 256, 6, 64, 128,
             3, 3, 3, 2, 2, 2, 1, 1, 1, 256, 49152, 0, 1);
    run_conv(pkA, pw2, pb2, pkF, nullptr, 256, 6, 64, 128, 3, 32, 64,
             3, 3, 3, 2, 2, 2, 1, 1, 1, 512, 8192, 0, 1);

    // ---- 2D tower ----
    run_conv(pkX, sw0, sb0, pkB, nullptr, 8, 1, 256, 512, 1, 128, 256,
             1, 3, 3, 1, 2, 2, 0, 1, 1, 128, 32768, 0, 1);
    run_conv(pkB, sw1, sb1, pkA, nullptr, 128, 1, 128, 256, 1, 64, 128,
             1, 3, 3, 1, 2, 2, 0, 1, 1, 256, 8192, 0, 1);
    run_conv(pkA, sw2, sb2, pkF, nullptr, 256, 1, 64, 128, 1, 32, 64,
             1, 3, 3, 1, 2, 2, 0, 1, 1, 512, 8192, 3 * 2048, 1);

    // ---- lateral 1x1x1 -> d_out fp32 ----
    run_conv(pkF, latw, latb, nullptr, lat, 512, 4, 32, 64, 4, 32, 64,
             1, 1, 1, 1, 1, 1, 0, 0, 0, 512, 8192, 0, 0);

    // ---- attention weight prepack ----
    const size_t QKV_PK = 8 * 12 * 32768;
    const size_t PRJ_PK = 8 * 4 * 32768;
    for (int i = 0; i < 3; i++) {
        wpackT_kernel<<<dim3(8, 12), 256>>>(qkvw + (size_t)i * 512 * 1536,
                                            wpk2 + i * QKV_PK, 512, 8, 1536);
        wpackT_kernel<<<dim3(8, 4), 256>>>(pjw + (size_t)i * 512 * 512,
                                           wpk2 + 3 * QKV_PK + i * PRJ_PK, 512, 8, 512);
    }

    // ---- 3 neighborhood-attention blocks ----
    for (int i = 0; i < 3; i++) {
        layernorm_kernel<<<8192 / 32, dim3(32, 8)>>>(lat, lng + i * 512, lnb + i * 512,
                                                     ynpk, 8192);
        TokParams pq{ ynpk, wpk2 + i * QKV_PK, qkvw + (size_t)i * 512 * 1536,
                      qkvb + i * 1536, qkvB, 8192, 1536, 512, 8, 0 };
        tok_mma_kernel<2><<<dim3(8192 / 128, 6), 512, CONV_SMEM_BYTES>>>(pq);
        kpack_kernel<<<8192, 256>>>(qkvB, kpl);
        natt_kernel<<<dim3(1024, 8), 256>>>(qkvB, atpk);
        TokParams pp{ atpk, wpk2 + 3 * QKV_PK + i * PRJ_PK,
                      pjw + (size_t)i * 512 * 512,
                      pjb + i * 512, lat, 8192, 512, 512, 8, 1 };
        tok_mma_kernel<1><<<dim3(8192 / 128, 4), 512, CONV_SMEM_BYTES>>>(pp);
    }
}

// round 14
// speedup vs baseline: 1.6139x; 1.0104x over previous
#include <cuda_runtime.h>
#include <cuda_bf16.h>
#include <math.h>
#include <cstdint>

#if defined(__CUDA_ARCH_SPECIFIC__) || defined(__CUDA_ARCH_FEAT_SM103_ALL)
#define HAS_TCGEN05 1
#else
#define HAS_TCGEN05 0
#endif

// ---------------------------------------------------------------------------
// Scratch buffers (packed u32 = bf16 hi << 16 | bf16 lo)
// ---------------------------------------------------------------------------
__device__ uint32_t g_pk_a[15728640];
__device__ uint32_t g_pk_b[50331648];
__device__ uint32_t g_pk_f[4194304];
__device__ uint32_t g_pk_x2d[1048576];
__device__ uint8_t  g_wpk[14155776];
__device__ uint8_t  g_wpk2[12582912];
__device__ uint32_t g_ynpk[8192 * 512];
__device__ float    g_qkv[8192 * 1536];
__device__ uint32_t g_kpl[8192 * 256];   // K-plane bf16x2 for natt score
__device__ uint32_t g_atpk[8192 * 512];
__device__ int2     g_dec[8192];
__device__ int      g_ndelta[256];
__device__ int      g_npack[256];

// ---------------------------------------------------------------------------
// Common helpers
// ---------------------------------------------------------------------------
__device__ __forceinline__ uint32_t smem_u32(const void* p) {
    uint32_t a;
    asm("{ .reg .u64 t; cvta.to.shared.u64 t, %1; cvt.u32.u64 %0, t; }"
        : "=r"(a) : "l"(p));
    return a;
}
__device__ __forceinline__ float gelu_tanh(float x) {
    float x3 = x * x * x;
    float t = tanhf(0.7978845608028654f * (x + 0.044715f * x3));
    return 0.5f * x * (1.0f + t);
}
__device__ __forceinline__ uint32_t pack_hl(float f) {
    __nv_bfloat16 h = __float2bfloat16(f);
    __nv_bfloat16 l = __float2bfloat16(f - __bfloat162float(h));
    return ((uint32_t)__bfloat16_as_ushort(h) << 16) | __bfloat16_as_ushort(l);
}
__device__ __forceinline__ float unpack_hl(uint32_t v) {
    float h = __bfloat162float(__ushort_as_bfloat16((unsigned short)(v >> 16)));
    float l = __bfloat162float(__ushort_as_bfloat16((unsigned short)(v & 0xFFFF)));
    return h + l;
}

#if HAS_TCGEN05
__device__ __forceinline__ uint32_t elect_one() {
    uint32_t pred;
    asm volatile("{ .reg .pred p; elect.sync _|p, 0xFFFFFFFF; selp.b32 %0, 1, 0, p; }"
                 : "=r"(pred));
    return pred;
}
#define TCGEN05_ALLOC(a, n) \
    asm volatile("tcgen05.alloc.cta_group::1.sync.aligned.shared::cta.b32 [%0], %1;" \
                 :: "r"((uint32_t)(a)), "r"((uint32_t)(n)) : "memory")
#define TCGEN05_DEALLOC(t, n) \
    asm volatile("tcgen05.dealloc.cta_group::1.sync.aligned.b32 %0, %1;" :: "r"(t), "r"(n))
#define TCGEN05_RELINQ() \
    asm volatile("tcgen05.relinquish_alloc_permit.cta_group::1.sync.aligned;")
#define TCGEN05_COMMIT(m) \
    asm volatile("tcgen05.commit.cta_group::1.mbarrier::arrive::one.shared::cluster.b64 [%0];" \
                 :: "r"((uint32_t)(m)) : "memory")
#define TCGEN05_FENCE_AFTER() \
    asm volatile("tcgen05.fence::after_thread_sync;" ::: "memory")
#define TCGEN05_FENCE_BEFORE() \
    asm volatile("tcgen05.fence::before_thread_sync;" ::: "memory")
#define TCGEN05_WAIT_LD() asm volatile("tcgen05.wait::ld.sync.aligned;" ::: "memory")
#define FENCE_PROXY_ASYNC() asm volatile("fence.proxy.async.shared::cta;" ::: "memory")
#define MBARRIER_INIT(m, c) \
    asm volatile("mbarrier.init.shared.b64 [%0], %1;" :: "r"((uint32_t)(m)), "r"((uint32_t)(c)) : "memory")
#define MBARRIER_INVAL(m) \
    asm volatile("mbarrier.inval.shared.b64 [%0];" :: "r"((uint32_t)(m)) : "memory")
#define MBARRIER_EXPECT_TX(m, b) \
    asm volatile("mbarrier.arrive.expect_tx.shared.b64 _, [%0], %1;" \
                 :: "r"((uint32_t)(m)), "r"((uint32_t)(b)) : "memory")
#define CP_BULK_G2S(dst, src, nbytes, mbar) \
    asm volatile("cp.async.bulk.shared::cta.global.mbarrier::complete_tx::bytes [%0], [%1], %2, [%3];" \
                 :: "r"((uint32_t)(dst)), "l"(src), "r"((uint32_t)(nbytes)), \
                    "r"((uint32_t)(mbar)) : "memory")
#define MBARRIER_WAIT_PARITY(m, ph) do {                                           \
    uint32_t _m = (uint32_t)(m), _p = (uint32_t)(ph), _d;                          \
    asm volatile("{ .reg .pred p; mbarrier.try_wait.parity.acquire.cta.shared::cta.b64 p, [%1], %2;" \
                 " selp.b32 %0, 1, 0, p; }" : "=r"(_d) : "r"(_m), "r"(_p) : "memory"); \
    if (!_d) {                                                                     \
        asm volatile("{ .reg .pred P1; WL_%=: mbarrier.try_wait.parity.acquire.cta.shared::cta.b64 P1, [%0], %1, 0x989680;" \
                     " @P1 bra.uni WD_%=; bra.uni WL_%=; WD_%=: }"                 \
                     :: "r"(_m), "r"(_p) : "memory");                              \
    }                                                                              \
} while (0)
#define TCGEN05_LD_X32(r, a)                                                       \
    asm volatile("tcgen05.ld.sync.aligned.32x32b.x32.b32 "                         \
        "{%0, %1, %2, %3, %4, %5, %6, %7, %8, %9, %10, %11, %12, %13, %14, %15, "  \
        " %16, %17, %18, %19, %20, %21, %22, %23, %24, %25, %26, %27, %28, %29, %30, %31}, [%32];" \
        : "=r"((r)[0]), "=r"((r)[1]), "=r"((r)[2]), "=r"((r)[3]),                  \
          "=r"((r)[4]), "=r"((r)[5]), "=r"((r)[6]), "=r"((r)[7]),                  \
          "=r"((r)[8]), "=r"((r)[9]), "=r"((r)[10]), "=r"((r)[11]),                \
          "=r"((r)[12]), "=r"((r)[13]), "=r"((r)[14]), "=r"((r)[15]),              \
          "=r"((r)[16]), "=r"((r)[17]), "=r"((r)[18]), "=r"((r)[19]),              \
          "=r"((r)[20]), "=r"((r)[21]), "=r"((r)[22]), "=r"((r)[23]),              \
          "=r"((r)[24]), "=r"((r)[25]), "=r"((r)[26]), "=r"((r)[27]),              \
          "=r"((r)[28]), "=r"((r)[29]), "=r"((r)[30]), "=r"((r)[31])               \
        : "r"(a))

static constexpr uint64_t SMEM_DESC_BASE_SW128 =
    (uint64_t(2) << 61) | (uint64_t(1) << 46) | (uint64_t(64) << 32) | (uint64_t(1) << 16);
__device__ __forceinline__ uint64_t make_desc(uint32_t addr) {
    return SMEM_DESC_BASE_SW128 | ((uint64_t)(addr >> 4) & 0x3FFF);
}
__device__ __forceinline__ void mma_f16_ss(uint32_t d, uint64_t ad, uint64_t bd,
                                           uint32_t idesc, uint32_t en) {
    asm volatile(
        "{ .reg .pred p; setp.ne.u32 p, %5, 0;\n\t"
        "tcgen05.mma.cta_group::1.kind::f16 [%0], %1, %2, %3, {%4, %4, %4, %4}, p; }"
        :: "r"(d), "l"(ad), "l"(bd), "r"(idesc), "r"(0u), "r"(en) : "memory");
}
static constexpr uint32_t CONV_IDESC =
    (1u << 4) | (1u << 7) | (1u << 10) | ((128u / 8) << 17) | ((128u / 16) << 24);
#endif // HAS_TCGEN05

#define SME_A 0
#define SME_B0 32768
#define SME_B1 65536
#define SME_MBAR 98304
#define SME_AMBAR 98336
#define SME_TSLOT 98344
#define CONV_SMEM_BYTES (1024 + 98304 + 128)

// ---------------------------------------------------------------------------
// Init / pack kernels
// ---------------------------------------------------------------------------
__global__ void conv_decode_kernel(int K, int Kpad, int KV, int KHW, int KW,
                                   int D, int H, int W) {
    int k = blockIdx.x * 256 + threadIdx.x;
    if (k >= Kpad) return;
    if (k < K) {
        int ci = k / KV; int tap = k - ci * KV;
        int kd = tap / KHW; int t2 = tap - kd * KHW;
        int kh = t2 / KW; int kw = t2 - kh * KW;
        g_dec[k] = make_int2(((ci * D + kd) * H + kh) * W + kw,
                             (kd << 20) | (kh << 10) | kw);
    } else {
        g_dec[k] = make_int2(0, 1023 << 20);
    }
}

__global__ void natt_table_kernel() {
    int nb = threadIdx.x;
    if (nb < 245) {
        int od = nb / 49; int r = nb - od * 49;
        int oh = r / 7;   int ow = r - oh * 7;
        g_ndelta[nb] = (od - 2) * 2048 + (oh - 3) * 64 + (ow - 3);
        g_npack[nb]  = (od << 16) | (oh << 8) | ow;
    }
}

__global__ void xpack_kernel(const float* __restrict__ x,
                             uint32_t* __restrict__ dst, int n4) {
    int i = blockIdx.x * 256 + threadIdx.x;
    if (i >= n4) return;
    float4 v = reinterpret_cast<const float4*>(x)[i];
    uint4 o;
    o.x = pack_hl(v.x); o.y = pack_hl(v.y);
    o.z = pack_hl(v.z); o.w = pack_hl(v.w);
    reinterpret_cast<uint4*>(dst)[i] = o;
}

__global__ void wpack_kernel(const float* __restrict__ w, int K, int NC) {
    int kc = blockIdx.x, bm = blockIdx.y;
    int tid = threadIdx.x;
    int r = tid >> 1, half = tid & 1;
    const float* wrow = w + (size_t)(bm * 128 + r) * K;
    uint8_t* hi = g_wpk + (size_t)(bm * NC + kc) * 32768;
    uint8_t* lo = hi + 16384;
#pragma unroll
    for (int i = 0; i < 16; i++) {
        int kk = half * 32 + 2 * i;
        int k = kc * 64 + kk;
        float a0 = (k < K) ? wrow[k] : 0.f;
        float a1 = (k + 1 < K) ? wrow[k + 1] : 0.f;
        uint32_t p0 = pack_hl(a0), p1 = pack_hl(a1);
        uint32_t hp = __byte_perm(p0, p1, 0x7632);
        uint32_t lp = __byte_perm(p0, p1, 0x5410);
        uint32_t off = r * 128 + kk * 2;
        uint32_t sw = off ^ ((off >> 3) & 0x70);
        *reinterpret_cast<uint32_t*>(hi + sw) = hp;
        *reinterpret_cast<uint32_t*>(lo + sw) = lp;
    }
}

__global__ void wpackT_kernel(const float* __restrict__ w, uint8_t* dst,
                              int K, int NC, int J) {
    int kc = blockIdx.x, bm = blockIdx.y;
    int tid = threadIdx.x;
    int r = tid >> 1, half = tid & 1;
    int m = bm * 128 + r;
    uint8_t* hi = dst + (size_t)(bm * NC + kc) * 32768;
    uint8_t* lo = hi + 16384;
#pragma unroll
    for (int i = 0; i < 16; i++) {
        int kk = half * 32 + 2 * i;
        int k = kc * 64 + kk;
        float a0 = (k < K) ? w[(size_t)k * J + m] : 0.f;
        float a1 = (k + 1 < K) ? w[(size_t)(k + 1) * J + m] : 0.f;
        uint32_t p0 = pack_hl(a0), p1 = pack_hl(a1);
        uint32_t hp = __byte_perm(p0, p1, 0x7632);
        uint32_t lp = __byte_perm(p0, p1, 0x5410);
        uint32_t off = r * 128 + kk * 2;
        uint32_t sw = off ^ ((off >> 3) & 0x70);
        *reinterpret_cast<uint32_t*>(hi + sw) = hp;
        *reinterpret_cast<uint32_t*>(lo + sw) = lp;
    }
}

// ---------------------------------------------------------------------------
// Conv kernel: bulk-copied A, double-buffered B gather, TMEM 256, 2 CTA/SM.
// ---------------------------------------------------------------------------
struct ConvParams {
    const uint32_t* xpk;
    const float* wf;
    const float* bias;
    uint32_t* outpk;
    float* outf;
    int D, H, W;
    int Hout, Wout;
    int sd, sh, sw, pd, ph, pw;
    int K, NC;
    int outStrideC, outOffset;
    int gelu;
};

template <int BM>
__global__ __launch_bounds__(512, 2) void conv_mma_kernel(ConvParams p) {
    extern __shared__ char smem_raw[];
    char* smem_al = (char*)(((uintptr_t)smem_raw + 1023) & ~(uintptr_t)1023);

    const int tid = threadIdx.x;
    const int bn = blockIdx.x;
    const int mblk0 = blockIdx.y * BM;
    const int HWo = p.Hout * p.Wout;

#if HAS_TCGEN05
    const uint32_t sb = smem_u32(smem_al);
    const uint32_t mbar = sb + SME_MBAR;
    const uint32_t ambar = sb + SME_AMBAR;
    const uint32_t tmem_slot = sb + SME_TSLOT;
    const int wid = tid >> 5;
    const int lane = tid & 31;

    if (wid == 0) {
        TCGEN05_ALLOC(tmem_slot, 256);
        TCGEN05_RELINQ();
    }
    if (tid == 0) {
#pragma unroll
        for (int i = 0; i < 4; i++) MBARRIER_INIT(mbar + 8 * i, 1);
        MBARRIER_INIT(ambar, 1);
    }
    __syncthreads();
    uint32_t tmem;
    asm volatile("ld.shared.b32 %0, [%1];" : "=r"(tmem) : "r"(tmem_slot));

    const int r = tid >> 2;
    const int q = tid & 3;
    const int n = bn * 128 + r;
    const int od = n / HWo; int rr2 = n - od * HWo;
    const int oh = rr2 / p.Wout; const int ow = rr2 - oh * p.Wout;
    const int id0 = od * p.sd - p.pd;
    const int ih0 = oh * p.sh - p.ph;
    const int iw0 = ow * p.sw - p.pw;
    const int gbase = (id0 * p.H + ih0) * p.W + iw0;
    const int NC = p.NC;

    auto fillB = [&](int st, int kc) {
        char* Bhi = smem_al + (st ? SME_B1 : SME_B0);
        char* Blo = Bhi + 16384;
        const int kt = kc * 64;
#pragma unroll
        for (int i = 0; i < 8; i++) {
            int kk = q * 16 + 2 * i;
            int k = kt + kk;
            int4 dv = *reinterpret_cast<const int4*>(&g_dec[k]);
            uint32_t v0 = 0, v1 = 0;
            {
                int kd = dv.y >> 20, kh = (dv.y >> 10) & 1023, kw = dv.y & 1023;
                if ((unsigned)(id0 + kd) < (unsigned)p.D &&
                    (unsigned)(ih0 + kh) < (unsigned)p.H &&
                    (unsigned)(iw0 + kw) < (unsigned)p.W)
                    v0 = p.xpk[gbase + dv.x];
            }
            {
                int kd = dv.w >> 20, kh = (dv.w >> 10) & 1023, kw = dv.w & 1023;
                if ((unsigned)(id0 + kd) < (unsigned)p.D &&
                    (unsigned)(ih0 + kh) < (unsigned)p.H &&
                    (unsigned)(iw0 + kw) < (unsigned)p.W)
                    v1 = p.xpk[gbase + dv.z];
            }
            uint32_t off = r * 128 + kk * 2;
            uint32_t sw = off ^ ((off >> 3) & 0x70);
            *reinterpret_cast<uint32_t*>(Bhi + sw) = __byte_perm(v0, v1, 0x7632);
            *reinterpret_cast<uint32_t*>(Blo + sw) = __byte_perm(v0, v1, 0x5410);
        }
    };

    int wpar = 0;
    auto waitCommits = [&](int target) {
        while (wpar < target) {
            MBARRIER_WAIT_PARITY(mbar + 8 * (wpar & 3), (wpar >> 2) & 1);
            wpar++;
        }
    };

    fillB(0, 0);

    for (int kc = 0; kc < NC; kc++) {
        int st = kc & 1;
#pragma unroll
        for (int bm = 0; bm < BM; bm++) {
            int ni = kc * BM + bm;
            if (ni >= 1) waitCommits(ni);
            if (wid == 0 && elect_one()) {
                const uint8_t* asrc =
                    g_wpk + ((size_t)(mblk0 + bm) * NC + kc) * 32768;
                MBARRIER_EXPECT_TX(ambar, 32768);
                CP_BULK_G2S(sb + SME_A, asrc, 32768, ambar);
            }
            MBARRIER_WAIT_PARITY(ambar, ni & 1);
            FENCE_PROXY_ASYNC();
            __syncthreads();
            if (wid == 0 && elect_one()) {
                uint64_t dAh = make_desc(sb + SME_A);
                uint64_t dAl = dAh + (16384 >> 4);
                uint64_t dBh = make_desc(sb + (st ? SME_B1 : SME_B0));
                uint64_t dBl = dBh + (16384 >> 4);
                uint32_t d = tmem + bm * 128;
                uint32_t first = (kc == 0) ? 0u : 1u;
#pragma unroll
                for (int s = 0; s < 4; s++) {
                    uint64_t o = s * 2;
                    mma_f16_ss(d, dAh + o, dBh + o, CONV_IDESC, first); first = 1;
                    mma_f16_ss(d, dAh + o, dBl + o, CONV_IDESC, 1);
                    mma_f16_ss(d, dAl + o, dBh + o, CONV_IDESC, 1);
                }
                TCGEN05_COMMIT(mbar + 8 * (ni & 3));
            }
        }
        if (kc + 1 < NC) fillB(st ^ 1, kc + 1);
    }
    waitCommits(NC * BM);
    TCGEN05_FENCE_AFTER();

    // ---- smem-staged coalesced epilogue ----
    {
        float* stage = reinterpret_cast<float*>(smem_al);   // [128][129]
        const int sp = wid & 3;
        const int cb = wid >> 2;
#pragma unroll
        for (int bm = 0; bm < BM; bm++) {
            uint32_t dr[32];
            TCGEN05_LD_X32(dr, tmem + bm * 128 + cb * 32);
            TCGEN05_WAIT_LD();
            __syncthreads();
            int srow = sp * 32 + lane;
#pragma unroll
            for (int j = 0; j < 32; j++)
                stage[srow * 129 + cb * 32 + j] = __uint_as_float(dr[j]);
            __syncthreads();
#pragma unroll
            for (int rr = 0; rr < 8; rr++) {
                int ml = wid * 8 + rr;
                int m = (mblk0 + bm) * 128 + ml;
                float bv = p.bias[m];
                size_t obase = (size_t)m * p.outStrideC + p.outOffset + bn * 128;
#pragma unroll
                for (int part = 0; part < 4; part++) {
                    float v = stage[ml * 129 + part * 32 + lane] + bv;
                    if (p.gelu) v = gelu_tanh(v);
                    if (p.outpk) p.outpk[obase + part * 32 + lane] = pack_hl(v);
                    else p.outf[obase + part * 32 + lane] = v;
                }
            }
        }
        TCGEN05_FENCE_BEFORE();
    }
    __syncthreads();
    if (tid == 0) {
#pragma unroll
        for (int i = 0; i < 4; i++) MBARRIER_INVAL(mbar + 8 * i);
        MBARRIER_INVAL(ambar);
    }
    if (wid == 0) TCGEN05_DEALLOC(tmem, 256);

#else  // FFMA fallback (never executes on GB300)
    for (int bm = 0; bm < BM; bm++) {
        const int m_base = (mblk0 + bm) * 128;
        for (int idx = tid; idx < 128 * 128; idx += 512) {
            int ml = idx >> 7, nl = idx & 127;
            int m = m_base + ml;
            int nn = bn * 128 + nl;
            int od = nn / HWo; int rr2 = nn - od * HWo;
            int oh = rr2 / p.Wout; int ow = rr2 - oh * p.Wout;
            int id0 = od * p.sd - p.pd, ih0 = oh * p.sh - p.ph, iw0 = ow * p.sw - p.pw;
            int gb = (id0 * p.H + ih0) * p.W + iw0;
            float s = 0.f;
            for (int k = 0; k < p.K; k++) {
                int2 dv = g_dec[k];
                int kd = dv.y >> 20, kh = (dv.y >> 10) & 1023, kw = dv.y & 1023;
                if ((unsigned)(id0 + kd) < (unsigned)p.D &&
                    (unsigned)(ih0 + kh) < (unsigned)p.H &&
                    (unsigned)(iw0 + kw) < (unsigned)p.W)
                    s += p.wf[(size_t)m * p.K + k] * unpack_hl(p.xpk[gb + dv.x]);
            }
            s += p.bias[m];
            if (p.gelu) s = gelu_tanh(s);
            size_t ob = (size_t)m * p.outStrideC + p.outOffset + nn;
            if (p.outpk) p.outpk[ob] = pack_hl(s);
            else p.outf[ob] = s;
        }
    }
#endif
}

// ---------------------------------------------------------------------------
// Token GEMM: bulk-copied A; mode-0 fuses K-plane emission; mode-1 staged.
// ---------------------------------------------------------------------------
struct TokParams {
    const uint32_t* bpk;
    const uint8_t* wpk;
    const float* wf;
    const float* bias;
    float* out;
    uint32_t* kpl;            // K-plane output (mode 0, may be null)
    int T, J, Kdim, NC, mode;
};

template <int BM>
__global__ __launch_bounds__(512, 2) void tok_mma_kernel(TokParams p) {
    extern __shared__ char smem_raw[];
    char* smem_al = (char*)(((uintptr_t)smem_raw + 1023) & ~(uintptr_t)1023);

    const int tid = threadIdx.x;
    const int bn = blockIdx.x;
    const int mblk0 = blockIdx.y * BM;

#if HAS_TCGEN05
    const uint32_t sb = smem_u32(smem_al);
    const uint32_t mbar = sb + SME_MBAR;
    const uint32_t ambar = sb + SME_AMBAR;
    const uint32_t tmem_slot = sb + SME_TSLOT;
    const int wid = tid >> 5;
    const int lane = tid & 31;

    if (wid == 0) {
        TCGEN05_ALLOC(tmem_slot, 256);
        TCGEN05_RELINQ();
    }
    if (tid == 0) {
#pragma unroll
        for (int i = 0; i < 4; i++) MBARRIER_INIT(mbar + 8 * i, 1);
        MBARRIER_INIT(ambar, 1);
    }
    __syncthreads();
    uint32_t tmem;
    asm volatile("ld.shared.b32 %0, [%1];" : "=r"(tmem) : "r"(tmem_slot));

    const int r = tid >> 2;
    const int q = tid & 3;
    const uint32_t* bsrc = p.bpk + (size_t)(bn * 128 + r) * p.Kdim;
    const int NC = p.NC;

    auto fillB = [&](int st, int kc) {
        char* Bhi = smem_al + (st ? SME_B1 : SME_B0);
        char* Blo = Bhi + 16384;
        const uint32_t* src = bsrc + kc * 64 + q * 16;
        uint32_t buf[16];
#pragma unroll
        for (int i = 0; i < 4; i++)
            *reinterpret_cast<uint4*>(&buf[i * 4]) =
                *reinterpret_cast<const uint4*>(src + i * 4);
#pragma unroll
        for (int i = 0; i < 8; i++) {
            int kk = q * 16 + 2 * i;
            uint32_t v0 = buf[2 * i], v1 = buf[2 * i + 1];
            uint32_t off = r * 128 + kk * 2;
            uint32_t sw = off ^ ((off >> 3) & 0x70);
            *reinterpret_cast<uint32_t*>(Bhi + sw) = __byte_perm(v0, v1, 0x7632);
            *reinterpret_cast<uint32_t*>(Blo + sw) = __byte_perm(v0, v1, 0x5410);
        }
    };

    int wpar = 0;
    auto waitCommits = [&](int target) {
        while (wpar < target) {
            MBARRIER_WAIT_PARITY(mbar + 8 * (wpar & 3), (wpar >> 2) & 1);
            wpar++;
        }
    };

    fillB(0, 0);

    for (int kc = 0; kc < NC; kc++) {
        int st = kc & 1;
#pragma unroll
        for (int bm = 0; bm < BM; bm++) {
            int ni = kc * BM + bm;
            if (ni >= 1) waitCommits(ni);
            if (wid == 0 && elect_one()) {
                const uint8_t* asrc =
                    p.wpk + ((size_t)(mblk0 + bm) * NC + kc) * 32768;
                MBARRIER_EXPECT_TX(ambar, 32768);
                CP_BULK_G2S(sb + SME_A, asrc, 32768, ambar);
            }
            MBARRIER_WAIT_PARITY(ambar, ni & 1);
            FENCE_PROXY_ASYNC();
            __syncthreads();
            if (wid == 0 && elect_one()) {
                uint64_t dAh = make_desc(sb + SME_A);
                uint64_t dAl = dAh + (16384 >> 4);
                uint64_t dBh = make_desc(sb + (st ? SME_B1 : SME_B0));
                uint64_t dBl = dBh + (16384 >> 4);
                uint32_t d = tmem + bm * 128;
                uint32_t first = (kc == 0) ? 0u : 1u;
#pragma unroll
                for (int s = 0; s < 4; s++) {
                    uint64_t o = s * 2;
                    mma_f16_ss(d, dAh + o, dBh + o, CONV_IDESC, first); first = 1;
                    mma_f16_ss(d, dAh + o, dBl + o, CONV_IDESC, 1);
                    mma_f16_ss(d, dAl + o, dBh + o, CONV_IDESC, 1);
                }
                TCGEN05_COMMIT(mbar + 8 * (ni & 3));
            }
        }
        if (kc + 1 < NC) fillB(st ^ 1, kc + 1);
    }
    waitCommits(NC * BM);
    TCGEN05_FENCE_AFTER();

    {
        const int sp = wid & 3;
        const int cb = wid >> 2;
        const int t0 = bn * 128 + cb * 32;
        if (p.mode == 0) {
#pragma unroll
            for (int bm = 0; bm < BM; bm++) {
                const int m = (mblk0 + bm) * 128 + sp * 32 + lane;
                const float bv = p.bias[m];
                uint32_t dr[32];
                TCGEN05_LD_X32(dr, tmem + bm * 128 + cb * 32);
                TCGEN05_WAIT_LD();
                const bool kplane = p.kpl && m >= 512 && m < 1024;
#pragma unroll
                for (int j = 0; j < 32; j++) {
                    float v = __uint_as_float(dr[j]) + bv;
                    p.out[(size_t)(t0 + j) * p.J + m] = v;
                    if (kplane) {
                        // pair channels (even m, odd m) into one bf16x2 word
                        float vhi = __shfl_down_sync(0xffffffffu, v, 1);
                        if ((lane & 1) == 0) {
                            __nv_bfloat162 b2 =
                                __float22bfloat162_rn(make_float2(v, vhi));
                            p.kpl[(size_t)(t0 + j) * 256 + ((m - 512) >> 1)] =
                                *reinterpret_cast<uint32_t*>(&b2);
                        }
                    }
                }
            }
        } else {
            float* stage = reinterpret_cast<float*>(smem_al);   // [128][129]
#pragma unroll
            for (int bm = 0; bm < BM; bm++) {
                uint32_t dr[32];
                TCGEN05_LD_X32(dr, tmem + bm * 128 + cb * 32);
                TCGEN05_WAIT_LD();
                __syncthreads();
                int srow = sp * 32 + lane;
#pragma unroll
                for (int j = 0; j < 32; j++)
                    stage[srow * 129 + cb * 32 + j] = __uint_as_float(dr[j]);
                __syncthreads();
#pragma unroll
                for (int rr = 0; rr < 8; rr++) {
                    int ml = wid * 8 + rr;
                    int m = (mblk0 + bm) * 128 + ml;
                    float bv = p.bias[m];
                    float* orow = p.out + (size_t)m * p.T + bn * 128;
#pragma unroll
                    for (int part = 0; part < 4; part++) {
                        int col = part * 32 + lane;
                        orow[col] += stage[ml * 129 + col] + bv;
                    }
                }
            }
        }
        TCGEN05_FENCE_BEFORE();
    }
    __syncthreads();
    if (tid == 0) {
#pragma unroll
        for (int i = 0; i < 4; i++) MBARRIER_INVAL(mbar + 8 * i);
        MBARRIER_INVAL(ambar);
    }
    if (wid == 0) TCGEN05_DEALLOC(tmem, 256);

#else  // FFMA fallback
    for (int bm = 0; bm < BM; bm++) {
        int m_base = (mblk0 + bm) * 128;
        for (int idx = tid; idx < 128 * 128; idx += 512) {
            int tl = idx >> 7, jl = idx & 127;
            int t = bn * 128 + tl, j = m_base + jl;
            float s = 0.f;
            for (int k = 0; k < p.Kdim; k++)
                s += unpack_hl(p.bpk[(size_t)t * p.Kdim + k]) * p.wf[(size_t)k * p.J + j];
            s += p.bias[j];
            if (p.mode == 0) {
                p.out[(size_t)t * p.J + j] = s;
                if (p.kpl && j >= 512 && j < 1024 && (j & 1) == 0) {
                    float s1 = 0.f;
                    for (int k = 0; k < p.Kdim; k++)
                        s1 += unpack_hl(p.bpk[(size_t)t * p.Kdim + k]) *
                              p.wf[(size_t)k * p.J + j + 1];
                    s1 += p.bias[j + 1];
                    __nv_bfloat162 b2 = __float22bfloat162_rn(make_float2(s, s1));
                    p.kpl[(size_t)t * 256 + ((j - 512) >> 1)] =
                        *reinterpret_cast<uint32_t*>(&b2);
                }
            } else {
                p.out[(size_t)j * p.T + t] += s;
            }
        }
    }
#endif
}

// ---------------------------------------------------------------------------
// LayerNorm: fp32 channel-major -> packed token-major
// ---------------------------------------------------------------------------
__global__ __launch_bounds__(256) void layernorm_kernel(
    const float* __restrict__ x, const float* __restrict__ g,
    const float* __restrict__ b, uint32_t* __restrict__ ypk, int T) {
    const int tx = threadIdx.x;
    const int ty = threadIdx.y;
    const int t = blockIdx.x * 32 + tx;

    float s = 0.f, ss = 0.f;
#pragma unroll
    for (int i = 0; i < 64; i++) {
        int c = ty * 64 + i;
        float v = x[(size_t)c * T + t];
        s += v; ss += v * v;
    }
    __shared__ float shs[8][32], shss[8][32];
    __shared__ float smu[32], srs[32];
    shs[ty][tx] = s; shss[ty][tx] = ss;
    __syncthreads();
    if (ty == 0) {
        float S = 0.f, SS = 0.f;
#pragma unroll
        for (int j = 0; j < 8; j++) { S += shs[j][tx]; SS += shss[j][tx]; }
        float mu = S * (1.f / 512.f);
        float var = SS * (1.f / 512.f) - mu * mu;
        smu[tx] = mu;
        srs[tx] = rsqrtf(var + 1e-5f);
    }
    __syncthreads();
    float mu = smu[tx], rs = srs[tx];
    uint32_t* yrow = ypk + (size_t)t * 512 + ty * 64;
#pragma unroll
    for (int i = 0; i < 64; i++) {
        int c = ty * 64 + i;
        float v = x[(size_t)c * T + t];
        yrow[i] = pack_hl((v - mu) * rs * g[c] + b[c]);
    }
}

// ---------------------------------------------------------------------------
// Neighborhood attention — bf16 K-plane score, float2 channel-pair PV.
// ---------------------------------------------------------------------------
__global__ __launch_bounds__(256) void natt_kernel(
    const float* __restrict__ qkv, uint32_t* __restrict__ atpk) {
    __shared__ float psh[8][248];
    __shared__ float tsh[8][32][33];

    const int warp = threadIdx.x >> 5;
    const int lane = threadIdx.x & 31;
    const int t = blockIdx.x * 8 + warp;
    const int hd = blockIdx.y;
    const int d = t >> 11;
    const int hh = (t >> 6) & 31;
    const int ww = t & 63;

    float2 q2 = *reinterpret_cast<const float2*>(
        qkv + (size_t)t * 1536 + hd * 64 + 2 * lane);
    q2.x *= 0.125f; q2.y *= 0.125f;

    float sc[8];
    float m = -1e30f;
#pragma unroll
    for (int it = 0; it < 8; it++) {
#pragma unroll
        for (int j = 0; j < 32; j++) {
            int nb = it * 32 + j;
            float pv = 0.f;
            if (nb < 245) {
                int pk = g_npack[nb];
                int nd = d + (pk >> 16) - 2;
                int nh = hh + ((pk >> 8) & 255) - 3;
                int nw = ww + (pk & 255) - 3;
                if ((unsigned)nd < 4u && (unsigned)nh < 32u && (unsigned)nw < 64u) {
                    int nt = (nd * 32 + nh) * 64 + nw;
                    uint32_t kw32 = g_kpl[(size_t)nt * 256 + hd * 32 + lane];
                    float2 kf = __bfloat1622float2(
                        *reinterpret_cast<__nv_bfloat162*>(&kw32));
                    pv = fmaf(q2.x, kf.x, q2.y * kf.y);
                }
            }
            tsh[warp][j][lane] = pv;
        }
        __syncwarp();
        float s = 0.f;
#pragma unroll
        for (int j = 0; j < 32; j++) s += tsh[warp][lane][j];
        __syncwarp();

        int nb = it * 32 + lane;
        float dot = -1e30f;
        if (nb < 245) {
            int pk = g_npack[nb];
            int nd = d + (pk >> 16) - 2;
            int nh = hh + ((pk >> 8) & 255) - 3;
            int nw = ww + (pk & 255) - 3;
            if ((unsigned)nd < 4u && (unsigned)nh < 32u && (unsigned)nw < 64u)
                dot = s;
        }
        sc[it] = dot;
        m = fmaxf(m, dot);
    }
#pragma unroll
    for (int o = 16; o; o >>= 1) m = fmaxf(m, __shfl_xor_sync(0xffffffffu, m, o));

    float l = 0.f;
#pragma unroll
    for (int it = 0; it < 8; it++) {
        int nb = it * 32 + lane;
        float e = (sc[it] > -1e29f) ? __expf(sc[it] - m) : 0.f;
        if (nb < 248) psh[warp][nb] = e;
        l += e;
    }
#pragma unroll
    for (int o = 16; o; o >>= 1) l += __shfl_xor_sync(0xffffffffu, l, o);
    __syncwarp();

    // PV phase: lane = channel pair (2*lane, 2*lane+1), single LDG.64/neighbor
    float acc0 = 0.f, acc1 = 0.f;
    for (int nb = 0; nb < 245; nb++) {
        float pb = psh[warp][nb];
        if (pb > 0.f) {
            int nt = t + g_ndelta[nb];
            float2 vv = *reinterpret_cast<const float2*>(
                qkv + (size_t)nt * 1536 + 1024 + hd * 64 + 2 * lane);
            acc0 = fmaf(pb, vv.x, acc0);
            acc1 = fmaf(pb, vv.y, acc1);
        }
    }
    float inv = 1.f / l;
    uint32_t* op = atpk + (size_t)t * 512 + hd * 64;
    op[2 * lane] = pack_hl(acc0 * inv);
    op[2 * lane + 1] = pack_hl(acc1 * inv);
}

// ---------------------------------------------------------------------------
// Host launcher
// ---------------------------------------------------------------------------
extern "C" void kernel_launch(void* const* d_in, const int* in_sizes, int n_in,
                              void* d_out, int out_size) {
    const float* x2d  = (const float*)d_in[0];
    const float* x3d  = (const float*)d_in[1];
    const float* sw0  = (const float*)d_in[2];  const float* sb0 = (const float*)d_in[3];
    const float* sw1  = (const float*)d_in[4];  const float* sb1 = (const float*)d_in[5];
    const float* sw2  = (const float*)d_in[6];  const float* sb2 = (const float*)d_in[7];
    const float* pw0  = (const float*)d_in[8];  const float* pb0 = (const float*)d_in[9];
    const float* pw1  = (const float*)d_in[10]; const float* pb1 = (const float*)d_in[11];
    const float* pw2  = (const float*)d_in[12]; const float* pb2 = (const float*)d_in[13];
    const float* latw = (const float*)d_in[14]; const float* latb = (const float*)d_in[15];
    const float* lng  = (const float*)d_in[16]; const float* lnb  = (const float*)d_in[17];
    const float* qkvw = (const float*)d_in[18]; const float* qkvb = (const float*)d_in[19];
    const float* pjw  = (const float*)d_in[20]; const float* pjb  = (const float*)d_in[21];
    float* lat = (float*)d_out;

    uint32_t *pkA, *pkB, *pkF, *pkX, *ynpk, *atpk, *kpl;
    float *qkvB;
    uint8_t *wpk2;
    cudaGetSymbolAddress((void**)&pkA, g_pk_a);
    cudaGetSymbolAddress((void**)&pkB, g_pk_b);
    cudaGetSymbolAddress((void**)&pkF, g_pk_f);
    cudaGetSymbolAddress((void**)&pkX, g_pk_x2d);
    cudaGetSymbolAddress((void**)&ynpk, g_ynpk);
    cudaGetSymbolAddress((void**)&qkvB, g_qkv);
    cudaGetSymbolAddress((void**)&atpk, g_atpk);
    cudaGetSymbolAddress((void**)&kpl, g_kpl);
    cudaGetSymbolAddress((void**)&wpk2, g_wpk2);

    cudaFuncSetAttribute(conv_mma_kernel<1>,
                         cudaFuncAttributeMaxDynamicSharedMemorySize, CONV_SMEM_BYTES);
    cudaFuncSetAttribute(conv_mma_kernel<2>,
                         cudaFuncAttributeMaxDynamicSharedMemorySize, CONV_SMEM_BYTES);
    cudaFuncSetAttribute(tok_mma_kernel<1>,
                         cudaFuncAttributeMaxDynamicSharedMemorySize, CONV_SMEM_BYTES);
    cudaFuncSetAttribute(tok_mma_kernel<2>,
                         cudaFuncAttributeMaxDynamicSharedMemorySize, CONV_SMEM_BYTES);

    auto run_conv = [&](const uint32_t* xpk, const float* wf, const float* bias,
                        uint32_t* outpk, float* outf,
                        int Cin, int D, int H, int W, int Dout, int Hout, int Wout,
                        int KD, int KH, int KW, int sd, int sh, int sw,
                        int pd, int ph, int pw, int Cout,
                        int outStrideC, int outOffset, int gelu) {
        int K = Cin * KD * KH * KW;
        int NC = (K + 63) / 64;
        int Kp = NC * 64;
        conv_decode_kernel<<<(Kp + 255) / 256, 256>>>(K, Kp, KD * KH * KW, KH * KW,
                                                      KW, D, H, W);
        wpack_kernel<<<dim3(NC, Cout / 128), 256>>>(wf, K, NC);
        int Nvox = Dout * Hout * Wout;
        ConvParams p{ xpk, wf, bias, outpk, outf,
                      D, H, W, Hout, Wout, sd, sh, sw, pd, ph, pw,
                      K, NC, outStrideC, outOffset, gelu };
        int nblk = Cout / 128;
        int bn = Nvox / 128;
        if (nblk % 2 == 0 && bn * (nblk / 2) >= 256)
            conv_mma_kernel<2><<<dim3(bn, nblk / 2), 512, CONV_SMEM_BYTES>>>(p);
        else
            conv_mma_kernel<1><<<dim3(bn, nblk), 512, CONV_SMEM_BYTES>>>(p);
    };

    natt_table_kernel<<<1, 256>>>();
    xpack_kernel<<<(5 * 24 * 256 * 512 / 4 + 255) / 256, 256>>>(
        x3d, pkA, 5 * 24 * 256 * 512 / 4);
    xpack_kernel<<<(8 * 256 * 512 / 4 + 255) / 256, 256>>>(
        x2d, pkX, 8 * 256 * 512 / 4);

    // ---- 3D tower ----
    run_conv(pkA, pw0, pb0, pkB, nullptr, 5, 24, 256, 512, 12, 128, 256,
             3, 3, 3, 2, 2, 2, 1, 1, 1, 128, 393216, 0, 1);
    run_conv(pkB, pw1, pb1, pkA, nullptr, 128, 12, 128, 256, 6, 64, 128,
             3, 3, 3, 2, 2, 2, 1, 1, 1, 256, 49152, 0, 1);
    run_conv(pkA, pw2, pb2, pkF, nullptr, 256, 6, 64, 128, 3, 32, 64,
             3, 3, 3, 2, 2, 2, 1, 1, 1, 512, 8192, 0, 1);

    // ---- 2D tower ----
    run_conv(pkX, sw0, sb0, pkB, nullptr, 8, 1, 256, 512, 1, 128, 256,
             1, 3, 3, 1, 2, 2, 0, 1, 1, 128, 32768, 0, 1);
    run_conv(pkB, sw1, sb1, pkA, nullptr, 128, 1, 128, 256, 1, 64, 128,
             1, 3, 3, 1, 2, 2, 0, 1, 1, 256, 8192, 0, 1);
    run_conv(pkA, sw2, sb2, pkF, nullptr, 256, 1, 64, 128, 1, 32, 64,
             1, 3, 3, 1, 2, 2, 0, 1, 1, 512, 8192, 3 * 2048, 1);

    // ---- lateral 1x1x1 -> d_out fp32 ----
    run_conv(pkF, latw, latb, nullptr, lat, 512, 4, 32, 64, 4, 32, 64,
             1, 1, 1, 1, 1, 1, 0, 0, 0, 512, 8192, 0, 0);

    // ---- attention weight prepack ----
    const size_t QKV_PK = 8 * 12 * 32768;
    const size_t PRJ_PK = 8 * 4 * 32768;
    for (int i = 0; i < 3; i++) {
        wpackT_kernel<<<dim3(8, 12), 256>>>(qkvw + (size_t)i * 512 * 1536,
                                            wpk2 + i * QKV_PK, 512, 8, 1536);
        wpackT_kernel<<<dim3(8, 4), 256>>>(pjw + (size_t)i * 512 * 512,
                                           wpk2 + 3 * QKV_PK + i * PRJ_PK, 512, 8, 512);
    }

    // ---- 3 neighborhood-attention blocks ----
    for (int i = 0; i < 3; i++) {
        layernorm_kernel<<<8192 / 32, dim3(32, 8)>>>(lat, lng + i * 512, lnb + i * 512,
                                                     ynpk, 8192);
        TokParams pq{ ynpk, wpk2 + i * QKV_PK, qkvw + (size_t)i * 512 * 1536,
                      qkvb + i * 1536, qkvB, kpl, 8192, 1536, 512, 8, 0 };
        tok_mma_kernel<2><<<dim3(8192 / 128, 6), 512, CONV_SMEM_BYTES>>>(pq);
        natt_kernel<<<dim3(1024, 8), 256>>>(qkvB, atpk);
        TokParams pp{ atpk, wpk2 + 3 * QKV_PK + i * PRJ_PK,
                      pjw + (size_t)i * 512 * 512,
                      pjb + i * 512, lat, nullptr, 8192, 512, 512, 8, 1 };
        tok_mma_kernel<1><<<dim3(8192 / 128, 4), 512, CONV_SMEM_BYTES>>>(pp);
    }
}

// round 15
// speedup vs baseline: 1.8524x; 1.1478x over previous
#include <cuda_runtime.h>
#include <cuda_bf16.h>
#include <math.h>
#include <cstdint>

#if defined(__CUDA_ARCH_SPECIFIC__) || defined(__CUDA_ARCH_FEAT_SM103_ALL)
#define HAS_TCGEN05 1
#else
#define HAS_TCGEN05 0
#endif

// ---------------------------------------------------------------------------
// Scratch buffers (packed u32 = bf16 hi << 16 | bf16 lo)
// ---------------------------------------------------------------------------
__device__ uint32_t g_pk_a[15728640];
__device__ uint32_t g_pk_b[50331648];
__device__ uint32_t g_pk_f[4194304];
__device__ uint32_t g_pk_x2d[1048576];
__device__ uint8_t  g_wpk[14155776];
__device__ uint8_t  g_wpk2[12582912];
__device__ uint32_t g_ynpk[8192 * 512];
__device__ float    g_qkv[8192 * 1536];
__device__ uint32_t g_kpl[8192 * 256];   // K-plane bf16x2 for natt score
__device__ uint32_t g_atpk[8192 * 512];
__device__ int2     g_dec[8192];
__device__ int      g_npack[256];

// ---------------------------------------------------------------------------
// Common helpers
// ---------------------------------------------------------------------------
__device__ __forceinline__ uint32_t smem_u32(const void* p) {
    uint32_t a;
    asm("{ .reg .u64 t; cvta.to.shared.u64 t, %1; cvt.u32.u64 %0, t; }"
        : "=r"(a) : "l"(p));
    return a;
}
__device__ __forceinline__ float gelu_tanh(float x) {
    float x3 = x * x * x;
    float t = tanhf(0.7978845608028654f * (x + 0.044715f * x3));
    return 0.5f * x * (1.0f + t);
}
__device__ __forceinline__ uint32_t pack_hl(float f) {
    __nv_bfloat16 h = __float2bfloat16(f);
    __nv_bfloat16 l = __float2bfloat16(f - __bfloat162float(h));
    return ((uint32_t)__bfloat16_as_ushort(h) << 16) | __bfloat16_as_ushort(l);
}
__device__ __forceinline__ float unpack_hl(uint32_t v) {
    float h = __bfloat162float(__ushort_as_bfloat16((unsigned short)(v >> 16)));
    float l = __bfloat162float(__ushort_as_bfloat16((unsigned short)(v & 0xFFFF)));
    return h + l;
}

#if HAS_TCGEN05
__device__ __forceinline__ uint32_t elect_one() {
    uint32_t pred;
    asm volatile("{ .reg .pred p; elect.sync _|p, 0xFFFFFFFF; selp.b32 %0, 1, 0, p; }"
                 : "=r"(pred));
    return pred;
}
#define TCGEN05_ALLOC(a, n) \
    asm volatile("tcgen05.alloc.cta_group::1.sync.aligned.shared::cta.b32 [%0], %1;" \
                 :: "r"((uint32_t)(a)), "r"((uint32_t)(n)) : "memory")
#define TCGEN05_DEALLOC(t, n) \
    asm volatile("tcgen05.dealloc.cta_group::1.sync.aligned.b32 %0, %1;" :: "r"(t), "r"(n))
#define TCGEN05_RELINQ() \
    asm volatile("tcgen05.relinquish_alloc_permit.cta_group::1.sync.aligned;")
#define TCGEN05_COMMIT(m) \
    asm volatile("tcgen05.commit.cta_group::1.mbarrier::arrive::one.shared::cluster.b64 [%0];" \
                 :: "r"((uint32_t)(m)) : "memory")
#define TCGEN05_FENCE_AFTER() \
    asm volatile("tcgen05.fence::after_thread_sync;" ::: "memory")
#define TCGEN05_FENCE_BEFORE() \
    asm volatile("tcgen05.fence::before_thread_sync;" ::: "memory")
#define TCGEN05_WAIT_LD() asm volatile("tcgen05.wait::ld.sync.aligned;" ::: "memory")
#define FENCE_PROXY_ASYNC() asm volatile("fence.proxy.async.shared::cta;" ::: "memory")
#define MBARRIER_INIT(m, c) \
    asm volatile("mbarrier.init.shared.b64 [%0], %1;" :: "r"((uint32_t)(m)), "r"((uint32_t)(c)) : "memory")
#define MBARRIER_INVAL(m) \
    asm volatile("mbarrier.inval.shared.b64 [%0];" :: "r"((uint32_t)(m)) : "memory")
#define MBARRIER_EXPECT_TX(m, b) \
    asm volatile("mbarrier.arrive.expect_tx.shared.b64 _, [%0], %1;" \
                 :: "r"((uint32_t)(m)), "r"((uint32_t)(b)) : "memory")
#define CP_BULK_G2S(dst, src, nbytes, mbar) \
    asm volatile("cp.async.bulk.shared::cta.global.mbarrier::complete_tx::bytes [%0], [%1], %2, [%3];" \
                 :: "r"((uint32_t)(dst)), "l"(src), "r"((uint32_t)(nbytes)), \
                    "r"((uint32_t)(mbar)) : "memory")
#define MBARRIER_WAIT_PARITY(m, ph) do {                                           \
    uint32_t _m = (uint32_t)(m), _p = (uint32_t)(ph), _d;                          \
    asm volatile("{ .reg .pred p; mbarrier.try_wait.parity.acquire.cta.shared::cta.b64 p, [%1], %2;" \
                 " selp.b32 %0, 1, 0, p; }" : "=r"(_d) : "r"(_m), "r"(_p) : "memory"); \
    if (!_d) {                                                                     \
        asm volatile("{ .reg .pred P1; WL_%=: mbarrier.try_wait.parity.acquire.cta.shared::cta.b64 P1, [%0], %1, 0x989680;" \
                     " @P1 bra.uni WD_%=; bra.uni WL_%=; WD_%=: }"                 \
                     :: "r"(_m), "r"(_p) : "memory");                              \
    }                                                                              \
} while (0)
#define TCGEN05_LD_X32(r, a)                                                       \
    asm volatile("tcgen05.ld.sync.aligned.32x32b.x32.b32 "                         \
        "{%0, %1, %2, %3, %4, %5, %6, %7, %8, %9, %10, %11, %12, %13, %14, %15, "  \
        " %16, %17, %18, %19, %20, %21, %22, %23, %24, %25, %26, %27, %28, %29, %30, %31}, [%32];" \
        : "=r"((r)[0]), "=r"((r)[1]), "=r"((r)[2]), "=r"((r)[3]),                  \
          "=r"((r)[4]), "=r"((r)[5]), "=r"((r)[6]), "=r"((r)[7]),                  \
          "=r"((r)[8]), "=r"((r)[9]), "=r"((r)[10]), "=r"((r)[11]),                \
          "=r"((r)[12]), "=r"((r)[13]), "=r"((r)[14]), "=r"((r)[15]),              \
          "=r"((r)[16]), "=r"((r)[17]), "=r"((r)[18]), "=r"((r)[19]),              \
          "=r"((r)[20]), "=r"((r)[21]), "=r"((r)[22]), "=r"((r)[23]),              \
          "=r"((r)[24]), "=r"((r)[25]), "=r"((r)[26]), "=r"((r)[27]),              \
          "=r"((r)[28]), "=r"((r)[29]), "=r"((r)[30]), "=r"((r)[31])               \
        : "r"(a))

static constexpr uint64_t SMEM_DESC_BASE_SW128 =
    (uint64_t(2) << 61) | (uint64_t(1) << 46) | (uint64_t(64) << 32) | (uint64_t(1) << 16);
__device__ __forceinline__ uint64_t make_desc(uint32_t addr) {
    return SMEM_DESC_BASE_SW128 | ((uint64_t)(addr >> 4) & 0x3FFF);
}
__device__ __forceinline__ void mma_f16_ss(uint32_t d, uint64_t ad, uint64_t bd,
                                           uint32_t idesc, uint32_t en) {
    asm volatile(
        "{ .reg .pred p; setp.ne.u32 p, %5, 0;\n\t"
        "tcgen05.mma.cta_group::1.kind::f16 [%0], %1, %2, %3, {%4, %4, %4, %4}, p; }"
        :: "r"(d), "l"(ad), "l"(bd), "r"(idesc), "r"(0u), "r"(en) : "memory");
}
static constexpr uint32_t CONV_IDESC =
    (1u << 4) | (1u << 7) | (1u << 10) | ((128u / 8) << 17) | ((128u / 16) << 24);
#endif // HAS_TCGEN05

#define SME_A 0
#define SME_B0 32768
#define SME_B1 65536
#define SME_MBAR 98304
#define SME_AMBAR 98336
#define SME_TSLOT 98344
#define CONV_SMEM_BYTES (1024 + 98304 + 128)

// ---------------------------------------------------------------------------
// Init / pack kernels
// ---------------------------------------------------------------------------
__global__ void natt_table_kernel() {
    int nb = threadIdx.x;
    if (nb < 245) {
        int od = nb / 49; int r = nb - od * 49;
        int oh = r / 7;   int ow = r - oh * 7;
        g_npack[nb] = (od << 16) | (oh << 8) | ow;
    }
}

__global__ void xpack_kernel(const float* __restrict__ x,
                             uint32_t* __restrict__ dst, int n4) {
    int i = blockIdx.x * 256 + threadIdx.x;
    if (i >= n4) return;
    float4 v = reinterpret_cast<const float4*>(x)[i];
    uint4 o;
    o.x = pack_hl(v.x); o.y = pack_hl(v.y);
    o.z = pack_hl(v.z); o.w = pack_hl(v.w);
    reinterpret_cast<uint4*>(dst)[i] = o;
}

// weight prepack; bm==0 blocks also decode their k-chunk of g_dec
__global__ void wpack_kernel(const float* __restrict__ w, int K, int NC,
                             int KV, int KHW, int KW, int D, int H, int W) {
    int kc = blockIdx.x, bm = blockIdx.y;
    int tid = threadIdx.x;
    if (bm == 0 && tid < 64) {
        int k = kc * 64 + tid;
        if (k < K) {
            int ci = k / KV; int tap = k - ci * KV;
            int kd = tap / KHW; int t2 = tap - kd * KHW;
            int kh = t2 / KW; int kw = t2 - kh * KW;
            g_dec[k] = make_int2(((ci * D + kd) * H + kh) * W + kw,
                                 (kd << 20) | (kh << 10) | kw);
        } else {
            g_dec[k] = make_int2(0, 1023 << 20);
        }
    }
    int r = tid >> 1, half = tid & 1;
    const float* wrow = w + (size_t)(bm * 128 + r) * K;
    uint8_t* hi = g_wpk + (size_t)(bm * NC + kc) * 32768;
    uint8_t* lo = hi + 16384;
#pragma unroll
    for (int i = 0; i < 16; i++) {
        int kk = half * 32 + 2 * i;
        int k = kc * 64 + kk;
        float a0 = (k < K) ? wrow[k] : 0.f;
        float a1 = (k + 1 < K) ? wrow[k + 1] : 0.f;
        uint32_t p0 = pack_hl(a0), p1 = pack_hl(a1);
        uint32_t hp = __byte_perm(p0, p1, 0x7632);
        uint32_t lp = __byte_perm(p0, p1, 0x5410);
        uint32_t off = r * 128 + kk * 2;
        uint32_t sw = off ^ ((off >> 3) & 0x70);
        *reinterpret_cast<uint32_t*>(hi + sw) = hp;
        *reinterpret_cast<uint32_t*>(lo + sw) = lp;
    }
}

__global__ void wpackT_kernel(const float* __restrict__ w, uint8_t* dst,
                              int K, int NC, int J) {
    int kc = blockIdx.x, bm = blockIdx.y;
    int tid = threadIdx.x;
    int r = tid >> 1, half = tid & 1;
    int m = bm * 128 + r;
    uint8_t* hi = dst + (size_t)(bm * NC + kc) * 32768;
    uint8_t* lo = hi + 16384;
#pragma unroll
    for (int i = 0; i < 16; i++) {
        int kk = half * 32 + 2 * i;
        int k = kc * 64 + kk;
        float a0 = (k < K) ? w[(size_t)k * J + m] : 0.f;
        float a1 = (k + 1 < K) ? w[(size_t)(k + 1) * J + m] : 0.f;
        uint32_t p0 = pack_hl(a0), p1 = pack_hl(a1);
        uint32_t hp = __byte_perm(p0, p1, 0x7632);
        uint32_t lp = __byte_perm(p0, p1, 0x5410);
        uint32_t off = r * 128 + kk * 2;
        uint32_t sw = off ^ ((off >> 3) & 0x70);
        *reinterpret_cast<uint32_t*>(hi + sw) = hp;
        *reinterpret_cast<uint32_t*>(lo + sw) = lp;
    }
}

// ---------------------------------------------------------------------------
// Conv kernel: bulk-copied A, double-buffered B gather, TMEM 256, 2 CTA/SM.
// ---------------------------------------------------------------------------
struct ConvParams {
    const uint32_t* xpk;
    const float* wf;
    const float* bias;
    uint32_t* outpk;
    float* outf;
    int D, H, W;
    int Hout, Wout;
    int sd, sh, sw, pd, ph, pw;
    int K, NC;
    int outStrideC, outOffset;
    int gelu;
};

template <int BM>
__global__ __launch_bounds__(512, 2) void conv_mma_kernel(ConvParams p) {
    extern __shared__ char smem_raw[];
    char* smem_al = (char*)(((uintptr_t)smem_raw + 1023) & ~(uintptr_t)1023);

    const int tid = threadIdx.x;
    const int bn = blockIdx.x;
    const int mblk0 = blockIdx.y * BM;
    const int HWo = p.Hout * p.Wout;

#if HAS_TCGEN05
    const uint32_t sb = smem_u32(smem_al);
    const uint32_t mbar = sb + SME_MBAR;
    const uint32_t ambar = sb + SME_AMBAR;
    const uint32_t tmem_slot = sb + SME_TSLOT;
    const int wid = tid >> 5;
    const int lane = tid & 31;

    if (wid == 0) {
        TCGEN05_ALLOC(tmem_slot, 256);
        TCGEN05_RELINQ();
    }
    if (tid == 0) {
#pragma unroll
        for (int i = 0; i < 4; i++) MBARRIER_INIT(mbar + 8 * i, 1);
        MBARRIER_INIT(ambar, 1);
    }
    __syncthreads();
    uint32_t tmem;
    asm volatile("ld.shared.b32 %0, [%1];" : "=r"(tmem) : "r"(tmem_slot));

    const int r = tid >> 2;
    const int q = tid & 3;
    const int n = bn * 128 + r;
    const int od = n / HWo; int rr2 = n - od * HWo;
    const int oh = rr2 / p.Wout; const int ow = rr2 - oh * p.Wout;
    const int id0 = od * p.sd - p.pd;
    const int ih0 = oh * p.sh - p.ph;
    const int iw0 = ow * p.sw - p.pw;
    const int gbase = (id0 * p.H + ih0) * p.W + iw0;
    const int NC = p.NC;

    auto fillB = [&](int st, int kc) {
        char* Bhi = smem_al + (st ? SME_B1 : SME_B0);
        char* Blo = Bhi + 16384;
        const int kt = kc * 64;
#pragma unroll
        for (int i = 0; i < 8; i++) {
            int kk = q * 16 + 2 * i;
            int k = kt + kk;
            int4 dv = *reinterpret_cast<const int4*>(&g_dec[k]);
            uint32_t v0 = 0, v1 = 0;
            {
                int kd = dv.y >> 20, kh = (dv.y >> 10) & 1023, kw = dv.y & 1023;
                if ((unsigned)(id0 + kd) < (unsigned)p.D &&
                    (unsigned)(ih0 + kh) < (unsigned)p.H &&
                    (unsigned)(iw0 + kw) < (unsigned)p.W)
                    v0 = p.xpk[gbase + dv.x];
            }
            {
                int kd = dv.w >> 20, kh = (dv.w >> 10) & 1023, kw = dv.w & 1023;
                if ((unsigned)(id0 + kd) < (unsigned)p.D &&
                    (unsigned)(ih0 + kh) < (unsigned)p.H &&
                    (unsigned)(iw0 + kw) < (unsigned)p.W)
                    v1 = p.xpk[gbase + dv.z];
            }
            uint32_t off = r * 128 + kk * 2;
            uint32_t sw = off ^ ((off >> 3) & 0x70);
            *reinterpret_cast<uint32_t*>(Bhi + sw) = __byte_perm(v0, v1, 0x7632);
            *reinterpret_cast<uint32_t*>(Blo + sw) = __byte_perm(v0, v1, 0x5410);
        }
    };

    int wpar = 0;
    auto waitCommits = [&](int target) {
        while (wpar < target) {
            MBARRIER_WAIT_PARITY(mbar + 8 * (wpar & 3), (wpar >> 2) & 1);
            wpar++;
        }
    };

    fillB(0, 0);

    for (int kc = 0; kc < NC; kc++) {
        int st = kc & 1;
#pragma unroll
        for (int bm = 0; bm < BM; bm++) {
            int ni = kc * BM + bm;
            if (ni >= 1) waitCommits(ni);
            if (wid == 0 && elect_one()) {
                const uint8_t* asrc =
                    g_wpk + ((size_t)(mblk0 + bm) * NC + kc) * 32768;
                MBARRIER_EXPECT_TX(ambar, 32768);
                CP_BULK_G2S(sb + SME_A, asrc, 32768, ambar);
            }
            MBARRIER_WAIT_PARITY(ambar, ni & 1);
            FENCE_PROXY_ASYNC();
            __syncthreads();
            if (wid == 0 && elect_one()) {
                uint64_t dAh = make_desc(sb + SME_A);
                uint64_t dAl = dAh + (16384 >> 4);
                uint64_t dBh = make_desc(sb + (st ? SME_B1 : SME_B0));
                uint64_t dBl = dBh + (16384 >> 4);
                uint32_t d = tmem + bm * 128;
                uint32_t first = (kc == 0) ? 0u : 1u;
#pragma unroll
                for (int s = 0; s < 4; s++) {
                    uint64_t o = s * 2;
                    mma_f16_ss(d, dAh + o, dBh + o, CONV_IDESC, first); first = 1;
                    mma_f16_ss(d, dAh + o, dBl + o, CONV_IDESC, 1);
                    mma_f16_ss(d, dAl + o, dBh + o, CONV_IDESC, 1);
                }
                TCGEN05_COMMIT(mbar + 8 * (ni & 3));
            }
        }
        if (kc + 1 < NC) fillB(st ^ 1, kc + 1);
    }
    waitCommits(NC * BM);
    TCGEN05_FENCE_AFTER();

    // ---- smem-staged coalesced epilogue ----
    {
        float* stage = reinterpret_cast<float*>(smem_al);   // [128][129]
        const int sp = wid & 3;
        const int cb = wid >> 2;
#pragma unroll
        for (int bm = 0; bm < BM; bm++) {
            uint32_t dr[32];
            TCGEN05_LD_X32(dr, tmem + bm * 128 + cb * 32);
            TCGEN05_WAIT_LD();
            __syncthreads();
            int srow = sp * 32 + lane;
#pragma unroll
            for (int j = 0; j < 32; j++)
                stage[srow * 129 + cb * 32 + j] = __uint_as_float(dr[j]);
            __syncthreads();
#pragma unroll
            for (int rr = 0; rr < 8; rr++) {
                int ml = wid * 8 + rr;
                int m = (mblk0 + bm) * 128 + ml;
                float bv = p.bias[m];
                size_t obase = (size_t)m * p.outStrideC + p.outOffset + bn * 128;
#pragma unroll
                for (int part = 0; part < 4; part++) {
                    float v = stage[ml * 129 + part * 32 + lane] + bv;
                    if (p.gelu) v = gelu_tanh(v);
                    if (p.outpk) p.outpk[obase + part * 32 + lane] = pack_hl(v);
                    else p.outf[obase + part * 32 + lane] = v;
                }
            }
        }
        TCGEN05_FENCE_BEFORE();
    }
    __syncthreads();
    if (tid == 0) {
#pragma unroll
        for (int i = 0; i < 4; i++) MBARRIER_INVAL(mbar + 8 * i);
        MBARRIER_INVAL(ambar);
    }
    if (wid == 0) TCGEN05_DEALLOC(tmem, 256);

#else  // FFMA fallback (never executes on GB300)
    for (int bm = 0; bm < BM; bm++) {
        const int m_base = (mblk0 + bm) * 128;
        for (int idx = tid; idx < 128 * 128; idx += 512) {
            int ml = idx >> 7, nl = idx & 127;
            int m = m_base + ml;
            int nn = bn * 128 + nl;
            int od = nn / HWo; int rr2 = nn - od * HWo;
            int oh = rr2 / p.Wout; int ow = rr2 - oh * p.Wout;
            int id0 = od * p.sd - p.pd, ih0 = oh * p.sh - p.ph, iw0 = ow * p.sw - p.pw;
            int gb = (id0 * p.H + ih0) * p.W + iw0;
            float s = 0.f;
            for (int k = 0; k < p.K; k++) {
                int2 dv = g_dec[k];
                int kd = dv.y >> 20, kh = (dv.y >> 10) & 1023, kw = dv.y & 1023;
                if ((unsigned)(id0 + kd) < (unsigned)p.D &&
                    (unsigned)(ih0 + kh) < (unsigned)p.H &&
                    (unsigned)(iw0 + kw) < (unsigned)p.W)
                    s += p.wf[(size_t)m * p.K + k] * unpack_hl(p.xpk[gb + dv.x]);
            }
            s += p.bias[m];
            if (p.gelu) s = gelu_tanh(s);
            size_t ob = (size_t)m * p.outStrideC + p.outOffset + nn;
            if (p.outpk) p.outpk[ob] = pack_hl(s);
            else p.outf[ob] = s;
        }
    }
#endif
}

// ---------------------------------------------------------------------------
// Token GEMM: bulk-copied A; mode-0 fuses K-plane emission; mode-1 staged.
// ---------------------------------------------------------------------------
struct TokParams {
    const uint32_t* bpk;
    const uint8_t* wpk;
    const float* wf;
    const float* bias;
    float* out;
    uint32_t* kpl;
    int T, J, Kdim, NC, mode;
};

template <int BM>
__global__ __launch_bounds__(512, 2) void tok_mma_kernel(TokParams p) {
    extern __shared__ char smem_raw[];
    char* smem_al = (char*)(((uintptr_t)smem_raw + 1023) & ~(uintptr_t)1023);

    const int tid = threadIdx.x;
    const int bn = blockIdx.x;
    const int mblk0 = blockIdx.y * BM;

#if HAS_TCGEN05
    const uint32_t sb = smem_u32(smem_al);
    const uint32_t mbar = sb + SME_MBAR;
    const uint32_t ambar = sb + SME_AMBAR;
    const uint32_t tmem_slot = sb + SME_TSLOT;
    const int wid = tid >> 5;
    const int lane = tid & 31;

    if (wid == 0) {
        TCGEN05_ALLOC(tmem_slot, 256);
        TCGEN05_RELINQ();
    }
    if (tid == 0) {
#pragma unroll
        for (int i = 0; i < 4; i++) MBARRIER_INIT(mbar + 8 * i, 1);
        MBARRIER_INIT(ambar, 1);
    }
    __syncthreads();
    uint32_t tmem;
    asm volatile("ld.shared.b32 %0, [%1];" : "=r"(tmem) : "r"(tmem_slot));

    const int r = tid >> 2;
    const int q = tid & 3;
    const uint32_t* bsrc = p.bpk + (size_t)(bn * 128 + r) * p.Kdim;
    const int NC = p.NC;

    auto fillB = [&](int st, int kc) {
        char* Bhi = smem_al + (st ? SME_B1 : SME_B0);
        char* Blo = Bhi + 16384;
        const uint32_t* src = bsrc + kc * 64 + q * 16;
        uint32_t buf[16];
#pragma unroll
        for (int i = 0; i < 4; i++)
            *reinterpret_cast<uint4*>(&buf[i * 4]) =
                *reinterpret_cast<const uint4*>(src + i * 4);
#pragma unroll
        for (int i = 0; i < 8; i++) {
            int kk = q * 16 + 2 * i;
            uint32_t v0 = buf[2 * i], v1 = buf[2 * i + 1];
            uint32_t off = r * 128 + kk * 2;
            uint32_t sw = off ^ ((off >> 3) & 0x70);
            *reinterpret_cast<uint32_t*>(Bhi + sw) = __byte_perm(v0, v1, 0x7632);
            *reinterpret_cast<uint32_t*>(Blo + sw) = __byte_perm(v0, v1, 0x5410);
        }
    };

    int wpar = 0;
    auto waitCommits = [&](int target) {
        while (wpar < target) {
            MBARRIER_WAIT_PARITY(mbar + 8 * (wpar & 3), (wpar >> 2) & 1);
            wpar++;
        }
    };

    fillB(0, 0);

    for (int kc = 0; kc < NC; kc++) {
        int st = kc & 1;
#pragma unroll
        for (int bm = 0; bm < BM; bm++) {
            int ni = kc * BM + bm;
            if (ni >= 1) waitCommits(ni);
            if (wid == 0 && elect_one()) {
                const uint8_t* asrc =
                    p.wpk + ((size_t)(mblk0 + bm) * NC + kc) * 32768;
                MBARRIER_EXPECT_TX(ambar, 32768);
                CP_BULK_G2S(sb + SME_A, asrc, 32768, ambar);
            }
            MBARRIER_WAIT_PARITY(ambar, ni & 1);
            FENCE_PROXY_ASYNC();
            __syncthreads();
            if (wid == 0 && elect_one()) {
                uint64_t dAh = make_desc(sb + SME_A);
                uint64_t dAl = dAh + (16384 >> 4);
                uint64_t dBh = make_desc(sb + (st ? SME_B1 : SME_B0));
                uint64_t dBl = dBh + (16384 >> 4);
                uint32_t d = tmem + bm * 128;
                uint32_t first = (kc == 0) ? 0u : 1u;
#pragma unroll
                for (int s = 0; s < 4; s++) {
                    uint64_t o = s * 2;
                    mma_f16_ss(d, dAh + o, dBh + o, CONV_IDESC, first); first = 1;
                    mma_f16_ss(d, dAh + o, dBl + o, CONV_IDESC, 1);
                    mma_f16_ss(d, dAl + o, dBh + o, CONV_IDESC, 1);
                }
                TCGEN05_COMMIT(mbar + 8 * (ni & 3));
            }
        }
        if (kc + 1 < NC) fillB(st ^ 1, kc + 1);
    }
    waitCommits(NC * BM);
    TCGEN05_FENCE_AFTER();

    {
        const int sp = wid & 3;
        const int cb = wid >> 2;
        const int t0 = bn * 128 + cb * 32;
        if (p.mode == 0) {
#pragma unroll
            for (int bm = 0; bm < BM; bm++) {
                const int m = (mblk0 + bm) * 128 + sp * 32 + lane;
                const float bv = p.bias[m];
                uint32_t dr[32];
                TCGEN05_LD_X32(dr, tmem + bm * 128 + cb * 32);
                TCGEN05_WAIT_LD();
                const bool kplane = p.kpl && m >= 512 && m < 1024;
#pragma unroll
                for (int j = 0; j < 32; j++) {
                    float v = __uint_as_float(dr[j]) + bv;
                    p.out[(size_t)(t0 + j) * p.J + m] = v;
                    if (kplane) {
                        float vhi = __shfl_down_sync(0xffffffffu, v, 1);
                        if ((lane & 1) == 0) {
                            __nv_bfloat162 b2 =
                                __float22bfloat162_rn(make_float2(v, vhi));
                            p.kpl[(size_t)(t0 + j) * 256 + ((m - 512) >> 1)] =
                                *reinterpret_cast<uint32_t*>(&b2);
                        }
                    }
                }
            }
        } else {
            float* stage = reinterpret_cast<float*>(smem_al);   // [128][129]
#pragma unroll
            for (int bm = 0; bm < BM; bm++) {
                uint32_t dr[32];
                TCGEN05_LD_X32(dr, tmem + bm * 128 + cb * 32);
                TCGEN05_WAIT_LD();
                __syncthreads();
                int srow = sp * 32 + lane;
#pragma unroll
                for (int j = 0; j < 32; j++)
                    stage[srow * 129 + cb * 32 + j] = __uint_as_float(dr[j]);
                __syncthreads();
#pragma unroll
                for (int rr = 0; rr < 8; rr++) {
                    int ml = wid * 8 + rr;
                    int m = (mblk0 + bm) * 128 + ml;
                    float bv = p.bias[m];
                    float* orow = p.out + (size_t)m * p.T + bn * 128;
#pragma unroll
                    for (int part = 0; part < 4; part++) {
                        int col = part * 32 + lane;
                        orow[col] += stage[ml * 129 + col] + bv;
                    }
                }
            }
        }
        TCGEN05_FENCE_BEFORE();
    }
    __syncthreads();
    if (tid == 0) {
#pragma unroll
        for (int i = 0; i < 4; i++) MBARRIER_INVAL(mbar + 8 * i);
        MBARRIER_INVAL(ambar);
    }
    if (wid == 0) TCGEN05_DEALLOC(tmem, 256);

#else  // FFMA fallback
    for (int bm = 0; bm < BM; bm++) {
        int m_base = (mblk0 + bm) * 128;
        for (int idx = tid; idx < 128 * 128; idx += 512) {
            int tl = idx >> 7, jl = idx & 127;
            int t = bn * 128 + tl, j = m_base + jl;
            float s = 0.f;
            for (int k = 0; k < p.Kdim; k++)
                s += unpack_hl(p.bpk[(size_t)t * p.Kdim + k]) * p.wf[(size_t)k * p.J + j];
            s += p.bias[j];
            if (p.mode == 0) {
                p.out[(size_t)t * p.J + j] = s;
                if (p.kpl && j >= 512 && j < 1024 && (j & 1) == 0) {
                    float s1 = 0.f;
                    for (int k = 0; k < p.Kdim; k++)
                        s1 += unpack_hl(p.bpk[(size_t)t * p.Kdim + k]) *
                              p.wf[(size_t)k * p.J + j + 1];
                    s1 += p.bias[j + 1];
                    __nv_bfloat162 b2 = __float22bfloat162_rn(make_float2(s, s1));
                    p.kpl[(size_t)t * 256 + ((j - 512) >> 1)] =
                        *reinterpret_cast<uint32_t*>(&b2);
                }
            } else {
                p.out[(size_t)j * p.T + t] += s;
            }
        }
    }
#endif
}

// ---------------------------------------------------------------------------
// LayerNorm: fp32 channel-major -> packed token-major
// ---------------------------------------------------------------------------
__global__ __launch_bounds__(256) void layernorm_kernel(
    const float* __restrict__ x, const float* __restrict__ g,
    const float* __restrict__ b, uint32_t* __restrict__ ypk, int T) {
    const int tx = threadIdx.x;
    const int ty = threadIdx.y;
    const int t = blockIdx.x * 32 + tx;

    float s = 0.f, ss = 0.f;
#pragma unroll
    for (int i = 0; i < 64; i++) {
        int c = ty * 64 + i;
        float v = x[(size_t)c * T + t];
        s += v; ss += v * v;
    }
    __shared__ float shs[8][32], shss[8][32];
    __shared__ float smu[32], srs[32];
    shs[ty][tx] = s; shss[ty][tx] = ss;
    __syncthreads();
    if (ty == 0) {
        float S = 0.f, SS = 0.f;
#pragma unroll
        for (int j = 0; j < 8; j++) { S += shs[j][tx]; SS += shss[j][tx]; }
        float mu = S * (1.f / 512.f);
        float var = SS * (1.f / 512.f) - mu * mu;
        smu[tx] = mu;
        srs[tx] = rsqrtf(var + 1e-5f);
    }
    __syncthreads();
    float mu = smu[tx], rs = srs[tx];
    uint32_t* yrow = ypk + (size_t)t * 512 + ty * 64;
#pragma unroll
    for (int i = 0; i < 64; i++) {
        int c = ty * 64 + i;
        float v = x[(size_t)c * T + t];
        yrow[i] = pack_hl((v - mu) * rs * g[c] + b[c]);
    }
}

// ---------------------------------------------------------------------------
// Neighborhood attention — shfl-broadcast neighbor indices, lean score loop.
// ---------------------------------------------------------------------------
__global__ __launch_bounds__(256) void natt_kernel(
    const float* __restrict__ qkv, uint32_t* __restrict__ atpk) {
    __shared__ float tsh[8][32][33];

    const int warp = threadIdx.x >> 5;
    const int lane = threadIdx.x & 31;
    const int t = blockIdx.x * 8 + warp;
    const int hd = blockIdx.y;
    const int d = t >> 11;
    const int hh = (t >> 6) & 31;
    const int ww = t & 63;

    float2 q2 = *reinterpret_cast<const float2*>(
        qkv + (size_t)t * 1536 + hd * 64 + 2 * lane);
    q2.x *= 0.125f; q2.y *= 0.125f;

    // each lane decodes its own neighbor for each batch once
    int ntreg[8];
    float sc[8];
    float m = -1e30f;
#pragma unroll
    for (int it = 0; it < 8; it++) {
        int nb = it * 32 + lane;
        int myNt = -1;
        if (nb < 245) {
            int pk = g_npack[nb];
            int nd = d + (pk >> 16) - 2;
            int nh = hh + ((pk >> 8) & 255) - 3;
            int nw = ww + (pk & 255) - 3;
            if ((unsigned)nd < 4u && (unsigned)nh < 32u && (unsigned)nw < 64u)
                myNt = (nd * 32 + nh) * 64 + nw;
        }
        ntreg[it] = myNt;
        // score partials: lane = channel pair, neighbor index via shfl
#pragma unroll
        for (int j = 0; j < 32; j++) {
            int nt = __shfl_sync(0xffffffffu, myNt, j);
            float pv = 0.f;
            if (nt >= 0) {
                uint32_t kw32 = g_kpl[(size_t)nt * 256 + hd * 32 + lane];
                float2 kf = __bfloat1622float2(
                    *reinterpret_cast<__nv_bfloat162*>(&kw32));
                pv = fmaf(q2.x, kf.x, q2.y * kf.y);
            }
            tsh[warp][j][lane] = pv;
        }
        __syncwarp();
        float s = 0.f;
#pragma unroll
        for (int j = 0; j < 32; j++) s += tsh[warp][lane][j];
        __syncwarp();
        float dot = (myNt >= 0) ? s : -1e30f;
        sc[it] = dot;
        m = fmaxf(m, dot);
    }
#pragma unroll
    for (int o = 16; o; o >>= 1) m = fmaxf(m, __shfl_xor_sync(0xffffffffu, m, o));

    float l = 0.f;
#pragma unroll
    for (int it = 0; it < 8; it++) {
        float e = (sc[it] > -1e29f) ? __expf(sc[it] - m) : 0.f;
        sc[it] = e;     // reuse as exp weight
        l += e;
    }
#pragma unroll
    for (int o = 16; o; o >>= 1) l += __shfl_xor_sync(0xffffffffu, l, o);

    // PV phase: both neighbor index and weight broadcast via shfl
    float acc0 = 0.f, acc1 = 0.f;
#pragma unroll
    for (int it = 0; it < 8; it++) {
        float ei = sc[it];
        int nti = ntreg[it];
#pragma unroll 4
        for (int j = 0; j < 32; j++) {
            int nt = __shfl_sync(0xffffffffu, nti, j);
            float pb = __shfl_sync(0xffffffffu, ei, j);
            if (nt >= 0) {
                float2 vv = *reinterpret_cast<const float2*>(
                    qkv + (size_t)nt * 1536 + 1024 + hd * 64 + 2 * lane);
                acc0 = fmaf(pb, vv.x, acc0);
                acc1 = fmaf(pb, vv.y, acc1);
            }
        }
    }
    float inv = 1.f / l;
    uint32_t* op = atpk + (size_t)t * 512 + hd * 64;
    op[2 * lane] = pack_hl(acc0 * inv);
    op[2 * lane + 1] = pack_hl(acc1 * inv);
}

// ---------------------------------------------------------------------------
// Host launcher
// ---------------------------------------------------------------------------
extern "C" void kernel_launch(void* const* d_in, const int* in_sizes, int n_in,
                              void* d_out, int out_size) {
    const float* x2d  = (const float*)d_in[0];
    const float* x3d  = (const float*)d_in[1];
    const float* sw0  = (const float*)d_in[2];  const float* sb0 = (const float*)d_in[3];
    const float* sw1  = (const float*)d_in[4];  const float* sb1 = (const float*)d_in[5];
    const float* sw2  = (const float*)d_in[6];  const float* sb2 = (const float*)d_in[7];
    const float* pw0  = (const float*)d_in[8];  const float* pb0 = (const float*)d_in[9];
    const float* pw1  = (const float*)d_in[10]; const float* pb1 = (const float*)d_in[11];
    const float* pw2  = (const float*)d_in[12]; const float* pb2 = (const float*)d_in[13];
    const float* latw = (const float*)d_in[14]; const float* latb = (const float*)d_in[15];
    const float* lng  = (const float*)d_in[16]; const float* lnb  = (const float*)d_in[17];
    const float* qkvw = (const float*)d_in[18]; const float* qkvb = (const float*)d_in[19];
    const float* pjw  = (const float*)d_in[20]; const float* pjb  = (const float*)d_in[21];
    float* lat = (float*)d_out;

    uint32_t *pkA, *pkB, *pkF, *pkX, *ynpk, *atpk, *kpl;
    float *qkvB;
    uint8_t *wpk2;
    cudaGetSymbolAddress((void**)&pkA, g_pk_a);
    cudaGetSymbolAddress((void**)&pkB, g_pk_b);
    cudaGetSymbolAddress((void**)&pkF, g_pk_f);
    cudaGetSymbolAddress((void**)&pkX, g_pk_x2d);
    cudaGetSymbolAddress((void**)&ynpk, g_ynpk);
    cudaGetSymbolAddress((void**)&qkvB, g_qkv);
    cudaGetSymbolAddress((void**)&atpk, g_atpk);
    cudaGetSymbolAddress((void**)&kpl, g_kpl);
    cudaGetSymbolAddress((void**)&wpk2, g_wpk2);

    cudaFuncSetAttribute(conv_mma_kernel<1>,
                         cudaFuncAttributeMaxDynamicSharedMemorySize, CONV_SMEM_BYTES);
    cudaFuncSetAttribute(conv_mma_kernel<2>,
                         cudaFuncAttributeMaxDynamicSharedMemorySize, CONV_SMEM_BYTES);
    cudaFuncSetAttribute(tok_mma_kernel<1>,
                         cudaFuncAttributeMaxDynamicSharedMemorySize, CONV_SMEM_BYTES);
    cudaFuncSetAttribute(tok_mma_kernel<2>,
                         cudaFuncAttributeMaxDynamicSharedMemorySize, CONV_SMEM_BYTES);

    auto run_conv = [&](const uint32_t* xpk, const float* wf, const float* bias,
                        uint32_t* outpk, float* outf,
                        int Cin, int D, int H, int W, int Dout, int Hout, int Wout,
                        int KD, int KH, int KW, int sd, int sh, int sw,
                        int pd, int ph, int pw, int Cout,
                        int outStrideC, int outOffset, int gelu) {
        int K = Cin * KD * KH * KW;
        int NC = (K + 63) / 64;
        wpack_kernel<<<dim3(NC, Cout / 128), 256>>>(wf, K, NC, KD * KH * KW,
                                                    KH * KW, KW, D, H, W);
        int Nvox = Dout * Hout * Wout;
        ConvParams p{ xpk, wf, bias, outpk, outf,
                      D, H, W, Hout, Wout, sd, sh, sw, pd, ph, pw,
                      K, NC, outStrideC, outOffset, gelu };
        int nblk = Cout / 128;
        int bn = Nvox / 128;
        if (nblk % 2 == 0 && bn * (nblk / 2) >= 256)
            conv_mma_kernel<2><<<dim3(bn, nblk / 2), 512, CONV_SMEM_BYTES>>>(p);
        else
            conv_mma_kernel<1><<<dim3(bn, nblk), 512, CONV_SMEM_BYTES>>>(p);
    };

    natt_table_kernel<<<1, 256>>>();
    xpack_kernel<<<(5 * 24 * 256 * 512 / 4 + 255) / 256, 256>>>(
        x3d, pkA, 5 * 24 * 256 * 512 / 4);
    xpack_kernel<<<(8 * 256 * 512 / 4 + 255) / 256, 256>>>(
        x2d, pkX, 8 * 256 * 512 / 4);

    // ---- 3D tower ----
    run_conv(pkA, pw0, pb0, pkB, nullptr, 5, 24, 256, 512, 12, 128, 256,
             3, 3, 3, 2, 2, 2, 1, 1, 1, 128, 393216, 0, 1);
    run_conv(pkB, pw1, pb1, pkA, nullptr, 128, 12, 128, 256, 6, 64, 128,
             3, 3, 3, 2, 2, 2, 1, 1, 1, 256, 49152, 0, 1);
    run_conv(pkA, pw2, pb2, pkF, nullptr, 256, 6, 64, 128, 3, 32, 64,
             3, 3, 3, 2, 2, 2, 1, 1, 1, 512, 8192, 0, 1);

    // ---- 2D tower ----
    run_conv(pkX, sw0, sb0, pkB, nullptr, 8, 1, 256, 512, 1, 128, 256,
             1, 3, 3, 1, 2, 2, 0, 1, 1, 128, 32768, 0, 1);
    run_conv(pkB, sw1, sb1, pkA, nullptr, 128, 1, 128, 256, 1, 64, 128,
             1, 3, 3, 1, 2, 2, 0, 1, 1, 256, 8192, 0, 1);
    run_conv(pkA, sw2, sb2, pkF, nullptr, 256, 1, 64, 128, 1, 32, 64,
             1, 3, 3, 1, 2, 2, 0, 1, 1, 512, 8192, 3 * 2048, 1);

    // ---- lateral 1x1x1 -> d_out fp32 ----
    run_conv(pkF, latw, latb, nullptr, lat, 512, 4, 32, 64, 4, 32, 64,
             1, 1, 1, 1, 1, 1, 0, 0, 0, 512, 8192, 0, 0);

    // ---- attention weight prepack ----
    const size_t QKV_PK = 8 * 12 * 32768;
    const size_t PRJ_PK = 8 * 4 * 32768;
    for (int i = 0; i < 3; i++) {
        wpackT_kernel<<<dim3(8, 12), 256>>>(qkvw + (size_t)i * 512 * 1536,
                                            wpk2 + i * QKV_PK, 512, 8, 1536);
        wpackT_kernel<<<dim3(8, 4), 256>>>(pjw + (size_t)i * 512 * 512,
                                           wpk2 + 3 * QKV_PK + i * PRJ_PK, 512, 8, 512);
    }

    // ---- 3 neighborhood-attention blocks ----
    for (int i = 0; i < 3; i++) {
        layernorm_kernel<<<8192 / 32, dim3(32, 8)>>>(lat, lng + i * 512, lnb + i * 512,
                                                     ynpk, 8192);
        TokParams pq{ ynpk, wpk2 + i * QKV_PK, qkvw + (size_t)i * 512 * 1536,
                      qkvb + i * 1536, qkvB, kpl, 8192, 1536, 512, 8, 0 };
        tok_mma_kernel<2><<<dim3(8192 / 128, 6), 512, CONV_SMEM_BYTES>>>(pq);
        natt_kernel<<<dim3(1024, 8), 256>>>(qkvB, atpk);
        TokParams pp{ atpk, wpk2 + 3 * QKV_PK + i * PRJ_PK,
                      pjw + (size_t)i * 512 * 512,
                      pjb + i * 512, lat, nullptr, 8192, 512, 512, 8, 1 };
        tok_mma_kernel<1><<<dim3(8192 / 128, 4), 512, CONV_SMEM_BYTES>>>(pp);
    }
}

// round 16
// speedup vs baseline: 1.9209x; 1.0370x over previous
#include <cuda_runtime.h>
#include <cuda_bf16.h>
#include <math.h>
#include <cstdint>

#if defined(__CUDA_ARCH_SPECIFIC__) || defined(__CUDA_ARCH_FEAT_SM103_ALL)
#define HAS_TCGEN05 1
#else
#define HAS_TCGEN05 0
#endif

// ---------------------------------------------------------------------------
// Scratch buffers (packed u32 = bf16 hi << 16 | bf16 lo)
// ---------------------------------------------------------------------------
__device__ uint32_t g_pk_a[15728640];
__device__ uint32_t g_pk_b[50331648];
__device__ uint32_t g_pk_f[4194304];
__device__ uint32_t g_pk_x2d[1048576];
__device__ uint8_t  g_wpk[14155776];
__device__ uint8_t  g_wpk2[12582912];
__device__ uint32_t g_ynpk[8192 * 512];
__device__ float    g_qkv[8192 * 1536];
__device__ uint32_t g_kpl[8192 * 256];   // K-plane bf16x2 for natt score
__device__ uint32_t g_atpk[8192 * 512];
__device__ int2     g_dec[8192];
__device__ int      g_npack[256];

// ---------------------------------------------------------------------------
// Common helpers
// ---------------------------------------------------------------------------
__device__ __forceinline__ uint32_t smem_u32(const void* p) {
    uint32_t a;
    asm("{ .reg .u64 t; cvta.to.shared.u64 t, %1; cvt.u32.u64 %0, t; }"
        : "=r"(a) : "l"(p));
    return a;
}
__device__ __forceinline__ float gelu_tanh(float x) {
    float x3 = x * x * x;
    float t = tanhf(0.7978845608028654f * (x + 0.044715f * x3));
    return 0.5f * x * (1.0f + t);
}
__device__ __forceinline__ uint32_t pack_hl(float f) {
    __nv_bfloat16 h = __float2bfloat16(f);
    __nv_bfloat16 l = __float2bfloat16(f - __bfloat162float(h));
    return ((uint32_t)__bfloat16_as_ushort(h) << 16) | __bfloat16_as_ushort(l);
}
__device__ __forceinline__ float unpack_hl(uint32_t v) {
    float h = __bfloat162float(__ushort_as_bfloat16((unsigned short)(v >> 16)));
    float l = __bfloat162float(__ushort_as_bfloat16((unsigned short)(v & 0xFFFF)));
    return h + l;
}

#if HAS_TCGEN05
__device__ __forceinline__ uint32_t elect_one() {
    uint32_t pred;
    asm volatile("{ .reg .pred p; elect.sync _|p, 0xFFFFFFFF; selp.b32 %0, 1, 0, p; }"
                 : "=r"(pred));
    return pred;
}
#define TCGEN05_ALLOC(a, n) \
    asm volatile("tcgen05.alloc.cta_group::1.sync.aligned.shared::cta.b32 [%0], %1;" \
                 :: "r"((uint32_t)(a)), "r"((uint32_t)(n)) : "memory")
#define TCGEN05_DEALLOC(t, n) \
    asm volatile("tcgen05.dealloc.cta_group::1.sync.aligned.b32 %0, %1;" :: "r"(t), "r"(n))
#define TCGEN05_RELINQ() \
    asm volatile("tcgen05.relinquish_alloc_permit.cta_group::1.sync.aligned;")
#define TCGEN05_COMMIT(m) \
    asm volatile("tcgen05.commit.cta_group::1.mbarrier::arrive::one.shared::cluster.b64 [%0];" \
                 :: "r"((uint32_t)(m)) : "memory")
#define TCGEN05_FENCE_AFTER() \
    asm volatile("tcgen05.fence::after_thread_sync;" ::: "memory")
#define TCGEN05_FENCE_BEFORE() \
    asm volatile("tcgen05.fence::before_thread_sync;" ::: "memory")
#define TCGEN05_WAIT_LD() asm volatile("tcgen05.wait::ld.sync.aligned;" ::: "memory")
#define FENCE_PROXY_ASYNC() asm volatile("fence.proxy.async.shared::cta;" ::: "memory")
#define MBARRIER_INIT(m, c) \
    asm volatile("mbarrier.init.shared.b64 [%0], %1;" :: "r"((uint32_t)(m)), "r"((uint32_t)(c)) : "memory")
#define MBARRIER_INVAL(m) \
    asm volatile("mbarrier.inval.shared.b64 [%0];" :: "r"((uint32_t)(m)) : "memory")
#define MBARRIER_EXPECT_TX(m, b) \
    asm volatile("mbarrier.arrive.expect_tx.shared.b64 _, [%0], %1;" \
                 :: "r"((uint32_t)(m)), "r"((uint32_t)(b)) : "memory")
#define CP_BULK_G2S(dst, src, nbytes, mbar) \
    asm volatile("cp.async.bulk.shared::cta.global.mbarrier::complete_tx::bytes [%0], [%1], %2, [%3];" \
                 :: "r"((uint32_t)(dst)), "l"(src), "r"((uint32_t)(nbytes)), \
                    "r"((uint32_t)(mbar)) : "memory")
#define MBARRIER_WAIT_PARITY(m, ph) do {                                           \
    uint32_t _m = (uint32_t)(m), _p = (uint32_t)(ph), _d;                          \
    asm volatile("{ .reg .pred p; mbarrier.try_wait.parity.acquire.cta.shared::cta.b64 p, [%1], %2;" \
                 " selp.b32 %0, 1, 0, p; }" : "=r"(_d) : "r"(_m), "r"(_p) : "memory"); \
    if (!_d) {                                                                     \
        asm volatile("{ .reg .pred P1; WL_%=: mbarrier.try_wait.parity.acquire.cta.shared::cta.b64 P1, [%0], %1, 0x989680;" \
                     " @P1 bra.uni WD_%=; bra.uni WL_%=; WD_%=: }"                 \
                     :: "r"(_m), "r"(_p) : "memory");                              \
    }                                                                              \
} while (0)
#define TCGEN05_LD_X32(r, a)                                                       \
    asm volatile("tcgen05.ld.sync.aligned.32x32b.x32.b32 "                         \
        "{%0, %1, %2, %3, %4, %5, %6, %7, %8, %9, %10, %11, %12, %13, %14, %15, "  \
        " %16, %17, %18, %19, %20, %21, %22, %23, %24, %25, %26, %27, %28, %29, %30, %31}, [%32];" \
        : "=r"((r)[0]), "=r"((r)[1]), "=r"((r)[2]), "=r"((r)[3]),                  \
          "=r"((r)[4]), "=r"((r)[5]), "=r"((r)[6]), "=r"((r)[7]),                  \
          "=r"((r)[8]), "=r"((r)[9]), "=r"((r)[10]), "=r"((r)[11]),                \
          "=r"((r)[12]), "=r"((r)[13]), "=r"((r)[14]), "=r"((r)[15]),              \
          "=r"((r)[16]), "=r"((r)[17]), "=r"((r)[18]), "=r"((r)[19]),              \
          "=r"((r)[20]), "=r"((r)[21]), "=r"((r)[22]), "=r"((r)[23]),              \
          "=r"((r)[24]), "=r"((r)[25]), "=r"((r)[26]), "=r"((r)[27]),              \
          "=r"((r)[28]), "=r"((r)[29]), "=r"((r)[30]), "=r"((r)[31])               \
        : "r"(a))

static constexpr uint64_t SMEM_DESC_BASE_SW128 =
    (uint64_t(2) << 61) | (uint64_t(1) << 46) | (uint64_t(64) << 32) | (uint64_t(1) << 16);
__device__ __forceinline__ uint64_t make_desc(uint32_t addr) {
    return SMEM_DESC_BASE_SW128 | ((uint64_t)(addr >> 4) & 0x3FFF);
}
__device__ __forceinline__ void mma_f16_ss(uint32_t d, uint64_t ad, uint64_t bd,
                                           uint32_t idesc, uint32_t en) {
    asm volatile(
        "{ .reg .pred p; setp.ne.u32 p, %5, 0;\n\t"
        "tcgen05.mma.cta_group::1.kind::f16 [%0], %1, %2, %3, {%4, %4, %4, %4}, p; }"
        :: "r"(d), "l"(ad), "l"(bd), "r"(idesc), "r"(0u), "r"(en) : "memory");
}
static constexpr uint32_t CONV_IDESC =
    (1u << 4) | (1u << 7) | (1u << 10) | ((128u / 8) << 17) | ((128u / 16) << 24);
#endif // HAS_TCGEN05

#define SME_A 0
#define SME_B0 32768
#define SME_B1 65536
#define SME_MBAR 98304
#define SME_AMBAR 98336
#define SME_TSLOT 98344
#define CONV_SMEM_BYTES (1024 + 98304 + 128)
#define LN_SMEM_BYTES (32 * 513 * 4)

// ---------------------------------------------------------------------------
// Init / pack kernels
// ---------------------------------------------------------------------------
__global__ void natt_table_kernel() {
    int nb = threadIdx.x;
    if (nb < 245) {
        int od = nb / 49; int r = nb - od * 49;
        int oh = r / 7;   int ow = r - oh * 7;
        g_npack[nb] = (od << 16) | (oh << 8) | ow;
    }
}

__global__ void xpack_kernel(const float* __restrict__ x,
                             uint32_t* __restrict__ dst, int n4) {
    int i = blockIdx.x * 256 + threadIdx.x;
    if (i >= n4) return;
    float4 v = reinterpret_cast<const float4*>(x)[i];
    uint4 o;
    o.x = pack_hl(v.x); o.y = pack_hl(v.y);
    o.z = pack_hl(v.z); o.w = pack_hl(v.w);
    reinterpret_cast<uint4*>(dst)[i] = o;
}

// weight prepack; bm==0 blocks also decode their k-chunk of g_dec
__global__ void wpack_kernel(const float* __restrict__ w, int K, int NC,
                             int KV, int KHW, int KW, int D, int H, int W) {
    int kc = blockIdx.x, bm = blockIdx.y;
    int tid = threadIdx.x;
    if (bm == 0 && tid < 64) {
        int k = kc * 64 + tid;
        if (k < K) {
            int ci = k / KV; int tap = k - ci * KV;
            int kd = tap / KHW; int t2 = tap - kd * KHW;
            int kh = t2 / KW; int kw = t2 - kh * KW;
            g_dec[k] = make_int2(((ci * D + kd) * H + kh) * W + kw,
                                 (kd << 20) | (kh << 10) | kw);
        } else {
            g_dec[k] = make_int2(0, 1023 << 20);
        }
    }
    int r = tid >> 1, half = tid & 1;
    const float* wrow = w + (size_t)(bm * 128 + r) * K;
    uint8_t* hi = g_wpk + (size_t)(bm * NC + kc) * 32768;
    uint8_t* lo = hi + 16384;
#pragma unroll
    for (int i = 0; i < 16; i++) {
        int kk = half * 32 + 2 * i;
        int k = kc * 64 + kk;
        float a0 = (k < K) ? wrow[k] : 0.f;
        float a1 = (k + 1 < K) ? wrow[k + 1] : 0.f;
        uint32_t p0 = pack_hl(a0), p1 = pack_hl(a1);
        uint32_t hp = __byte_perm(p0, p1, 0x7632);
        uint32_t lp = __byte_perm(p0, p1, 0x5410);
        uint32_t off = r * 128 + kk * 2;
        uint32_t sw = off ^ ((off >> 3) & 0x70);
        *reinterpret_cast<uint32_t*>(hi + sw) = hp;
        *reinterpret_cast<uint32_t*>(lo + sw) = lp;
    }
}

__global__ void wpackT_kernel(const float* __restrict__ w, uint8_t* dst,
                              int K, int NC, int J) {
    int kc = blockIdx.x, bm = blockIdx.y;
    int tid = threadIdx.x;
    int r = tid >> 1, half = tid & 1;
    int m = bm * 128 + r;
    uint8_t* hi = dst + (size_t)(bm * NC + kc) * 32768;
    uint8_t* lo = hi + 16384;
#pragma unroll
    for (int i = 0; i < 16; i++) {
        int kk = half * 32 + 2 * i;
        int k = kc * 64 + kk;
        float a0 = (k < K) ? w[(size_t)k * J + m] : 0.f;
        float a1 = (k + 1 < K) ? w[(size_t)(k + 1) * J + m] : 0.f;
        uint32_t p0 = pack_hl(a0), p1 = pack_hl(a1);
        uint32_t hp = __byte_perm(p0, p1, 0x7632);
        uint32_t lp = __byte_perm(p0, p1, 0x5410);
        uint32_t off = r * 128 + kk * 2;
        uint32_t sw = off ^ ((off >> 3) & 0x70);
        *reinterpret_cast<uint32_t*>(hi + sw) = hp;
        *reinterpret_cast<uint32_t*>(lo + sw) = lp;
    }
}

// ---------------------------------------------------------------------------
// Conv kernel: bulk-copied A, double-buffered B gather, TMEM 256, 2 CTA/SM.
// ---------------------------------------------------------------------------
struct ConvParams {
    const uint32_t* xpk;
    const float* wf;
    const float* bias;
    uint32_t* outpk;
    float* outf;
    int D, H, W;
    int Hout, Wout;
    int sd, sh, sw, pd, ph, pw;
    int K, NC;
    int outStrideC, outOffset;
    int gelu;
};

template <int BM>
__global__ __launch_bounds__(512, 2) void conv_mma_kernel(ConvParams p) {
    extern __shared__ char smem_raw[];
    char* smem_al = (char*)(((uintptr_t)smem_raw + 1023) & ~(uintptr_t)1023);

    const int tid = threadIdx.x;
    const int bn = blockIdx.x;
    const int mblk0 = blockIdx.y * BM;
    const int HWo = p.Hout * p.Wout;

#if HAS_TCGEN05
    const uint32_t sb = smem_u32(smem_al);
    const uint32_t mbar = sb + SME_MBAR;
    const uint32_t ambar = sb + SME_AMBAR;
    const uint32_t tmem_slot = sb + SME_TSLOT;
    const int wid = tid >> 5;
    const int lane = tid & 31;

    if (wid == 0) {
        TCGEN05_ALLOC(tmem_slot, 256);
        TCGEN05_RELINQ();
    }
    if (tid == 0) {
#pragma unroll
        for (int i = 0; i < 4; i++) MBARRIER_INIT(mbar + 8 * i, 1);
        MBARRIER_INIT(ambar, 1);
    }
    __syncthreads();
    uint32_t tmem;
    asm volatile("ld.shared.b32 %0, [%1];" : "=r"(tmem) : "r"(tmem_slot));

    const int r = tid >> 2;
    const int q = tid & 3;
    const int n = bn * 128 + r;
    const int od = n / HWo; int rr2 = n - od * HWo;
    const int oh = rr2 / p.Wout; const int ow = rr2 - oh * p.Wout;
    const int id0 = od * p.sd - p.pd;
    const int ih0 = oh * p.sh - p.ph;
    const int iw0 = ow * p.sw - p.pw;
    const int gbase = (id0 * p.H + ih0) * p.W + iw0;
    const int NC = p.NC;

    auto fillB = [&](int st, int kc) {
        char* Bhi = smem_al + (st ? SME_B1 : SME_B0);
        char* Blo = Bhi + 16384;
        const int kt = kc * 64;
#pragma unroll
        for (int i = 0; i < 8; i++) {
            int kk = q * 16 + 2 * i;
            int k = kt + kk;
            int4 dv = *reinterpret_cast<const int4*>(&g_dec[k]);
            uint32_t v0 = 0, v1 = 0;
            {
                int kd = dv.y >> 20, kh = (dv.y >> 10) & 1023, kw = dv.y & 1023;
                if ((unsigned)(id0 + kd) < (unsigned)p.D &&
                    (unsigned)(ih0 + kh) < (unsigned)p.H &&
                    (unsigned)(iw0 + kw) < (unsigned)p.W)
                    v0 = p.xpk[gbase + dv.x];
            }
            {
                int kd = dv.w >> 20, kh = (dv.w >> 10) & 1023, kw = dv.w & 1023;
                if ((unsigned)(id0 + kd) < (unsigned)p.D &&
                    (unsigned)(ih0 + kh) < (unsigned)p.H &&
                    (unsigned)(iw0 + kw) < (unsigned)p.W)
                    v1 = p.xpk[gbase + dv.z];
            }
            uint32_t off = r * 128 + kk * 2;
            uint32_t sw = off ^ ((off >> 3) & 0x70);
            *reinterpret_cast<uint32_t*>(Bhi + sw) = __byte_perm(v0, v1, 0x7632);
            *reinterpret_cast<uint32_t*>(Blo + sw) = __byte_perm(v0, v1, 0x5410);
        }
    };

    int wpar = 0;
    auto waitCommits = [&](int target) {
        while (wpar < target) {
            MBARRIER_WAIT_PARITY(mbar + 8 * (wpar & 3), (wpar >> 2) & 1);
            wpar++;
        }
    };

    fillB(0, 0);

    for (int kc = 0; kc < NC; kc++) {
        int st = kc & 1;
#pragma unroll
        for (int bm = 0; bm < BM; bm++) {
            int ni = kc * BM + bm;
            if (ni >= 1) waitCommits(ni);
            if (wid == 0 && elect_one()) {
                const uint8_t* asrc =
                    g_wpk + ((size_t)(mblk0 + bm) * NC + kc) * 32768;
                MBARRIER_EXPECT_TX(ambar, 32768);
                CP_BULK_G2S(sb + SME_A, asrc, 32768, ambar);
            }
            MBARRIER_WAIT_PARITY(ambar, ni & 1);
            FENCE_PROXY_ASYNC();
            __syncthreads();
            if (wid == 0 && elect_one()) {
                uint64_t dAh = make_desc(sb + SME_A);
                uint64_t dAl = dAh + (16384 >> 4);
                uint64_t dBh = make_desc(sb + (st ? SME_B1 : SME_B0));
                uint64_t dBl = dBh + (16384 >> 4);
                uint32_t d = tmem + bm * 128;
                uint32_t first = (kc == 0) ? 0u : 1u;
#pragma unroll
                for (int s = 0; s < 4; s++) {
                    uint64_t o = s * 2;
                    mma_f16_ss(d, dAh + o, dBh + o, CONV_IDESC, first); first = 1;
                    mma_f16_ss(d, dAh + o, dBl + o, CONV_IDESC, 1);
                    mma_f16_ss(d, dAl + o, dBh + o, CONV_IDESC, 1);
                }
                TCGEN05_COMMIT(mbar + 8 * (ni & 3));
            }
        }
        if (kc + 1 < NC) fillB(st ^ 1, kc + 1);
    }
    waitCommits(NC * BM);
    TCGEN05_FENCE_AFTER();

    // ---- smem-staged coalesced epilogue ----
    {
        float* stage = reinterpret_cast<float*>(smem_al);   // [128][129]
        const int sp = wid & 3;
        const int cb = wid >> 2;
#pragma unroll
        for (int bm = 0; bm < BM; bm++) {
            uint32_t dr[32];
            TCGEN05_LD_X32(dr, tmem + bm * 128 + cb * 32);
            TCGEN05_WAIT_LD();
            __syncthreads();
            int srow = sp * 32 + lane;
#pragma unroll
            for (int j = 0; j < 32; j++)
                stage[srow * 129 + cb * 32 + j] = __uint_as_float(dr[j]);
            __syncthreads();
#pragma unroll
            for (int rr = 0; rr < 8; rr++) {
                int ml = wid * 8 + rr;
                int m = (mblk0 + bm) * 128 + ml;
                float bv = p.bias[m];
                size_t obase = (size_t)m * p.outStrideC + p.outOffset + bn * 128;
#pragma unroll
                for (int part = 0; part < 4; part++) {
                    float v = stage[ml * 129 + part * 32 + lane] + bv;
                    if (p.gelu) v = gelu_tanh(v);
                    if (p.outpk) p.outpk[obase + part * 32 + lane] = pack_hl(v);
                    else p.outf[obase + part * 32 + lane] = v;
                }
            }
        }
        TCGEN05_FENCE_BEFORE();
    }
    __syncthreads();
    if (tid == 0) {
#pragma unroll
        for (int i = 0; i < 4; i++) MBARRIER_INVAL(mbar + 8 * i);
        MBARRIER_INVAL(ambar);
    }
    if (wid == 0) TCGEN05_DEALLOC(tmem, 256);

#else  // FFMA fallback (never executes on GB300)
    for (int bm = 0; bm < BM; bm++) {
        const int m_base = (mblk0 + bm) * 128;
        for (int idx = tid; idx < 128 * 128; idx += 512) {
            int ml = idx >> 7, nl = idx & 127;
            int m = m_base + ml;
            int nn = bn * 128 + nl;
            int od = nn / HWo; int rr2 = nn - od * HWo;
            int oh = rr2 / p.Wout; int ow = rr2 - oh * p.Wout;
            int id0 = od * p.sd - p.pd, ih0 = oh * p.sh - p.ph, iw0 = ow * p.sw - p.pw;
            int gb = (id0 * p.H + ih0) * p.W + iw0;
            float s = 0.f;
            for (int k = 0; k < p.K; k++) {
                int2 dv = g_dec[k];
                int kd = dv.y >> 20, kh = (dv.y >> 10) & 1023, kw = dv.y & 1023;
                if ((unsigned)(id0 + kd) < (unsigned)p.D &&
                    (unsigned)(ih0 + kh) < (unsigned)p.H &&
                    (unsigned)(iw0 + kw) < (unsigned)p.W)
                    s += p.wf[(size_t)m * p.K + k] * unpack_hl(p.xpk[gb + dv.x]);
            }
            s += p.bias[m];
            if (p.gelu) s = gelu_tanh(s);
            size_t ob = (size_t)m * p.outStrideC + p.outOffset + nn;
            if (p.outpk) p.outpk[ob] = pack_hl(s);
            else p.outf[ob] = s;
        }
    }
#endif
}

// ---------------------------------------------------------------------------
// Token GEMM: bulk-copied A; mode-0 fuses K-plane emission; mode-1 staged.
// ---------------------------------------------------------------------------
struct TokParams {
    const uint32_t* bpk;
    const uint8_t* wpk;
    const float* wf;
    const float* bias;
    float* out;
    uint32_t* kpl;
    int T, J, Kdim, NC, mode;
};

template <int BM>
__global__ __launch_bounds__(512, 2) void tok_mma_kernel(TokParams p) {
    extern __shared__ char smem_raw[];
    char* smem_al = (char*)(((uintptr_t)smem_raw + 1023) & ~(uintptr_t)1023);

    const int tid = threadIdx.x;
    const int bn = blockIdx.x;
    const int mblk0 = blockIdx.y * BM;

#if HAS_TCGEN05
    const uint32_t sb = smem_u32(smem_al);
    const uint32_t mbar = sb + SME_MBAR;
    const uint32_t ambar = sb + SME_AMBAR;
    const uint32_t tmem_slot = sb + SME_TSLOT;
    const int wid = tid >> 5;
    const int lane = tid & 31;

    if (wid == 0) {
        TCGEN05_ALLOC(tmem_slot, 256);
        TCGEN05_RELINQ();
    }
    if (tid == 0) {
#pragma unroll
        for (int i = 0; i < 4; i++) MBARRIER_INIT(mbar + 8 * i, 1);
        MBARRIER_INIT(ambar, 1);
    }
    __syncthreads();
    uint32_t tmem;
    asm volatile("ld.shared.b32 %0, [%1];" : "=r"(tmem) : "r"(tmem_slot));

    const int r = tid >> 2;
    const int q = tid & 3;
    const uint32_t* bsrc = p.bpk + (size_t)(bn * 128 + r) * p.Kdim;
    const int NC = p.NC;

    auto fillB = [&](int st, int kc) {
        char* Bhi = smem_al + (st ? SME_B1 : SME_B0);
        char* Blo = Bhi + 16384;
        const uint32_t* src = bsrc + kc * 64 + q * 16;
        uint32_t buf[16];
#pragma unroll
        for (int i = 0; i < 4; i++)
            *reinterpret_cast<uint4*>(&buf[i * 4]) =
                *reinterpret_cast<const uint4*>(src + i * 4);
#pragma unroll
        for (int i = 0; i < 8; i++) {
            int kk = q * 16 + 2 * i;
            uint32_t v0 = buf[2 * i], v1 = buf[2 * i + 1];
            uint32_t off = r * 128 + kk * 2;
            uint32_t sw = off ^ ((off >> 3) & 0x70);
            *reinterpret_cast<uint32_t*>(Bhi + sw) = __byte_perm(v0, v1, 0x7632);
            *reinterpret_cast<uint32_t*>(Blo + sw) = __byte_perm(v0, v1, 0x5410);
        }
    };

    int wpar = 0;
    auto waitCommits = [&](int target) {
        while (wpar < target) {
            MBARRIER_WAIT_PARITY(mbar + 8 * (wpar & 3), (wpar >> 2) & 1);
            wpar++;
        }
    };

    fillB(0, 0);

    for (int kc = 0; kc < NC; kc++) {
        int st = kc & 1;
#pragma unroll
        for (int bm = 0; bm < BM; bm++) {
            int ni = kc * BM + bm;
            if (ni >= 1) waitCommits(ni);
            if (wid == 0 && elect_one()) {
                const uint8_t* asrc =
                    p.wpk + ((size_t)(mblk0 + bm) * NC + kc) * 32768;
                MBARRIER_EXPECT_TX(ambar, 32768);
                CP_BULK_G2S(sb + SME_A, asrc, 32768, ambar);
            }
            MBARRIER_WAIT_PARITY(ambar, ni & 1);
            FENCE_PROXY_ASYNC();
            __syncthreads();
            if (wid == 0 && elect_one()) {
                uint64_t dAh = make_desc(sb + SME_A);
                uint64_t dAl = dAh + (16384 >> 4);
                uint64_t dBh = make_desc(sb + (st ? SME_B1 : SME_B0));
                uint64_t dBl = dBh + (16384 >> 4);
                uint32_t d = tmem + bm * 128;
                uint32_t first = (kc == 0) ? 0u : 1u;
#pragma unroll
                for (int s = 0; s < 4; s++) {
                    uint64_t o = s * 2;
                    mma_f16_ss(d, dAh + o, dBh + o, CONV_IDESC, first); first = 1;
                    mma_f16_ss(d, dAh + o, dBl + o, CONV_IDESC, 1);
                    mma_f16_ss(d, dAl + o, dBh + o, CONV_IDESC, 1);
                }
                TCGEN05_COMMIT(mbar + 8 * (ni & 3));
            }
        }
        if (kc + 1 < NC) fillB(st ^ 1, kc + 1);
    }
    waitCommits(NC * BM);
    TCGEN05_FENCE_AFTER();

    {
        const int sp = wid & 3;
        const int cb = wid >> 2;
        const int t0 = bn * 128 + cb * 32;
        if (p.mode == 0) {
#pragma unroll
            for (int bm = 0; bm < BM; bm++) {
                const int m = (mblk0 + bm) * 128 + sp * 32 + lane;
                const float bv = p.bias[m];
                uint32_t dr[32];
                TCGEN05_LD_X32(dr, tmem + bm * 128 + cb * 32);
                TCGEN05_WAIT_LD();
                const bool kplane = p.kpl && m >= 512 && m < 1024;
#pragma unroll
                for (int j = 0; j < 32; j++) {
                    float v = __uint_as_float(dr[j]) + bv;
                    p.out[(size_t)(t0 + j) * p.J + m] = v;
                    if (kplane) {
                        float vhi = __shfl_down_sync(0xffffffffu, v, 1);
                        if ((lane & 1) == 0) {
                            __nv_bfloat162 b2 =
                                __float22bfloat162_rn(make_float2(v, vhi));
                            p.kpl[(size_t)(t0 + j) * 256 + ((m - 512) >> 1)] =
                                *reinterpret_cast<uint32_t*>(&b2);
                        }
                    }
                }
            }
        } else {
            float* stage = reinterpret_cast<float*>(smem_al);   // [128][129]
#pragma unroll
            for (int bm = 0; bm < BM; bm++) {
                uint32_t dr[32];
                TCGEN05_LD_X32(dr, tmem + bm * 128 + cb * 32);
                TCGEN05_WAIT_LD();
                __syncthreads();
                int srow = sp * 32 + lane;
#pragma unroll
                for (int j = 0; j < 32; j++)
                    stage[srow * 129 + cb * 32 + j] = __uint_as_float(dr[j]);
                __syncthreads();
#pragma unroll
                for (int rr = 0; rr < 8; rr++) {
                    int ml = wid * 8 + rr;
                    int m = (mblk0 + bm) * 128 + ml;
                    float bv = p.bias[m];
                    float* orow = p.out + (size_t)m * p.T + bn * 128;
#pragma unroll
                    for (int part = 0; part < 4; part++) {
                        int col = part * 32 + lane;
                        orow[col] += stage[ml * 129 + col] + bv;
                    }
                }
            }
        }
        TCGEN05_FENCE_BEFORE();
    }
    __syncthreads();
    if (tid == 0) {
#pragma unroll
        for (int i = 0; i < 4; i++) MBARRIER_INVAL(mbar + 8 * i);
        MBARRIER_INVAL(ambar);
    }
    if (wid == 0) TCGEN05_DEALLOC(tmem, 256);

#else  // FFMA fallback
    for (int bm = 0; bm < BM; bm++) {
        int m_base = (mblk0 + bm) * 128;
        for (int idx = tid; idx < 128 * 128; idx += 512) {
            int tl = idx >> 7, jl = idx & 127;
            int t = bn * 128 + tl, j = m_base + jl;
            float s = 0.f;
            for (int k = 0; k < p.Kdim; k++)
                s += unpack_hl(p.bpk[(size_t)t * p.Kdim + k]) * p.wf[(size_t)k * p.J + j];
            s += p.bias[j];
            if (p.mode == 0) {
                p.out[(size_t)t * p.J + j] = s;
                if (p.kpl && j >= 512 && j < 1024 && (j & 1) == 0) {
                    float s1 = 0.f;
                    for (int k = 0; k < p.Kdim; k++)
                        s1 += unpack_hl(p.bpk[(size_t)t * p.Kdim + k]) *
                              p.wf[(size_t)k * p.J + j + 1];
                    s1 += p.bias[j + 1];
                    __nv_bfloat162 b2 = __float22bfloat162_rn(make_float2(s, s1));
                    p.kpl[(size_t)t * 256 + ((j - 512) >> 1)] =
                        *reinterpret_cast<uint32_t*>(&b2);
                }
            } else {
                p.out[(size_t)j * p.T + t] += s;
            }
        }
    }
#endif
}

// ---------------------------------------------------------------------------
// LayerNorm: fp32 channel-major -> packed token-major, smem-staged writes.
// Dynamic smem stage [32 tokens][513] u32.
// ---------------------------------------------------------------------------
__global__ __launch_bounds__(256) void layernorm_kernel(
    const float* __restrict__ x, const float* __restrict__ g,
    const float* __restrict__ b, uint32_t* __restrict__ ypk, int T) {
    extern __shared__ uint32_t ystage[];    // [32][513]
    const int tx = threadIdx.x & 31;
    const int ty = threadIdx.x >> 5;
    const int t = blockIdx.x * 32 + tx;

    float s = 0.f, ss = 0.f;
#pragma unroll
    for (int i = 0; i < 64; i++) {
        int c = ty * 64 + i;
        float v = x[(size_t)c * T + t];
        s += v; ss += v * v;
    }
    __shared__ float shs[8][32], shss[8][32];
    __shared__ float smu[32], srs[32];
    shs[ty][tx] = s; shss[ty][tx] = ss;
    __syncthreads();
    if (ty == 0) {
        float S = 0.f, SS = 0.f;
#pragma unroll
        for (int j = 0; j < 8; j++) { S += shs[j][tx]; SS += shss[j][tx]; }
        float mu = S * (1.f / 512.f);
        float var = SS * (1.f / 512.f) - mu * mu;
        smu[tx] = mu;
        srs[tx] = rsqrtf(var + 1e-5f);
    }
    __syncthreads();
    float mu = smu[tx], rs = srs[tx];
#pragma unroll
    for (int i = 0; i < 64; i++) {
        int c = ty * 64 + i;
        float v = x[(size_t)c * T + t];
        ystage[tx * 513 + c] = pack_hl((v - mu) * rs * g[c] + b[c]);
    }
    __syncthreads();
    // write out: each warp owns 4 tokens, lane = channel (coalesced 128B lines)
    const int warp = threadIdx.x >> 5;
    const int lane = threadIdx.x & 31;
#pragma unroll
    for (int k = 0; k < 4; k++) {
        int tt = warp * 4 + k;
        uint32_t* yr = ypk + (size_t)(blockIdx.x * 32 + tt) * 512;
#pragma unroll
        for (int i = 0; i < 16; i++)
            yr[i * 32 + lane] = ystage[tt * 513 + i * 32 + lane];
    }
}

// ---------------------------------------------------------------------------
// Neighborhood attention — shfl-broadcast neighbor indices, lean score loop.
// ---------------------------------------------------------------------------
__global__ __launch_bounds__(256) void natt_kernel(
    const float* __restrict__ qkv, uint32_t* __restrict__ atpk) {
    __shared__ float tsh[8][32][33];

    const int warp = threadIdx.x >> 5;
    const int lane = threadIdx.x & 31;
    const int t = blockIdx.x * 8 + warp;
    const int hd = blockIdx.y;
    const int d = t >> 11;
    const int hh = (t >> 6) & 31;
    const int ww = t & 63;

    float2 q2 = *reinterpret_cast<const float2*>(
        qkv + (size_t)t * 1536 + hd * 64 + 2 * lane);
    q2.x *= 0.125f; q2.y *= 0.125f;

    int ntreg[8];
    float sc[8];
    float m = -1e30f;
#pragma unroll
    for (int it = 0; it < 8; it++) {
        int nb = it * 32 + lane;
        int myNt = -1;
        if (nb < 245) {
            int pk = g_npack[nb];
            int nd = d + (pk >> 16) - 2;
            int nh = hh + ((pk >> 8) & 255) - 3;
            int nw = ww + (pk & 255) - 3;
            if ((unsigned)nd < 4u && (unsigned)nh < 32u && (unsigned)nw < 64u)
                myNt = (nd * 32 + nh) * 64 + nw;
        }
        ntreg[it] = myNt;
#pragma unroll
        for (int j = 0; j < 32; j++) {
            int nt = __shfl_sync(0xffffffffu, myNt, j);
            float pv = 0.f;
            if (nt >= 0) {
                uint32_t kw32 = g_kpl[(size_t)nt * 256 + hd * 32 + lane];
                float2 kf = __bfloat1622float2(
                    *reinterpret_cast<__nv_bfloat162*>(&kw32));
                pv = fmaf(q2.x, kf.x, q2.y * kf.y);
            }
            tsh[warp][j][lane] = pv;
        }
        __syncwarp();
        float s = 0.f;
#pragma unroll
        for (int j = 0; j < 32; j++) s += tsh[warp][lane][j];
        __syncwarp();
        float dot = (myNt >= 0) ? s : -1e30f;
        sc[it] = dot;
        m = fmaxf(m, dot);
    }
#pragma unroll
    for (int o = 16; o; o >>= 1) m = fmaxf(m, __shfl_xor_sync(0xffffffffu, m, o));

    float l = 0.f;
#pragma unroll
    for (int it = 0; it < 8; it++) {
        float e = (sc[it] > -1e29f) ? __expf(sc[it] - m) : 0.f;
        sc[it] = e;
        l += e;
    }
#pragma unroll
    for (int o = 16; o; o >>= 1) l += __shfl_xor_sync(0xffffffffu, l, o);

    float acc0 = 0.f, acc1 = 0.f;
#pragma unroll
    for (int it = 0; it < 8; it++) {
        float ei = sc[it];
        int nti = ntreg[it];
#pragma unroll 4
        for (int j = 0; j < 32; j++) {
            int nt = __shfl_sync(0xffffffffu, nti, j);
            float pb = __shfl_sync(0xffffffffu, ei, j);
            if (nt >= 0) {
                float2 vv = *reinterpret_cast<const float2*>(
                    qkv + (size_t)nt * 1536 + 1024 + hd * 64 + 2 * lane);
                acc0 = fmaf(pb, vv.x, acc0);
                acc1 = fmaf(pb, vv.y, acc1);
            }
        }
    }
    float inv = 1.f / l;
    uint2 ov;
    ov.x = pack_hl(acc0 * inv);
    ov.y = pack_hl(acc1 * inv);
    *reinterpret_cast<uint2*>(atpk + (size_t)t * 512 + hd * 64 + 2 * lane) = ov;
}

// ---------------------------------------------------------------------------
// Host launcher
// ---------------------------------------------------------------------------
extern "C" void kernel_launch(void* const* d_in, const int* in_sizes, int n_in,
                              void* d_out, int out_size) {
    const float* x2d  = (const float*)d_in[0];
    const float* x3d  = (const float*)d_in[1];
    const float* sw0  = (const float*)d_in[2];  const float* sb0 = (const float*)d_in[3];
    const float* sw1  = (const float*)d_in[4];  const float* sb1 = (const float*)d_in[5];
    const float* sw2  = (const float*)d_in[6];  const float* sb2 = (const float*)d_in[7];
    const float* pw0  = (const float*)d_in[8];  const float* pb0 = (const float*)d_in[9];
    const float* pw1  = (const float*)d_in[10]; const float* pb1 = (const float*)d_in[11];
    const float* pw2  = (const float*)d_in[12]; const float* pb2 = (const float*)d_in[13];
    const float* latw = (const float*)d_in[14]; const float* latb = (const float*)d_in[15];
    const float* lng  = (const float*)d_in[16]; const float* lnb  = (const float*)d_in[17];
    const float* qkvw = (const float*)d_in[18]; const float* qkvb = (const float*)d_in[19];
    const float* pjw  = (const float*)d_in[20]; const float* pjb  = (const float*)d_in[21];
    float* lat = (float*)d_out;

    uint32_t *pkA, *pkB, *pkF, *pkX, *ynpk, *atpk, *kpl;
    float *qkvB;
    uint8_t *wpk2;
    cudaGetSymbolAddress((void**)&pkA, g_pk_a);
    cudaGetSymbolAddress((void**)&pkB, g_pk_b);
    cudaGetSymbolAddress((void**)&pkF, g_pk_f);
    cudaGetSymbolAddress((void**)&pkX, g_pk_x2d);
    cudaGetSymbolAddress((void**)&ynpk, g_ynpk);
    cudaGetSymbolAddress((void**)&qkvB, g_qkv);
    cudaGetSymbolAddress((void**)&atpk, g_atpk);
    cudaGetSymbolAddress((void**)&kpl, g_kpl);
    cudaGetSymbolAddress((void**)&wpk2, g_wpk2);

    cudaFuncSetAttribute(conv_mma_kernel<1>,
                         cudaFuncAttributeMaxDynamicSharedMemorySize, CONV_SMEM_BYTES);
    cudaFuncSetAttribute(conv_mma_kernel<2>,
                         cudaFuncAttributeMaxDynamicSharedMemorySize, CONV_SMEM_BYTES);
    cudaFuncSetAttribute(tok_mma_kernel<1>,
                         cudaFuncAttributeMaxDynamicSharedMemorySize, CONV_SMEM_BYTES);
    cudaFuncSetAttribute(tok_mma_kernel<2>,
                         cudaFuncAttributeMaxDynamicSharedMemorySize, CONV_SMEM_BYTES);
    cudaFuncSetAttribute(layernorm_kernel,
                         cudaFuncAttributeMaxDynamicSharedMemorySize, LN_SMEM_BYTES);

    auto run_conv = [&](const uint32_t* xpk, const float* wf, const float* bias,
                        uint32_t* outpk, float* outf,
                        int Cin, int D, int H, int W, int Dout, int Hout, int Wout,
                        int KD, int KH, int KW, int sd, int sh, int sw,
                        int pd, int ph, int pw, int Cout,
                        int outStrideC, int outOffset, int gelu) {
        int K = Cin * KD * KH * KW;
        int NC = (K + 63) / 64;
        wpack_kernel<<<dim3(NC, Cout / 128), 256>>>(wf, K, NC, KD * KH * KW,
                                                    KH * KW, KW, D, H, W);
        int Nvox = Dout * Hout * Wout;
        ConvParams p{ xpk, wf, bias, outpk, outf,
                      D, H, W, Hout, Wout, sd, sh, sw, pd, ph, pw,
                      K, NC, outStrideC, outOffset, gelu };
        int nblk = Cout / 128;
        int bn = Nvox / 128;
        if (nblk % 2 == 0 && bn * (nblk / 2) >= 256)
            conv_mma_kernel<2><<<dim3(bn, nblk / 2), 512, CONV_SMEM_BYTES>>>(p);
        else
            conv_mma_kernel<1><<<dim3(bn, nblk), 512, CONV_SMEM_BYTES>>>(p);
    };

    natt_table_kernel<<<1, 256>>>();
    xpack_kernel<<<(5 * 24 * 256 * 512 / 4 + 255) / 256, 256>>>(
        x3d, pkA, 5 * 24 * 256 * 512 / 4);
    xpack_kernel<<<(8 * 256 * 512 / 4 + 255) / 256, 256>>>(
        x2d, pkX, 8 * 256 * 512 / 4);

    // ---- 3D tower ----
    run_conv(pkA, pw0, pb0, pkB, nullptr, 5, 24, 256, 512, 12, 128, 256,
             3, 3, 3, 2, 2, 2, 1, 1, 1, 128, 393216, 0, 1);
    run_conv(pkB, pw1, pb1, pkA, nullptr, 128, 12, 128, 256, 6, 64, 128,
             3, 3, 3, 2, 2, 2, 1, 1, 1, 256, 49152, 0, 1);
    run_conv(pkA, pw2, pb2, pkF, nullptr, 256, 6, 64, 128, 3, 32, 64,
             3, 3, 3, 2, 2, 2, 1, 1, 1, 512, 8192, 0, 1);

    // ---- 2D tower ----
    run_conv(pkX, sw0, sb0, pkB, nullptr, 8, 1, 256, 512, 1, 128, 256,
             1, 3, 3, 1, 2, 2, 0, 1, 1, 128, 32768, 0, 1);
    run_conv(pkB, sw1, sb1, pkA, nullptr, 128, 1, 128, 256, 1, 64, 128,
             1, 3, 3, 1, 2, 2, 0, 1, 1, 256, 8192, 0, 1);
    run_conv(pkA, sw2, sb2, pkF, nullptr, 256, 1, 64, 128, 1, 32, 64,
             1, 3, 3, 1, 2, 2, 0, 1, 1, 512, 8192, 3 * 2048, 1);

    // ---- lateral 1x1x1 -> d_out fp32 ----
    run_conv(pkF, latw, latb, nullptr, lat, 512, 4, 32, 64, 4, 32, 64,
             1, 1, 1, 1, 1, 1, 0, 0, 0, 512, 8192, 0, 0);

    // ---- attention weight prepack ----
    const size_t QKV_PK = 8 * 12 * 32768;
    const size_t PRJ_PK = 8 * 4 * 32768;
    for (int i = 0; i < 3; i++) {
        wpackT_kernel<<<dim3(8, 12), 256>>>(qkvw + (size_t)i * 512 * 1536,
                                            wpk2 + i * QKV_PK, 512, 8, 1536);
        wpackT_kernel<<<dim3(8, 4), 256>>>(pjw + (size_t)i * 512 * 512,
                                           wpk2 + 3 * QKV_PK + i * PRJ_PK, 512, 8, 512);
    }

    // ---- 3 neighborhood-attention blocks ----
    for (int i = 0; i < 3; i++) {
        layernorm_kernel<<<8192 / 32, 256, LN_SMEM_BYTES>>>(
            lat, lng + i * 512, lnb + i * 512, ynpk, 8192);
        TokParams pq{ ynpk, wpk2 + i * QKV_PK, qkvw + (size_t)i * 512 * 1536,
                      qkvb + i * 1536, qkvB, kpl, 8192, 1536, 512, 8, 0 };
        tok_mma_kernel<2><<<dim3(8192 / 128, 6), 512, CONV_SMEM_BYTES>>>(pq);
        natt_kernel<<<dim3(1024, 8), 256>>>(qkvB, atpk);
        TokParams pp{ atpk, wpk2 + 3 * QKV_PK + i * PRJ_PK,
                      pjw + (size_t)i * 512 * 512,
                      pjb + i * 512, lat, nullptr, 8192, 512, 512, 8, 1 };
        tok_mma_kernel<1><<<dim3(8192 / 128, 4), 512, CONV_SMEM_BYTES>>>(pp);
    }
}

// round 17
// speedup vs baseline: 1.9543x; 1.0174x over previous
#include <cuda_runtime.h>
#include <cuda_bf16.h>
#include <math.h>
#include <cstdint>

#if defined(__CUDA_ARCH_SPECIFIC__) || defined(__CUDA_ARCH_FEAT_SM103_ALL)
#define HAS_TCGEN05 1
#else
#define HAS_TCGEN05 0
#endif

// ---------------------------------------------------------------------------
// Scratch buffers (packed u32 = bf16 hi << 16 | bf16 lo)
// ---------------------------------------------------------------------------
__device__ uint32_t g_pk_a[15728640];
__device__ uint32_t g_pk_b[50331648];
__device__ uint32_t g_pk_f[4194304];
__device__ uint32_t g_pk_x2d[1048576];
__device__ uint8_t  g_wpk[14155776];
__device__ uint8_t  g_wpk2[12582912];
__device__ uint32_t g_ynpk[8192 * 512];
__device__ float    g_qkv[8192 * 1536];
__device__ uint32_t g_kpl[8192 * 256];   // K-plane bf16x2 for natt score
__device__ uint32_t g_atpk[8192 * 512];
__device__ int2     g_dec[8192];

// ---------------------------------------------------------------------------
// Common helpers
// ---------------------------------------------------------------------------
__device__ __forceinline__ uint32_t smem_u32(const void* p) {
    uint32_t a;
    asm("{ .reg .u64 t; cvta.to.shared.u64 t, %1; cvt.u32.u64 %0, t; }"
        : "=r"(a) : "l"(p));
    return a;
}
__device__ __forceinline__ float gelu_tanh(float x) {
    float x3 = x * x * x;
    float t = tanhf(0.7978845608028654f * (x + 0.044715f * x3));
    return 0.5f * x * (1.0f + t);
}
__device__ __forceinline__ uint32_t pack_hl(float f) {
    __nv_bfloat16 h = __float2bfloat16(f);
    __nv_bfloat16 l = __float2bfloat16(f - __bfloat162float(h));
    return ((uint32_t)__bfloat16_as_ushort(h) << 16) | __bfloat16_as_ushort(l);
}
__device__ __forceinline__ float unpack_hl(uint32_t v) {
    float h = __bfloat162float(__ushort_as_bfloat16((unsigned short)(v >> 16)));
    float l = __bfloat162float(__ushort_as_bfloat16((unsigned short)(v & 0xFFFF)));
    return h + l;
}

#if HAS_TCGEN05
__device__ __forceinline__ uint32_t elect_one() {
    uint32_t pred;
    asm volatile("{ .reg .pred p; elect.sync _|p, 0xFFFFFFFF; selp.b32 %0, 1, 0, p; }"
                 : "=r"(pred));
    return pred;
}
#define TCGEN05_ALLOC(a, n) \
    asm volatile("tcgen05.alloc.cta_group::1.sync.aligned.shared::cta.b32 [%0], %1;" \
                 :: "r"((uint32_t)(a)), "r"((uint32_t)(n)) : "memory")
#define TCGEN05_DEALLOC(t, n) \
    asm volatile("tcgen05.dealloc.cta_group::1.sync.aligned.b32 %0, %1;" :: "r"(t), "r"(n))
#define TCGEN05_RELINQ() \
    asm volatile("tcgen05.relinquish_alloc_permit.cta_group::1.sync.aligned;")
#define TCGEN05_COMMIT(m) \
    asm volatile("tcgen05.commit.cta_group::1.mbarrier::arrive::one.shared::cluster.b64 [%0];" \
                 :: "r"((uint32_t)(m)) : "memory")
#define TCGEN05_FENCE_AFTER() \
    asm volatile("tcgen05.fence::after_thread_sync;" ::: "memory")
#define TCGEN05_FENCE_BEFORE() \
    asm volatile("tcgen05.fence::before_thread_sync;" ::: "memory")
#define TCGEN05_WAIT_LD() asm volatile("tcgen05.wait::ld.sync.aligned;" ::: "memory")
#define FENCE_PROXY_ASYNC() asm volatile("fence.proxy.async.shared::cta;" ::: "memory")
#define MBARRIER_INIT(m, c) \
    asm volatile("mbarrier.init.shared.b64 [%0], %1;" :: "r"((uint32_t)(m)), "r"((uint32_t)(c)) : "memory")
#define MBARRIER_INVAL(m) \
    asm volatile("mbarrier.inval.shared.b64 [%0];" :: "r"((uint32_t)(m)) : "memory")
#define MBARRIER_EXPECT_TX(m, b) \
    asm volatile("mbarrier.arrive.expect_tx.shared.b64 _, [%0], %1;" \
                 :: "r"((uint32_t)(m)), "r"((uint32_t)(b)) : "memory")
#define CP_BULK_G2S(dst, src, nbytes, mbar) \
    asm volatile("cp.async.bulk.shared::cta.global.mbarrier::complete_tx::bytes [%0], [%1], %2, [%3];" \
                 :: "r"((uint32_t)(dst)), "l"(src), "r"((uint32_t)(nbytes)), \
                    "r"((uint32_t)(mbar)) : "memory")
#define MBARRIER_WAIT_PARITY(m, ph) do {                                           \
    uint32_t _m = (uint32_t)(m), _p = (uint32_t)(ph), _d;                          \
    asm volatile("{ .reg .pred p; mbarrier.try_wait.parity.acquire.cta.shared::cta.b64 p, [%1], %2;" \
                 " selp.b32 %0, 1, 0, p; }" : "=r"(_d) : "r"(_m), "r"(_p) : "memory"); \
    if (!_d) {                                                                     \
        asm volatile("{ .reg .pred P1; WL_%=: mbarrier.try_wait.parity.acquire.cta.shared::cta.b64 P1, [%0], %1, 0x989680;" \
                     " @P1 bra.uni WD_%=; bra.uni WL_%=; WD_%=: }"                 \
                     :: "r"(_m), "r"(_p) : "memory");                              \
    }                                                                              \
} while (0)
#define TCGEN05_LD_X32(r, a)                                                       \
    asm volatile("tcgen05.ld.sync.aligned.32x32b.x32.b32 "                         \
        "{%0, %1, %2, %3, %4, %5, %6, %7, %8, %9, %10, %11, %12, %13, %14, %15, "  \
        " %16, %17, %18, %19, %20, %21, %22, %23, %24, %25, %26, %27, %28, %29, %30, %31}, [%32];" \
        : "=r"((r)[0]), "=r"((r)[1]), "=r"((r)[2]), "=r"((r)[3]),                  \
          "=r"((r)[4]), "=r"((r)[5]), "=r"((r)[6]), "=r"((r)[7]),                  \
          "=r"((r)[8]), "=r"((r)[9]), "=r"((r)[10]), "=r"((r)[11]),                \
          "=r"((r)[12]), "=r"((r)[13]), "=r"((r)[14]), "=r"((r)[15]),              \
          "=r"((r)[16]), "=r"((r)[17]), "=r"((r)[18]), "=r"((r)[19]),              \
          "=r"((r)[20]), "=r"((r)[21]), "=r"((r)[22]), "=r"((r)[23]),              \
          "=r"((r)[24]), "=r"((r)[25]), "=r"((r)[26]), "=r"((r)[27]),              \
          "=r"((r)[28]), "=r"((r)[29]), "=r"((r)[30]), "=r"((r)[31])               \
        : "r"(a))

static constexpr uint64_t SMEM_DESC_BASE_SW128 =
    (uint64_t(2) << 61) | (uint64_t(1) << 46) | (uint64_t(64) << 32) | (uint64_t(1) << 16);
__device__ __forceinline__ uint64_t make_desc(uint32_t addr) {
    return SMEM_DESC_BASE_SW128 | ((uint64_t)(addr >> 4) & 0x3FFF);
}
__device__ __forceinline__ void mma_f16_ss(uint32_t d, uint64_t ad, uint64_t bd,
                                           uint32_t idesc, uint32_t en) {
    asm volatile(
        "{ .reg .pred p; setp.ne.u32 p, %5, 0;\n\t"
        "tcgen05.mma.cta_group::1.kind::f16 [%0], %1, %2, %3, {%4, %4, %4, %4}, p; }"
        :: "r"(d), "l"(ad), "l"(bd), "r"(idesc), "r"(0u), "r"(en) : "memory");
}
static constexpr uint32_t CONV_IDESC =
    (1u << 4) | (1u << 7) | (1u << 10) | ((128u / 8) << 17) | ((128u / 16) << 24);
#endif // HAS_TCGEN05

#define SME_A 0
#define SME_B0 32768
#define SME_B1 65536
#define SME_MBAR 98304
#define SME_AMBAR 98336
#define SME_TSLOT 98344
#define CONV_SMEM_BYTES (1024 + 98304 + 128)
#define LN_SMEM_BYTES (32 * 513 * 4)

// ---------------------------------------------------------------------------
// Init / pack kernels
// ---------------------------------------------------------------------------
__global__ void xpack_kernel(const float* __restrict__ x,
                             uint32_t* __restrict__ dst, int n4) {
    int i = blockIdx.x * 256 + threadIdx.x;
    if (i >= n4) return;
    float4 v = reinterpret_cast<const float4*>(x)[i];
    uint4 o;
    o.x = pack_hl(v.x); o.y = pack_hl(v.y);
    o.z = pack_hl(v.z); o.w = pack_hl(v.w);
    reinterpret_cast<uint4*>(dst)[i] = o;
}

// weight prepack; bm==0 blocks also decode their k-chunk of g_dec
__global__ void wpack_kernel(const float* __restrict__ w, int K, int NC,
                             int KV, int KHW, int KW, int D, int H, int W) {
    int kc = blockIdx.x, bm = blockIdx.y;
    int tid = threadIdx.x;
    if (bm == 0 && tid < 64) {
        int k = kc * 64 + tid;
        if (k < K) {
            int ci = k / KV; int tap = k - ci * KV;
            int kd = tap / KHW; int t2 = tap - kd * KHW;
            int kh = t2 / KW; int kw = t2 - kh * KW;
            g_dec[k] = make_int2(((ci * D + kd) * H + kh) * W + kw,
                                 (kd << 20) | (kh << 10) | kw);
        } else {
            g_dec[k] = make_int2(0, 1023 << 20);
        }
    }
    int r = tid >> 1, half = tid & 1;
    const float* wrow = w + (size_t)(bm * 128 + r) * K;
    uint8_t* hi = g_wpk + (size_t)(bm * NC + kc) * 32768;
    uint8_t* lo = hi + 16384;
#pragma unroll
    for (int i = 0; i < 16; i++) {
        int kk = half * 32 + 2 * i;
        int k = kc * 64 + kk;
        float a0 = (k < K) ? wrow[k] : 0.f;
        float a1 = (k + 1 < K) ? wrow[k + 1] : 0.f;
        uint32_t p0 = pack_hl(a0), p1 = pack_hl(a1);
        uint32_t hp = __byte_perm(p0, p1, 0x7632);
        uint32_t lp = __byte_perm(p0, p1, 0x5410);
        uint32_t off = r * 128 + kk * 2;
        uint32_t sw = off ^ ((off >> 3) & 0x70);
        *reinterpret_cast<uint32_t*>(hi + sw) = hp;
        *reinterpret_cast<uint32_t*>(lo + sw) = lp;
    }
}

__global__ void wpackT_kernel(const float* __restrict__ w, uint8_t* dst,
                              int K, int NC, int J) {
    int kc = blockIdx.x, bm = blockIdx.y;
    int tid = threadIdx.x;
    int r = tid >> 1, half = tid & 1;
    int m = bm * 128 + r;
    uint8_t* hi = dst + (size_t)(bm * NC + kc) * 32768;
    uint8_t* lo = hi + 16384;
#pragma unroll
    for (int i = 0; i < 16; i++) {
        int kk = half * 32 + 2 * i;
        int k = kc * 64 + kk;
        float a0 = (k < K) ? w[(size_t)k * J + m] : 0.f;
        float a1 = (k + 1 < K) ? w[(size_t)(k + 1) * J + m] : 0.f;
        uint32_t p0 = pack_hl(a0), p1 = pack_hl(a1);
        uint32_t hp = __byte_perm(p0, p1, 0x7632);
        uint32_t lp = __byte_perm(p0, p1, 0x5410);
        uint32_t off = r * 128 + kk * 2;
        uint32_t sw = off ^ ((off >> 3) & 0x70);
        *reinterpret_cast<uint32_t*>(hi + sw) = hp;
        *reinterpret_cast<uint32_t*>(lo + sw) = lp;
    }
}

// ---------------------------------------------------------------------------
// Conv kernel: bulk-copied A, double-buffered B gather, TMEM 256, 2 CTA/SM.
// ---------------------------------------------------------------------------
struct ConvParams {
    const uint32_t* xpk;
    const float* wf;
    const float* bias;
    uint32_t* outpk;
    float* outf;
    int D, H, W;
    int Hout, Wout;
    int sd, sh, sw, pd, ph, pw;
    int K, NC;
    int outStrideC, outOffset;
    int gelu;
};

template <int BM>
__global__ __launch_bounds__(512, 2) void conv_mma_kernel(ConvParams p) {
    extern __shared__ char smem_raw[];
    char* smem_al = (char*)(((uintptr_t)smem_raw + 1023) & ~(uintptr_t)1023);

    const int tid = threadIdx.x;
    const int bn = blockIdx.x;
    const int mblk0 = blockIdx.y * BM;
    const int HWo = p.Hout * p.Wout;

#if HAS_TCGEN05
    const uint32_t sb = smem_u32(smem_al);
    const uint32_t mbar = sb + SME_MBAR;
    const uint32_t ambar = sb + SME_AMBAR;
    const uint32_t tmem_slot = sb + SME_TSLOT;
    const int wid = tid >> 5;
    const int lane = tid & 31;

    if (wid == 0) {
        TCGEN05_ALLOC(tmem_slot, 256);
        TCGEN05_RELINQ();
    }
    if (tid == 0) {
#pragma unroll
        for (int i = 0; i < 4; i++) MBARRIER_INIT(mbar + 8 * i, 1);
        MBARRIER_INIT(ambar, 1);
    }
    __syncthreads();
    uint32_t tmem;
    asm volatile("ld.shared.b32 %0, [%1];" : "=r"(tmem) : "r"(tmem_slot));

    const int r = tid >> 2;
    const int q = tid & 3;
    const int n = bn * 128 + r;
    const int od = n / HWo; int rr2 = n - od * HWo;
    const int oh = rr2 / p.Wout; const int ow = rr2 - oh * p.Wout;
    const int id0 = od * p.sd - p.pd;
    const int ih0 = oh * p.sh - p.ph;
    const int iw0 = ow * p.sw - p.pw;
    const int gbase = (id0 * p.H + ih0) * p.W + iw0;
    const int NC = p.NC;

    auto fillB = [&](int st, int kc) {
        char* Bhi = smem_al + (st ? SME_B1 : SME_B0);
        char* Blo = Bhi + 16384;
        const int kt = kc * 64;
#pragma unroll
        for (int i = 0; i < 8; i++) {
            int kk = q * 16 + 2 * i;
            int k = kt + kk;
            int4 dv = *reinterpret_cast<const int4*>(&g_dec[k]);
            uint32_t v0 = 0, v1 = 0;
            {
                int kd = dv.y >> 20, kh = (dv.y >> 10) & 1023, kw = dv.y & 1023;
                if ((unsigned)(id0 + kd) < (unsigned)p.D &&
                    (unsigned)(ih0 + kh) < (unsigned)p.H &&
                    (unsigned)(iw0 + kw) < (unsigned)p.W)
                    v0 = p.xpk[gbase + dv.x];
            }
            {
                int kd = dv.w >> 20, kh = (dv.w >> 10) & 1023, kw = dv.w & 1023;
                if ((unsigned)(id0 + kd) < (unsigned)p.D &&
                    (unsigned)(ih0 + kh) < (unsigned)p.H &&
                    (unsigned)(iw0 + kw) < (unsigned)p.W)
                    v1 = p.xpk[gbase + dv.z];
            }
            uint32_t off = r * 128 + kk * 2;
            uint32_t sw = off ^ ((off >> 3) & 0x70);
            *reinterpret_cast<uint32_t*>(Bhi + sw) = __byte_perm(v0, v1, 0x7632);
            *reinterpret_cast<uint32_t*>(Blo + sw) = __byte_perm(v0, v1, 0x5410);
        }
    };

    int wpar = 0;
    auto waitCommits = [&](int target) {
        while (wpar < target) {
            MBARRIER_WAIT_PARITY(mbar + 8 * (wpar & 3), (wpar >> 2) & 1);
            wpar++;
        }
    };

    fillB(0, 0);

    for (int kc = 0; kc < NC; kc++) {
        int st = kc & 1;
#pragma unroll
        for (int bm = 0; bm < BM; bm++) {
            int ni = kc * BM + bm;
            if (ni >= 1) waitCommits(ni);
            if (wid == 0 && elect_one()) {
                const uint8_t* asrc =
                    g_wpk + ((size_t)(mblk0 + bm) * NC + kc) * 32768;
                MBARRIER_EXPECT_TX(ambar, 32768);
                CP_BULK_G2S(sb + SME_A, asrc, 32768, ambar);
            }
            MBARRIER_WAIT_PARITY(ambar, ni & 1);
            FENCE_PROXY_ASYNC();
            __syncthreads();
            if (wid == 0 && elect_one()) {
                uint64_t dAh = make_desc(sb + SME_A);
                uint64_t dAl = dAh + (16384 >> 4);
                uint64_t dBh = make_desc(sb + (st ? SME_B1 : SME_B0));
                uint64_t dBl = dBh + (16384 >> 4);
                uint32_t d = tmem + bm * 128;
                uint32_t first = (kc == 0) ? 0u : 1u;
#pragma unroll
                for (int s = 0; s < 4; s++) {
                    uint64_t o = s * 2;
                    mma_f16_ss(d, dAh + o, dBh + o, CONV_IDESC, first); first = 1;
                    mma_f16_ss(d, dAh + o, dBl + o, CONV_IDESC, 1);
                    mma_f16_ss(d, dAl + o, dBh + o, CONV_IDESC, 1);
                }
                TCGEN05_COMMIT(mbar + 8 * (ni & 3));
            }
        }
        if (kc + 1 < NC) fillB(st ^ 1, kc + 1);
    }
    waitCommits(NC * BM);
    TCGEN05_FENCE_AFTER();

    // ---- smem-staged coalesced epilogue ----
    {
        float* stage = reinterpret_cast<float*>(smem_al);   // [128][129]
        const int sp = wid & 3;
        const int cb = wid >> 2;
#pragma unroll
        for (int bm = 0; bm < BM; bm++) {
            uint32_t dr[32];
            TCGEN05_LD_X32(dr, tmem + bm * 128 + cb * 32);
            TCGEN05_WAIT_LD();
            __syncthreads();
            int srow = sp * 32 + lane;
#pragma unroll
            for (int j = 0; j < 32; j++)
                stage[srow * 129 + cb * 32 + j] = __uint_as_float(dr[j]);
            __syncthreads();
#pragma unroll
            for (int rr = 0; rr < 8; rr++) {
                int ml = wid * 8 + rr;
                int m = (mblk0 + bm) * 128 + ml;
                float bv = p.bias[m];
                size_t obase = (size_t)m * p.outStrideC + p.outOffset + bn * 128;
#pragma unroll
                for (int part = 0; part < 4; part++) {
                    float v = stage[ml * 129 + part * 32 + lane] + bv;
                    if (p.gelu) v = gelu_tanh(v);
                    if (p.outpk) p.outpk[obase + part * 32 + lane] = pack_hl(v);
                    else p.outf[obase + part * 32 + lane] = v;
                }
            }
        }
        TCGEN05_FENCE_BEFORE();
    }
    __syncthreads();
    if (tid == 0) {
#pragma unroll
        for (int i = 0; i < 4; i++) MBARRIER_INVAL(mbar + 8 * i);
        MBARRIER_INVAL(ambar);
    }
    if (wid == 0) TCGEN05_DEALLOC(tmem, 256);

#else  // FFMA fallback (never executes on GB300)
    for (int bm = 0; bm < BM; bm++) {
        const int m_base = (mblk0 + bm) * 128;
        for (int idx = tid; idx < 128 * 128; idx += 512) {
            int ml = idx >> 7, nl = idx & 127;
            int m = m_base + ml;
            int nn = bn * 128 + nl;
            int od = nn / HWo; int rr2 = nn - od * HWo;
            int oh = rr2 / p.Wout; int ow = rr2 - oh * p.Wout;
            int id0 = od * p.sd - p.pd, ih0 = oh * p.sh - p.ph, iw0 = ow * p.sw - p.pw;
            int gb = (id0 * p.H + ih0) * p.W + iw0;
            float s = 0.f;
            for (int k = 0; k < p.K; k++) {
                int2 dv = g_dec[k];
                int kd = dv.y >> 20, kh = (dv.y >> 10) & 1023, kw = dv.y & 1023;
                if ((unsigned)(id0 + kd) < (unsigned)p.D &&
                    (unsigned)(ih0 + kh) < (unsigned)p.H &&
                    (unsigned)(iw0 + kw) < (unsigned)p.W)
                    s += p.wf[(size_t)m * p.K + k] * unpack_hl(p.xpk[gb + dv.x]);
            }
            s += p.bias[m];
            if (p.gelu) s = gelu_tanh(s);
            size_t ob = (size_t)m * p.outStrideC + p.outOffset + nn;
            if (p.outpk) p.outpk[ob] = pack_hl(s);
            else p.outf[ob] = s;
        }
    }
#endif
}

// ---------------------------------------------------------------------------
// Token GEMM: bulk-copied A; mode-0 fuses K-plane emission; mode-1 staged.
// ---------------------------------------------------------------------------
struct TokParams {
    const uint32_t* bpk;
    const uint8_t* wpk;
    const float* wf;
    const float* bias;
    float* out;
    uint32_t* kpl;
    int T, J, Kdim, NC, mode;
};

template <int BM>
__global__ __launch_bounds__(512, 2) void tok_mma_kernel(TokParams p) {
    extern __shared__ char smem_raw[];
    char* smem_al = (char*)(((uintptr_t)smem_raw + 1023) & ~(uintptr_t)1023);

    const int tid = threadIdx.x;
    const int bn = blockIdx.x;
    const int mblk0 = blockIdx.y * BM;

#if HAS_TCGEN05
    const uint32_t sb = smem_u32(smem_al);
    const uint32_t mbar = sb + SME_MBAR;
    const uint32_t ambar = sb + SME_AMBAR;
    const uint32_t tmem_slot = sb + SME_TSLOT;
    const int wid = tid >> 5;
    const int lane = tid & 31;

    if (wid == 0) {
        TCGEN05_ALLOC(tmem_slot, 256);
        TCGEN05_RELINQ();
    }
    if (tid == 0) {
#pragma unroll
        for (int i = 0; i < 4; i++) MBARRIER_INIT(mbar + 8 * i, 1);
        MBARRIER_INIT(ambar, 1);
    }
    __syncthreads();
    uint32_t tmem;
    asm volatile("ld.shared.b32 %0, [%1];" : "=r"(tmem) : "r"(tmem_slot));

    const int r = tid >> 2;
    const int q = tid & 3;
    const uint32_t* bsrc = p.bpk + (size_t)(bn * 128 + r) * p.Kdim;
    const int NC = p.NC;

    auto fillB = [&](int st, int kc) {
        char* Bhi = smem_al + (st ? SME_B1 : SME_B0);
        char* Blo = Bhi + 16384;
        const uint32_t* src = bsrc + kc * 64 + q * 16;
        uint32_t buf[16];
#pragma unroll
        for (int i = 0; i < 4; i++)
            *reinterpret_cast<uint4*>(&buf[i * 4]) =
                *reinterpret_cast<const uint4*>(src + i * 4);
#pragma unroll
        for (int i = 0; i < 8; i++) {
            int kk = q * 16 + 2 * i;
            uint32_t v0 = buf[2 * i], v1 = buf[2 * i + 1];
            uint32_t off = r * 128 + kk * 2;
            uint32_t sw = off ^ ((off >> 3) & 0x70);
            *reinterpret_cast<uint32_t*>(Bhi + sw) = __byte_perm(v0, v1, 0x7632);
            *reinterpret_cast<uint32_t*>(Blo + sw) = __byte_perm(v0, v1, 0x5410);
        }
    };

    int wpar = 0;
    auto waitCommits = [&](int target) {
        while (wpar < target) {
            MBARRIER_WAIT_PARITY(mbar + 8 * (wpar & 3), (wpar >> 2) & 1);
            wpar++;
        }
    };

    fillB(0, 0);

    for (int kc = 0; kc < NC; kc++) {
        int st = kc & 1;
#pragma unroll
        for (int bm = 0; bm < BM; bm++) {
            int ni = kc * BM + bm;
            if (ni >= 1) waitCommits(ni);
            if (wid == 0 && elect_one()) {
                const uint8_t* asrc =
                    p.wpk + ((size_t)(mblk0 + bm) * NC + kc) * 32768;
                MBARRIER_EXPECT_TX(ambar, 32768);
                CP_BULK_G2S(sb + SME_A, asrc, 32768, ambar);
            }
            MBARRIER_WAIT_PARITY(ambar, ni & 1);
            FENCE_PROXY_ASYNC();
            __syncthreads();
            if (wid == 0 && elect_one()) {
                uint64_t dAh = make_desc(sb + SME_A);
                uint64_t dAl = dAh + (16384 >> 4);
                uint64_t dBh = make_desc(sb + (st ? SME_B1 : SME_B0));
                uint64_t dBl = dBh + (16384 >> 4);
                uint32_t d = tmem + bm * 128;
                uint32_t first = (kc == 0) ? 0u : 1u;
#pragma unroll
                for (int s = 0; s < 4; s++) {
                    uint64_t o = s * 2;
                    mma_f16_ss(d, dAh + o, dBh + o, CONV_IDESC, first); first = 1;
                    mma_f16_ss(d, dAh + o, dBl + o, CONV_IDESC, 1);
                    mma_f16_ss(d, dAl + o, dBh + o, CONV_IDESC, 1);
                }
                TCGEN05_COMMIT(mbar + 8 * (ni & 3));
            }
        }
        if (kc + 1 < NC) fillB(st ^ 1, kc + 1);
    }
    waitCommits(NC * BM);
    TCGEN05_FENCE_AFTER();

    {
        const int sp = wid & 3;
        const int cb = wid >> 2;
        const int t0 = bn * 128 + cb * 32;
        if (p.mode == 0) {
#pragma unroll
            for (int bm = 0; bm < BM; bm++) {
                const int m = (mblk0 + bm) * 128 + sp * 32 + lane;
                const float bv = p.bias[m];
                uint32_t dr[32];
                TCGEN05_LD_X32(dr, tmem + bm * 128 + cb * 32);
                TCGEN05_WAIT_LD();
                const bool kplane = p.kpl && m >= 512 && m < 1024;
#pragma unroll
                for (int j = 0; j < 32; j++) {
                    float v = __uint_as_float(dr[j]) + bv;
                    p.out[(size_t)(t0 + j) * p.J + m] = v;
                    if (kplane) {
                        float vhi = __shfl_down_sync(0xffffffffu, v, 1);
                        if ((lane & 1) == 0) {
                            __nv_bfloat162 b2 =
                                __float22bfloat162_rn(make_float2(v, vhi));
                            p.kpl[(size_t)(t0 + j) * 256 + ((m - 512) >> 1)] =
                                *reinterpret_cast<uint32_t*>(&b2);
                        }
                    }
                }
            }
        } else {
            float* stage = reinterpret_cast<float*>(smem_al);   // [128][129]
#pragma unroll
            for (int bm = 0; bm < BM; bm++) {
                uint32_t dr[32];
                TCGEN05_LD_X32(dr, tmem + bm * 128 + cb * 32);
                TCGEN05_WAIT_LD();
                __syncthreads();
                int srow = sp * 32 + lane;
#pragma unroll
                for (int j = 0; j < 32; j++)
                    stage[srow * 129 + cb * 32 + j] = __uint_as_float(dr[j]);
                __syncthreads();
#pragma unroll
                for (int rr = 0; rr < 8; rr++) {
                    int ml = wid * 8 + rr;
                    int m = (mblk0 + bm) * 128 + ml;
                    float bv = p.bias[m];
                    float* orow = p.out + (size_t)m * p.T + bn * 128;
#pragma unroll
                    for (int part = 0; part < 4; part++) {
                        int col = part * 32 + lane;
                        orow[col] += stage[ml * 129 + col] + bv;
                    }
                }
            }
        }
        TCGEN05_FENCE_BEFORE();
    }
    __syncthreads();
    if (tid == 0) {
#pragma unroll
        for (int i = 0; i < 4; i++) MBARRIER_INVAL(mbar + 8 * i);
        MBARRIER_INVAL(ambar);
    }
    if (wid == 0) TCGEN05_DEALLOC(tmem, 256);

#else  // FFMA fallback
    for (int bm = 0; bm < BM; bm++) {
        int m_base = (mblk0 + bm) * 128;
        for (int idx = tid; idx < 128 * 128; idx += 512) {
            int tl = idx >> 7, jl = idx & 127;
            int t = bn * 128 + tl, j = m_base + jl;
            float s = 0.f;
            for (int k = 0; k < p.Kdim; k++)
                s += unpack_hl(p.bpk[(size_t)t * p.Kdim + k]) * p.wf[(size_t)k * p.J + j];
            s += p.bias[j];
            if (p.mode == 0) {
                p.out[(size_t)t * p.J + j] = s;
                if (p.kpl && j >= 512 && j < 1024 && (j & 1) == 0) {
                    float s1 = 0.f;
                    for (int k = 0; k < p.Kdim; k++)
                        s1 += unpack_hl(p.bpk[(size_t)t * p.Kdim + k]) *
                              p.wf[(size_t)k * p.J + j + 1];
                    s1 += p.bias[j + 1];
                    __nv_bfloat162 b2 = __float22bfloat162_rn(make_float2(s, s1));
                    p.kpl[(size_t)t * 256 + ((j - 512) >> 1)] =
                        *reinterpret_cast<uint32_t*>(&b2);
                }
            } else {
                p.out[(size_t)j * p.T + t] += s;
            }
        }
    }
#endif
}

// ---------------------------------------------------------------------------
// LayerNorm: fp32 channel-major -> packed token-major, smem-staged writes.
// ---------------------------------------------------------------------------
__global__ __launch_bounds__(256) void layernorm_kernel(
    const float* __restrict__ x, const float* __restrict__ g,
    const float* __restrict__ b, uint32_t* __restrict__ ypk, int T) {
    extern __shared__ uint32_t ystage[];    // [32][513]
    const int tx = threadIdx.x & 31;
    const int ty = threadIdx.x >> 5;
    const int t = blockIdx.x * 32 + tx;

    float s = 0.f, ss = 0.f;
#pragma unroll
    for (int i = 0; i < 64; i++) {
        int c = ty * 64 + i;
        float v = x[(size_t)c * T + t];
        s += v; ss += v * v;
    }
    __shared__ float shs[8][32], shss[8][32];
    __shared__ float smu[32], srs[32];
    shs[ty][tx] = s; shss[ty][tx] = ss;
    __syncthreads();
    if (ty == 0) {
        float S = 0.f, SS = 0.f;
#pragma unroll
        for (int j = 0; j < 8; j++) { S += shs[j][tx]; SS += shss[j][tx]; }
        float mu = S * (1.f / 512.f);
        float var = SS * (1.f / 512.f) - mu * mu;
        smu[tx] = mu;
        srs[tx] = rsqrtf(var + 1e-5f);
    }
    __syncthreads();
    float mu = smu[tx], rs = srs[tx];
#pragma unroll
    for (int i = 0; i < 64; i++) {
        int c = ty * 64 + i;
        float v = x[(size_t)c * T + t];
        ystage[tx * 513 + c] = pack_hl((v - mu) * rs * g[c] + b[c]);
    }
    __syncthreads();
    const int warp = threadIdx.x >> 5;
    const int lane = threadIdx.x & 31;
#pragma unroll
    for (int k = 0; k < 4; k++) {
        int tt = warp * 4 + k;
        uint32_t* yr = ypk + (size_t)(blockIdx.x * 32 + tt) * 512;
#pragma unroll
        for (int i = 0; i < 16; i++)
            yr[i * 32 + lane] = ystage[tt * 513 + i * 32 + lane];
    }
}

// ---------------------------------------------------------------------------
// Neighborhood attention — compact valid-neighbor iteration (warp-uniform
// clipped window), shfl-broadcast indices, bf16 K-plane score, fp32 V PV.
// ---------------------------------------------------------------------------
__global__ __launch_bounds__(256) void natt_kernel(
    const float* __restrict__ qkv, uint32_t* __restrict__ atpk) {
    __shared__ float tsh[8][32][33];

    const int warp = threadIdx.x >> 5;
    const int lane = threadIdx.x & 31;
    const int t = blockIdx.x * 8 + warp;
    const int hd = blockIdx.y;
    const int d = t >> 11;
    const int hh = (t >> 6) & 31;
    const int ww = t & 63;

    // warp-uniform clipped window -> compact index space [0, nvalid)
    const int dlo = max(d - 2, 0), dhi = min(d + 2, 3);
    const int hlo = max(hh - 3, 0), hhi = min(hh + 3, 31);
    const int wlo = max(ww - 3, 0), whi = min(ww + 3, 63);
    const int nwc = whi - wlo + 1;
    const int nhw = (hhi - hlo + 1) * nwc;
    const int nvalid = (dhi - dlo + 1) * nhw;

    float2 q2 = *reinterpret_cast<const float2*>(
        qkv + (size_t)t * 1536 + hd * 64 + 2 * lane);
    q2.x *= 0.125f; q2.y *= 0.125f;

    int ntreg[8];
    float sc[8];
    float m = -1e30f;
#pragma unroll
    for (int it = 0; it < 8; it++) {
        if (it * 32 >= nvalid) {            // warp-uniform skip
            sc[it] = -1e30f;
            ntreg[it] = -1;
            continue;
        }
        int nb = it * 32 + lane;
        int myNt = -1;
        if (nb < nvalid) {
            int od = nb / nhw; int rem = nb - od * nhw;
            int oh = rem / nwc; int ow = rem - oh * nwc;
            myNt = ((dlo + od) * 32 + (hlo + oh)) * 64 + (wlo + ow);
        }
        ntreg[it] = myNt;
#pragma unroll
        for (int j = 0; j < 32; j++) {
            int nt = __shfl_sync(0xffffffffu, myNt, j);
            float pv = 0.f;
            if (nt >= 0) {
                uint32_t kw32 = g_kpl[(size_t)nt * 256 + hd * 32 + lane];
                float2 kf = __bfloat1622float2(
                    *reinterpret_cast<__nv_bfloat162*>(&kw32));
                pv = fmaf(q2.x, kf.x, q2.y * kf.y);
            }
            tsh[warp][j][lane] = pv;
        }
        __syncwarp();
        float s = 0.f;
#pragma unroll
        for (int j = 0; j < 32; j++) s += tsh[warp][lane][j];
        __syncwarp();
        float dot = (myNt >= 0) ? s : -1e30f;
        sc[it] = dot;
        m = fmaxf(m, dot);
    }
#pragma unroll
    for (int o = 16; o; o >>= 1) m = fmaxf(m, __shfl_xor_sync(0xffffffffu, m, o));

    float l = 0.f;
#pragma unroll
    for (int it = 0; it < 8; it++) {
        float e = (sc[it] > -1e29f) ? __expf(sc[it] - m) : 0.f;
        sc[it] = e;
        l += e;
    }
#pragma unroll
    for (int o = 16; o; o >>= 1) l += __shfl_xor_sync(0xffffffffu, l, o);

    float acc0 = 0.f, acc1 = 0.f;
#pragma unroll
    for (int it = 0; it < 8; it++) {
        if (it * 32 >= nvalid) continue;    // warp-uniform skip
        float ei = sc[it];
        int nti = ntreg[it];
#pragma unroll 4
        for (int j = 0; j < 32; j++) {
            int nt = __shfl_sync(0xffffffffu, nti, j);
            float pb = __shfl_sync(0xffffffffu, ei, j);
            if (nt >= 0) {
                float2 vv = *reinterpret_cast<const float2*>(
                    qkv + (size_t)nt * 1536 + 1024 + hd * 64 + 2 * lane);
                acc0 = fmaf(pb, vv.x, acc0);
                acc1 = fmaf(pb, vv.y, acc1);
            }
        }
    }
    float inv = 1.f / l;
    uint2 ov;
    ov.x = pack_hl(acc0 * inv);
    ov.y = pack_hl(acc1 * inv);
    *reinterpret_cast<uint2*>(atpk + (size_t)t * 512 + hd * 64 + 2 * lane) = ov;
}

// ---------------------------------------------------------------------------
// Host launcher
// ---------------------------------------------------------------------------
extern "C" void kernel_launch(void* const* d_in, const int* in_sizes, int n_in,
                              void* d_out, int out_size) {
    const float* x2d  = (const float*)d_in[0];
    const float* x3d  = (const float*)d_in[1];
    const float* sw0  = (const float*)d_in[2];  const float* sb0 = (const float*)d_in[3];
    const float* sw1  = (const float*)d_in[4];  const float* sb1 = (const float*)d_in[5];
    const float* sw2  = (const float*)d_in[6];  const float* sb2 = (const float*)d_in[7];
    const float* pw0  = (const float*)d_in[8];  const float* pb0 = (const float*)d_in[9];
    const float* pw1  = (const float*)d_in[10]; const float* pb1 = (const float*)d_in[11];
    const float* pw2  = (const float*)d_in[12]; const float* pb2 = (const float*)d_in[13];
    const float* latw = (const float*)d_in[14]; const float* latb = (const float*)d_in[15];
    const float* lng  = (const float*)d_in[16]; const float* lnb  = (const float*)d_in[17];
    const float* qkvw = (const float*)d_in[18]; const float* qkvb = (const float*)d_in[19];
    const float* pjw  = (const float*)d_in[20]; const float* pjb  = (const float*)d_in[21];
    float* lat = (float*)d_out;

    uint32_t *pkA, *pkB, *pkF, *pkX, *ynpk, *atpk, *kpl;
    float *qkvB;
    uint8_t *wpk2;
    cudaGetSymbolAddress((void**)&pkA, g_pk_a);
    cudaGetSymbolAddress((void**)&pkB, g_pk_b);
    cudaGetSymbolAddress((void**)&pkF, g_pk_f);
    cudaGetSymbolAddress((void**)&pkX, g_pk_x2d);
    cudaGetSymbolAddress((void**)&ynpk, g_ynpk);
    cudaGetSymbolAddress((void**)&qkvB, g_qkv);
    cudaGetSymbolAddress((void**)&atpk, g_atpk);
    cudaGetSymbolAddress((void**)&kpl, g_kpl);
    cudaGetSymbolAddress((void**)&wpk2, g_wpk2);

    cudaFuncSetAttribute(conv_mma_kernel<1>,
                         cudaFuncAttributeMaxDynamicSharedMemorySize, CONV_SMEM_BYTES);
    cudaFuncSetAttribute(conv_mma_kernel<2>,
                         cudaFuncAttributeMaxDynamicSharedMemorySize, CONV_SMEM_BYTES);
    cudaFuncSetAttribute(tok_mma_kernel<1>,
                         cudaFuncAttributeMaxDynamicSharedMemorySize, CONV_SMEM_BYTES);
    cudaFuncSetAttribute(tok_mma_kernel<2>,
                         cudaFuncAttributeMaxDynamicSharedMemorySize, CONV_SMEM_BYTES);
    cudaFuncSetAttribute(layernorm_kernel,
                         cudaFuncAttributeMaxDynamicSharedMemorySize, LN_SMEM_BYTES);

    auto run_conv = [&](const uint32_t* xpk, const float* wf, const float* bias,
                        uint32_t* outpk, float* outf,
                        int Cin, int D, int H, int W, int Dout, int Hout, int Wout,
                        int KD, int KH, int KW, int sd, int sh, int sw,
                        int pd, int ph, int pw, int Cout,
                        int outStrideC, int outOffset, int gelu) {
        int K = Cin * KD * KH * KW;
        int NC = (K + 63) / 64;
        wpack_kernel<<<dim3(NC, Cout / 128), 256>>>(wf, K, NC, KD * KH * KW,
                                                    KH * KW, KW, D, H, W);
        int Nvox = Dout * Hout * Wout;
        ConvParams p{ xpk, wf, bias, outpk, outf,
                      D, H, W, Hout, Wout, sd, sh, sw, pd, ph, pw,
                      K, NC, outStrideC, outOffset, gelu };
        int nblk = Cout / 128;
        int bn = Nvox / 128;
        if (nblk % 2 == 0 && bn * (nblk / 2) >= 256)
            conv_mma_kernel<2><<<dim3(bn, nblk / 2), 512, CONV_SMEM_BYTES>>>(p);
        else
            conv_mma_kernel<1><<<dim3(bn, nblk), 512, CONV_SMEM_BYTES>>>(p);
    };

    xpack_kernel<<<(5 * 24 * 256 * 512 / 4 + 255) / 256, 256>>>(
        x3d, pkA, 5 * 24 * 256 * 512 / 4);
    xpack_kernel<<<(8 * 256 * 512 / 4 + 255) / 256, 256>>>(
        x2d, pkX, 8 * 256 * 512 / 4);

    // ---- 3D tower ----
    run_conv(pkA, pw0, pb0, pkB, nullptr, 5, 24, 256, 512, 12, 128, 256,
             3, 3, 3, 2, 2, 2, 1, 1, 1, 128, 393216, 0, 1);
    run_conv(pkB, pw1, pb1, pkA, nullptr, 128, 12, 128, 256, 6, 64, 128,
             3, 3, 3, 2, 2, 2, 1, 1, 1, 256, 49152, 0, 1);
    run_conv(pkA, pw2, pb2, pkF, nullptr, 256, 6, 64, 128, 3, 32, 64,
             3, 3, 3, 2, 2, 2, 1, 1, 1, 512, 8192, 0, 1);

    // ---- 2D tower ----
    run_conv(pkX, sw0, sb0, pkB, nullptr, 8, 1, 256, 512, 1, 128, 256,
             1, 3, 3, 1, 2, 2, 0, 1, 1, 128, 32768, 0, 1);
    run_conv(pkB, sw1, sb1, pkA, nullptr, 128, 1, 128, 256, 1, 64, 128,
             1, 3, 3, 1, 2, 2, 0, 1, 1, 256, 8192, 0, 1);
    run_conv(pkA, sw2, sb2, pkF, nullptr, 256, 1, 64, 128, 1, 32, 64,
             1, 3, 3, 1, 2, 2, 0, 1, 1, 512, 8192, 3 * 2048, 1);

    // ---- lateral 1x1x1 -> d_out fp32 ----
    run_conv(pkF, latw, latb, nullptr, lat, 512, 4, 32, 64, 4, 32, 64,
             1, 1, 1, 1, 1, 1, 0, 0, 0, 512, 8192, 0, 0);

    // ---- attention weight prepack ----
    const size_t QKV_PK = 8 * 12 * 32768;
    const size_t PRJ_PK = 8 * 4 * 32768;
    for (int i = 0; i < 3; i++) {
        wpackT_kernel<<<dim3(8, 12), 256>>>(qkvw + (size_t)i * 512 * 1536,
                                            wpk2 + i * QKV_PK, 512, 8, 1536);
        wpackT_kernel<<<dim3(8, 4), 256>>>(pjw + (size_t)i * 512 * 512,
                                           wpk2 + 3 * QKV_PK + i * PRJ_PK, 512, 8, 512);
    }

    // ---- 3 neighborhood-attention blocks ----
    for (int i = 0; i < 3; i++) {
        layernorm_kernel<<<8192 / 32, 256, LN_SMEM_BYTES>>>(
            lat, lng + i * 512, lnb + i * 512, ynpk, 8192);
        TokParams pq{ ynpk, wpk2 + i * QKV_PK, qkvw + (size_t)i * 512 * 1536,
                      qkvb + i * 1536, qkvB, kpl, 8192, 1536, 512, 8, 0 };
        tok_mma_kernel<2><<<dim3(8192 / 128, 6), 512, CONV_SMEM_BYTES>>>(pq);
        natt_kernel<<<dim3(1024, 8), 256>>>(qkvB, atpk);
        TokParams pp{ atpk, wpk2 + 3 * QKV_PK + i * PRJ_PK,
                      pjw + (size_t)i * 512 * 512,
                      pjb + i * 512, lat, nullptr, 8192, 512, 512, 8, 1 };
        tok_mma_kernel<1><<<dim3(8192 / 128, 4), 512, CONV_SMEM_BYTES>>>(pp);
    }
}